// round 10
// baseline (speedup 1.0000x reference)
#include <cuda_runtime.h>
#include <math.h>
#include <stdint.h>

// Problem shapes (fixed by the dataset)
constexpr int Bb = 16;    // batch
constexpr int Ss = 2048;  // tokens
constexpr int Dd = 512;   // dim
constexpr int Mm = 256;   // memory slots
constexpr int Rr = 64;    // low rank
constexpr float EPS = 1e-5f;
constexpr float STATE_MASS = 4.0f;
constexpr float LRS = 0.1f;

typedef unsigned long long ull;

// ---------------- scratch (static device globals; no allocs) ----------------
__device__ float g_scores[(size_t)Bb * Mm * Ss];   // 33.5 MB (L2-resident) [b][m][s]
__device__ float g_ps_h[(size_t)Bb * Ss * Rr];     // ps split hi
__device__ float g_ps_l[(size_t)Bb * Ss * Rr];     // ps split lo
__device__ float g_mem_val0[(size_t)Mm * Dd];      // LN(init_val), batch-independent
__device__ float g_pt2_h[(size_t)Mm * Rr];         // pt2 split hi
__device__ float g_pt2_l[(size_t)Mm * Rr];         // pt2 split lo
__device__ float g_Wh[(size_t)Dd * Rr];            // rUs_w split hi
__device__ float g_Wl[(size_t)Dd * Rr];            // rUs_w split lo
__device__ float g_mem_state0[Mm];                 // signed-softmax-state(init_state)
__device__ float g_mem_val1[(size_t)Bb * Mm * Dd]; // post-write, post-LN
__device__ float g_state1_raw[(size_t)Bb * Mm];
__device__ float g_state1[(size_t)Bb * Mm];
__device__ float g_qt[(size_t)Bb * Mm * Rr];       // (mem_val1@pUt + b) * p_w * 0.1
__device__ float g_qs2[(size_t)Bb * Mm * Rr];      // (mem_val1@pUs + b) * state1[b,j]

// ---------------- tf32 / cp.async helpers ----------------
__device__ __forceinline__ uint32_t f2tf32(float x) {
    uint32_t r;
    asm("cvt.rna.tf32.f32 %0, %1;" : "=r"(r) : "f"(x));
    return r;
}

__device__ __forceinline__ void cpa16(void* dst_smem, const void* src) {
    uint32_t d = (uint32_t)__cvta_generic_to_shared(dst_smem);
    asm volatile("cp.async.ca.shared.global [%0], [%1], 16;" :: "r"(d), "l"(src));
}
#define CP_COMMIT() asm volatile("cp.async.commit_group;")
#define CP_WAIT(n)  asm volatile("cp.async.wait_group %0;" :: "n"(n))

#define MMA_TF32(C, A, B0, B1)                                                  \
    asm volatile(                                                               \
        "mma.sync.aligned.m16n8k8.row.col.f32.tf32.tf32.f32 "                   \
        "{%0,%1,%2,%3}, {%4,%5,%6,%7}, {%8,%9}, {%0,%1,%2,%3};"                 \
        : "+f"((C)[0]), "+f"((C)[1]), "+f"((C)[2]), "+f"((C)[3])                \
        : "r"((A)[0]), "r"((A)[1]), "r"((A)[2]), "r"((A)[3]), "r"(B0), "r"(B1))

// ---------------- kernel: split an array into tf32 hi/lo ----------------
__global__ void split_kernel(const float* __restrict__ src, float* __restrict__ dh,
                             float* __restrict__ dl, int n) {
    int i = blockIdx.x * blockDim.x + threadIdx.x;
    if (i < n) {
        float v = src[i];
        uint32_t h = f2tf32(v);
        float hf = __uint_as_float(h);
        dh[i] = hf;
        dl[i] = __uint_as_float(f2tf32(v - hf));
    }
}

// ---------------- shared helpers ----------------
__device__ __forceinline__ void block_ln_512(float a0, float a1, float& mu, float& ri,
                                             float* swr) {
    float ps = a0 + a1;
    float pq = fmaf(a0, a0, a1 * a1);
#pragma unroll
    for (int off = 16; off; off >>= 1) {
        ps += __shfl_down_sync(0xffffffffu, ps, off);
        pq += __shfl_down_sync(0xffffffffu, pq, off);
    }
    int tid = threadIdx.x, wid = tid >> 5, lane = tid & 31;
    if (lane == 0) { swr[wid] = ps; swr[8 + wid] = pq; }
    __syncthreads();
    if (tid == 0) {
        float s = 0.f, q = 0.f;
#pragma unroll
        for (int i = 0; i < 8; i++) { s += swr[i]; q += swr[8 + i]; }
        float m = s * (1.0f / 512.0f);
        float v = q * (1.0f / 512.0f) - m * m;
        swr[16] = m;
        swr[17] = rsqrtf(v + EPS);
    }
    __syncthreads();
    mu = swr[16];
    ri = swr[17];
}

// ---------------- kernel: LayerNorm rows ----------------
__global__ void ln_rows_kernel(const float* __restrict__ in, float* __restrict__ out,
                               const float* __restrict__ g, const float* __restrict__ bta) {
    __shared__ float swr[18];
    int row = blockIdx.x, tid = threadIdx.x;
    const float* x = in + (size_t)row * Dd;
    float a0 = x[tid], a1 = x[tid + 256];
    float mu, ri;
    block_ln_512(a0, a1, mu, ri, swr);
    float* o = out + (size_t)row * Dd;
    o[tid]       = (a0 - mu) * ri * g[tid] + bta[tid];
    o[tid + 256] = (a1 - mu) * ri * g[tid + 256] + bta[tid + 256];
}

// ---------------- kernel: signed softmax state over 256 slots ----------------
__global__ void sss_kernel(const float* __restrict__ in, float* __restrict__ out) {
    int tid = threadIdx.x;
    const float* x = in + (size_t)blockIdx.x * Mm;
    float v = x[tid];
    float a = fabsf(v);
    __shared__ float swr[8];
    __shared__ float s_bc[2];
    int wid = tid >> 5, lane = tid & 31;
    float m = a;
#pragma unroll
    for (int off = 16; off; off >>= 1) m = fmaxf(m, __shfl_down_sync(0xffffffffu, m, off));
    if (lane == 0) swr[wid] = m;
    __syncthreads();
    if (tid == 0) {
        float mm = swr[0];
#pragma unroll
        for (int i = 1; i < 8; i++) mm = fmaxf(mm, swr[i]);
        s_bc[0] = mm;
    }
    __syncthreads();
    float e = expf(a - s_bc[0]);
    float s = e;
#pragma unroll
    for (int off = 16; off; off >>= 1) s += __shfl_down_sync(0xffffffffu, s, off);
    __syncthreads();
    if (lane == 0) swr[wid] = s;
    __syncthreads();
    if (tid == 0) {
        float ss = 0.f;
#pragma unroll
        for (int i = 0; i < 8; i++) ss += swr[i];
        s_bc[1] = ss;
    }
    __syncthreads();
    float sgn = (v > 0.f) ? 1.f : ((v < 0.f) ? -1.f : 0.f);
    out[(size_t)blockIdx.x * Mm + tid] = sgn * e / s_bc[1] * STATE_MASS;
}

// ---------------- scalar tiled projection (small launches: pt2, qt, qs2) ----------------
// If outh non-null for a set, writes tf32-split (hi, lo) outputs instead of raw.
template <int RT>
__global__ __launch_bounds__(256) void gemm_proj(
    const float* __restrict__ X0,
    float* __restrict__ out0, const float* __restrict__ W0, const float* __restrict__ b0,
    const float* __restrict__ rs0, const float* __restrict__ rowsc0,
    float* __restrict__ outh0, float* __restrict__ outl0,
    const float* __restrict__ X1,
    float* __restrict__ out1, const float* __restrict__ W1, const float* __restrict__ b1,
    const float* __restrict__ rs1, const float* __restrict__ rowsc1,
    float* __restrict__ outh1, float* __restrict__ outl1) {
    constexpr int RPT = RT / 16;
    constexpr int XSTR = RT + 4;
    __shared__ float sx[16 * XSTR];
    __shared__ float sw[16 * 68];

    int tid = threadIdx.x;
    int set = blockIdx.y;
    int row0 = blockIdx.x * RT;
    const float* X     = set ? X1 : X0;
    const float* W     = set ? W1 : W0;
    const float* bias  = set ? b1 : b0;
    const float* rs    = set ? rs1 : rs0;
    const float* rowsc = set ? rowsc1 : rowsc0;
    float* out         = set ? out1 : out0;
    float* outh        = set ? outh1 : outh0;
    float* outl        = set ? outl1 : outl0;

    int rowg = tid >> 4;
    int colg = tid & 15;

    float acc[RPT][4];
#pragma unroll
    for (int r = 0; r < RPT; r++)
#pragma unroll
        for (int c = 0; c < 4; c++) acc[r][c] = 0.f;

    for (int k0 = 0; k0 < Dd; k0 += 16) {
        constexpr int NV = RT * 16 / 4;
#pragma unroll
        for (int t = 0; t < (NV + 255) / 256; t++) {
            int f = tid + 256 * t;
            if ((NV % 256 == 0) || (f < NV)) {
                int row = f >> 2, q = f & 3;
                float4 v = *(const float4*)&X[(size_t)(row0 + row) * Dd + k0 + 4 * q];
                sx[(4 * q + 0) * XSTR + row] = v.x;
                sx[(4 * q + 1) * XSTR + row] = v.y;
                sx[(4 * q + 2) * XSTR + row] = v.z;
                sx[(4 * q + 3) * XSTR + row] = v.w;
            }
        }
        {
            int k = tid >> 4, c = tid & 15;
            float4 v = *(const float4*)&W[(size_t)(k0 + k) * Rr + 4 * c];
            *(float4*)&sw[k * 68 + 4 * c] = v;
        }
        __syncthreads();
#pragma unroll
        for (int kk = 0; kk < 16; kk++) {
            float4 wv = *(const float4*)&sw[kk * 68 + colg * 4];
            float xr[RPT];
            float2 x0 = *(const float2*)&sx[kk * XSTR + rowg * RPT];
            xr[0] = x0.x; xr[1] = x0.y;
#pragma unroll
            for (int r = 0; r < RPT; r++) {
                acc[r][0] = fmaf(xr[r], wv.x, acc[r][0]);
                acc[r][1] = fmaf(xr[r], wv.y, acc[r][1]);
                acc[r][2] = fmaf(xr[r], wv.z, acc[r][2]);
                acc[r][3] = fmaf(xr[r], wv.w, acc[r][3]);
            }
        }
        __syncthreads();
    }

    float4 bv = *(const float4*)&bias[colg * 4];
    float s0 = 1.f, s1 = 1.f, s2 = 1.f, s3 = 1.f;
    if (rs) {
        float4 rv = *(const float4*)&rs[colg * 4];
        s0 = rv.x * LRS; s1 = rv.y * LRS; s2 = rv.z * LRS; s3 = rv.w * LRS;
    }
#pragma unroll
    for (int r = 0; r < RPT; r++) {
        int row = row0 + rowg * RPT + r;
        float rsc = rowsc ? rowsc[row] : 1.f;
        float o[4];
        o[0] = (acc[r][0] + bv.x) * s0 * rsc;
        o[1] = (acc[r][1] + bv.y) * s1 * rsc;
        o[2] = (acc[r][2] + bv.z) * s2 * rsc;
        o[3] = (acc[r][3] + bv.w) * s3 * rsc;
        if (outh) {
            float h[4], l[4];
#pragma unroll
            for (int c = 0; c < 4; c++) {
                uint32_t hb = f2tf32(o[c]);
                h[c] = __uint_as_float(hb);
                l[c] = __uint_as_float(f2tf32(o[c] - h[c]));
            }
            *(float4*)&outh[(size_t)row * Rr + colg * 4] = make_float4(h[0], h[1], h[2], h[3]);
            *(float4*)&outl[(size_t)row * Rr + colg * 4] = make_float4(l[0], l[1], l[2], l[3]);
        } else {
            *(float4*)&out[(size_t)row * Rr + colg * 4] = make_float4(o[0], o[1], o[2], o[3]);
        }
    }
}

// ---------------- tensor-core ps GEMM, cp.async 3-stage pipeline, pre-split W ----------
// ps[32768,64] = X[32768,512] @ W[512,64] + b. Outputs split hi/lo.
// Dynamic smem: 3 stages x (128x20 X + 16x72 Wh + 16x72 Wl) floats = 58368 bytes.
constexpr int PS_XOFF = 0;               // per-stage X offset (floats)
constexpr int PS_WHOFF = 128 * 20;       // per-stage Wh offset
constexpr int PS_WLOFF = 128 * 20 + 16 * 72;
constexpr int PS_STAGE = 128 * 20 + 2 * 16 * 72;  // floats per stage = 4864
constexpr int PS_SMEM_BYTES = 3 * PS_STAGE * 4;   // 58368

__global__ __launch_bounds__(256) void gemm_ps_tc(
    const float* __restrict__ X, const float* __restrict__ bias) {
    extern __shared__ __align__(16) float smp[];
    int tid = threadIdx.x, w = tid >> 5, lane = tid & 31;
    int g = lane >> 2, tg = lane & 3;
    int row0 = blockIdx.x * 128;
    int wm = w >> 1, wn = w & 1;

    int lr = tid >> 2, lq = (tid & 3) * 4;   // X cp.async coords (rows lr, lr+64)
    int wk = tid >> 4, wc = (tid & 15) * 4;  // W cp.async coords

    float acc[2][4][4];
#pragma unroll
    for (int mt = 0; mt < 2; mt++)
#pragma unroll
        for (int nt = 0; nt < 4; nt++)
#pragma unroll
            for (int c = 0; c < 4; c++) acc[mt][nt][c] = 0.f;

#pragma unroll
    for (int pc = 0; pc < 2; pc++) {
        int k0 = pc * 16;
        float* st = smp + pc * PS_STAGE;
        cpa16(st + PS_XOFF + lr * 20 + lq,        &X[(size_t)(row0 + lr) * Dd + k0 + lq]);
        cpa16(st + PS_XOFF + (lr + 64) * 20 + lq, &X[(size_t)(row0 + lr + 64) * Dd + k0 + lq]);
        cpa16(st + PS_WHOFF + wk * 72 + wc,       &g_Wh[(size_t)(k0 + wk) * Rr + wc]);
        cpa16(st + PS_WLOFF + wk * 72 + wc,       &g_Wl[(size_t)(k0 + wk) * Rr + wc]);
        CP_COMMIT();
    }

    for (int c = 0; c < 32; c++) {
        CP_WAIT(1);
        __syncthreads();
        float* st = smp + (c % 3) * PS_STAGE;
        float* sx = st + PS_XOFF;
        float* swh = st + PS_WHOFF;
        float* swl = st + PS_WLOFF;
#pragma unroll
        for (int ks = 0; ks < 2; ks++) {
            int kk = ks * 8;
            uint32_t ah[2][4], al[2][4];
#pragma unroll
            for (int mt = 0; mt < 2; mt++) {
                int r = wm * 32 + mt * 16;
                float x0 = sx[(r + g) * 20 + kk + tg];
                float x1 = sx[(r + g + 8) * 20 + kk + tg];
                float x2 = sx[(r + g) * 20 + kk + tg + 4];
                float x3 = sx[(r + g + 8) * 20 + kk + tg + 4];
                ah[mt][0] = f2tf32(x0); al[mt][0] = f2tf32(x0 - __uint_as_float(ah[mt][0]));
                ah[mt][1] = f2tf32(x1); al[mt][1] = f2tf32(x1 - __uint_as_float(ah[mt][1]));
                ah[mt][2] = f2tf32(x2); al[mt][2] = f2tf32(x2 - __uint_as_float(ah[mt][2]));
                ah[mt][3] = f2tf32(x3); al[mt][3] = f2tf32(x3 - __uint_as_float(ah[mt][3]));
            }
#pragma unroll
            for (int nt = 0; nt < 4; nt++) {
                int cc = wn * 32 + nt * 8 + g;
                uint32_t bh0 = __float_as_uint(swh[(kk + tg) * 72 + cc]);
                uint32_t bh1 = __float_as_uint(swh[(kk + tg + 4) * 72 + cc]);
                uint32_t bl0 = __float_as_uint(swl[(kk + tg) * 72 + cc]);
                uint32_t bl1 = __float_as_uint(swl[(kk + tg + 4) * 72 + cc]);
#pragma unroll
                for (int mt = 0; mt < 2; mt++) {
                    MMA_TF32(acc[mt][nt], ah[mt], bh0, bh1);
                    MMA_TF32(acc[mt][nt], ah[mt], bl0, bl1);
                    MMA_TF32(acc[mt][nt], al[mt], bh0, bh1);
                }
            }
        }
        __syncthreads();
        int nc = c + 2;
        if (nc < 32) {
            int k0 = nc * 16;
            float* s2 = smp + (nc % 3) * PS_STAGE;
            cpa16(s2 + PS_XOFF + lr * 20 + lq,        &X[(size_t)(row0 + lr) * Dd + k0 + lq]);
            cpa16(s2 + PS_XOFF + (lr + 64) * 20 + lq, &X[(size_t)(row0 + lr + 64) * Dd + k0 + lq]);
            cpa16(s2 + PS_WHOFF + wk * 72 + wc,       &g_Wh[(size_t)(k0 + wk) * Rr + wc]);
            cpa16(s2 + PS_WLOFF + wk * 72 + wc,       &g_Wl[(size_t)(k0 + wk) * Rr + wc]);
        }
        CP_COMMIT();
    }

    // epilogue: add bias, split to hi/lo, store
#pragma unroll
    for (int mt = 0; mt < 2; mt++) {
        int r = row0 + wm * 32 + mt * 16 + g;
#pragma unroll
        for (int nt = 0; nt < 4; nt++) {
            int c = wn * 32 + nt * 8 + 2 * tg;
            float b0 = bias[c], b1 = bias[c + 1];
            float v00 = acc[mt][nt][0] + b0, v01 = acc[mt][nt][1] + b1;
            float v10 = acc[mt][nt][2] + b0, v11 = acc[mt][nt][3] + b1;
            float h00 = __uint_as_float(f2tf32(v00));
            float h01 = __uint_as_float(f2tf32(v01));
            float h10 = __uint_as_float(f2tf32(v10));
            float h11 = __uint_as_float(f2tf32(v11));
            *(float2*)&g_ps_h[(size_t)r * Rr + c]       = make_float2(h00, h01);
            *(float2*)&g_ps_h[(size_t)(r + 8) * Rr + c] = make_float2(h10, h11);
            *(float2*)&g_ps_l[(size_t)r * Rr + c] = make_float2(
                __uint_as_float(f2tf32(v00 - h00)), __uint_as_float(f2tf32(v01 - h01)));
            *(float2*)&g_ps_l[(size_t)(r + 8) * Rr + c] = make_float2(
                __uint_as_float(f2tf32(v10 - h10)), __uint_as_float(f2tf32(v11 - h11)));
        }
    }
}

// ---------------- tensor-core scores GEMM: pure MMA from pre-split tiles ----------
// Block 128 m x 128 s; all four K=64 tiles staged once (147.5 KB dynamic smem).
__global__ __launch_bounds__(256) void scores_tc_kernel() {
    extern __shared__ __align__(16) float smc[];
    float (*sah)[72] = (float(*)[72])smc;                    // pt2 hi [m][k]
    float (*sal)[72] = (float(*)[72])(smc + 128 * 72);       // pt2 lo
    float (*sbh)[72] = (float(*)[72])(smc + 2 * 128 * 72);   // ps hi [s][k]
    float (*sbl)[72] = (float(*)[72])(smc + 3 * 128 * 72);   // ps lo
    int tid = threadIdx.x, w = tid >> 5, lane = tid & 31;
    int g = lane >> 2, tg = lane & 3;
    int b = blockIdx.z;
    int m0 = blockIdx.y * 128;
    int s0 = blockIdx.x * 128;
    int wm = w >> 1, wn = w & 1;

#pragma unroll
    for (int t = 0; t < 8; t++) {
        int f = tid + 256 * t;
        int r = f >> 4, q = (f & 15) * 4;
        cpa16(&sah[r][q], &g_pt2_h[(size_t)(m0 + r) * Rr + q]);
        cpa16(&sal[r][q], &g_pt2_l[(size_t)(m0 + r) * Rr + q]);
        cpa16(&sbh[r][q], &g_ps_h[((size_t)b * Ss + s0 + r) * Rr + q]);
        cpa16(&sbl[r][q], &g_ps_l[((size_t)b * Ss + s0 + r) * Rr + q]);
    }
    CP_COMMIT();

    float acc[2][8][4];
#pragma unroll
    for (int mt = 0; mt < 2; mt++)
#pragma unroll
        for (int nt = 0; nt < 8; nt++)
#pragma unroll
            for (int c = 0; c < 4; c++) acc[mt][nt][c] = 0.f;

    CP_WAIT(0);
    __syncthreads();

#pragma unroll
    for (int ks = 0; ks < 8; ks++) {
        int kk = ks * 8;
        uint32_t ah[2][4], al[2][4];
#pragma unroll
        for (int mt = 0; mt < 2; mt++) {
            int r = wm * 32 + mt * 16;
            ah[mt][0] = __float_as_uint(sah[r + g][kk + tg]);
            ah[mt][1] = __float_as_uint(sah[r + g + 8][kk + tg]);
            ah[mt][2] = __float_as_uint(sah[r + g][kk + tg + 4]);
            ah[mt][3] = __float_as_uint(sah[r + g + 8][kk + tg + 4]);
            al[mt][0] = __float_as_uint(sal[r + g][kk + tg]);
            al[mt][1] = __float_as_uint(sal[r + g + 8][kk + tg]);
            al[mt][2] = __float_as_uint(sal[r + g][kk + tg + 4]);
            al[mt][3] = __float_as_uint(sal[r + g + 8][kk + tg + 4]);
        }
#pragma unroll
        for (int nt = 0; nt < 8; nt++) {
            int cc = wn * 64 + nt * 8 + g;
            uint32_t bh0 = __float_as_uint(sbh[cc][kk + tg]);
            uint32_t bh1 = __float_as_uint(sbh[cc][kk + tg + 4]);
            uint32_t bl0 = __float_as_uint(sbl[cc][kk + tg]);
            uint32_t bl1 = __float_as_uint(sbl[cc][kk + tg + 4]);
#pragma unroll
            for (int mt = 0; mt < 2; mt++) {
                MMA_TF32(acc[mt][nt], ah[mt], bh0, bh1);
                MMA_TF32(acc[mt][nt], ah[mt], bl0, bl1);
                MMA_TF32(acc[mt][nt], al[mt], bh0, bh1);
            }
        }
    }

#pragma unroll
    for (int mt = 0; mt < 2; mt++) {
        int m = m0 + wm * 32 + mt * 16 + g;
#pragma unroll
        for (int nt = 0; nt < 8; nt++) {
            int s = s0 + wn * 64 + nt * 8 + 2 * tg;
            *(float2*)&g_scores[((size_t)(b * Mm + m)) * Ss + s] =
                make_float2(acc[mt][nt][0], acc[mt][nt][1]);
            *(float2*)&g_scores[((size_t)(b * Mm + m + 8)) * Ss + s] =
                make_float2(acc[mt][nt][2], acc[mt][nt][3]);
        }
    }
}

// ---------------- write phase: count-bisection top-16 + edges + gather + LN ----------------
__global__ __launch_bounds__(256) void write_kernel(
    const float* __restrict__ token_val, const float* __restrict__ token_state,
    const float* __restrict__ ln_g, const float* __restrict__ ln_b) {
    int bm = blockIdx.x;
    int b = bm >> 8, m = bm & 255;
    int tid = threadIdx.x, w = tid >> 5, lane = tid & 31;
    __shared__ ull skeys[64];
    __shared__ float swr[18];
    __shared__ int s_ic[8];
    __shared__ int s_tot;
    __shared__ float s_edge[16];
    __shared__ int s_eidx[16];

    const float* row = g_scores + (size_t)bm * Ss;

    float aa[8];
#pragma unroll
    for (int j = 0; j < 8; j++) aa[j] = fabsf(row[tid + 256 * j]);

    {
        unsigned um = 0;
#pragma unroll
        for (int j = 0; j < 8; j++) um = max(um, __float_as_uint(aa[j]));
        um = __reduce_max_sync(0xffffffffu, um);
        if (lane == 0) s_ic[w] = (int)um;
        __syncthreads();
        if (tid == 0) {
            unsigned mm = (unsigned)s_ic[0];
#pragma unroll
            for (int i = 1; i < 8; i++) mm = max(mm, (unsigned)s_ic[i]);
            swr[16] = __uint_as_float(mm);
        }
        __syncthreads();
    }
    float hi = swr[16], lo = 0.f;
    int cl = Ss;

    for (int it = 0; it < 32 && cl > 64; it++) {
        float mid = 0.5f * (lo + hi);
        int c = 0;
#pragma unroll
        for (int j = 0; j < 8; j++) c += (aa[j] > mid);
        c = (int)__reduce_add_sync(0xffffffffu, (unsigned)c);
        if (lane == 0) s_ic[w] = c;
        __syncthreads();
        if (tid == 0) {
            int t = 0;
#pragma unroll
            for (int i = 0; i < 8; i++) t += s_ic[i];
            s_tot = t;
        }
        __syncthreads();
        int tot = s_tot;
        if (tot >= 16) { lo = mid; cl = tot; } else { hi = mid; }
        __syncthreads();
    }

    if (tid == 0) s_tot = 0;
    if (tid < 64) skeys[tid] = 0ull;
    __syncthreads();
#pragma unroll
    for (int j = 0; j < 8; j++) {
        if (aa[j] > lo) {
            int p = atomicAdd(&s_tot, 1);
            if (p < 64)
                skeys[p] = ((ull)__float_as_uint(aa[j]) << 32) | (unsigned)(~(tid + 256 * j));
        }
    }
    __syncthreads();

    for (int k = 2; k <= 64; k <<= 1) {
        for (int j = k >> 1; j; j >>= 1) {
            int i = tid, l = i ^ j;
            if (i < 64 && l > i) {
                ull a = skeys[i], bq = skeys[l];
                bool sw2 = ((i & k) == 0) ? (a < bq) : (a > bq);
                if (sw2) { skeys[i] = bq; skeys[l] = a; }
            }
            __syncthreads();
        }
    }

    if (w == 0) {
        bool valid = lane < 16;
        ull key = skeys[valid ? lane : 0];
        float a = __uint_as_float((unsigned)(key >> 32));
        int idx = (int)(~(unsigned)key);
        float maxa = __shfl_sync(0xffffffffu, a, 0);
        float sel = valid ? row[idx] : 0.f;
        float e = valid ? expf(a - maxa) : 0.f;
        float sum = e;
#pragma unroll
        for (int off = 8; off; off >>= 1) sum += __shfl_xor_sync(0xffffffffu, sum, off, 16);
        float sgn = (sel > 0.f) ? 1.f : ((sel < 0.f) ? -1.f : 0.f);
        float edge = sgn * e / sum;
        if (valid) { s_edge[lane] = edge; s_eidx[lane] = idx; }
        float c = valid ? edge * token_state[(size_t)b * Ss + idx] : 0.f;
#pragma unroll
        for (int off = 8; off; off >>= 1) c += __shfl_xor_sync(0xffffffffu, c, off, 16);
        if (lane == 0) g_state1_raw[bm] = g_mem_state0[m] + c;
    }
    __syncthreads();

    int d = tid;
    float a0 = g_mem_val0[(size_t)m * Dd + d];
    float a1 = g_mem_val0[(size_t)m * Dd + d + 256];
#pragma unroll
    for (int k = 0; k < 16; k++) {
        const float* tv = token_val + ((size_t)b * Ss + s_eidx[k]) * Dd;
        float ek = s_edge[k];
        a0 = fmaf(ek, tv[d], a0);
        a1 = fmaf(ek, tv[d + 256], a1);
    }
    float mu, ri;
    block_ln_512(a0, a1, mu, ri, swr);
    float* o = g_mem_val1 + (size_t)bm * Dd;
    o[d]       = (a0 - mu) * ri * ln_g[d] + ln_b[d];
    o[d + 256] = (a1 - mu) * ri * ln_g[d + 256] + ln_b[d + 256];
}

// ---------------- propagation: 8 rows/block, per-warp bisection top-16 ----------------
__global__ __launch_bounds__(256) void prop8_kernel(
    float* __restrict__ out_final, const float* __restrict__ ln_g,
    const float* __restrict__ ln_b) {
    int b = blockIdx.x >> 5;
    int i0 = (blockIdx.x & 31) * 8;
    int tid = threadIdx.x, w = tid >> 5, lane = tid & 31;
    __shared__ float s_qt[8][68];
    __shared__ float sqs[32][68];
    __shared__ float prow[8][256];
    __shared__ ull wkeys[8][32];
    __shared__ float s_edge[8][16];
    __shared__ int s_eidx[8][16];
    __shared__ float swr[18];

    if (tid < 128) {
        int r = tid >> 4, q = tid & 15;
        *(float4*)&s_qt[r][q * 4] =
            *(const float4*)&g_qt[((size_t)(b * Mm + i0 + r)) * Rr + 4 * q];
    }
    __syncthreads();

    float pv[8];
    for (int j0 = 0; j0 < Mm; j0 += 32) {
#pragma unroll
        for (int t = 0; t < 2; t++) {
            int f = tid + 256 * t;
            int jj = f >> 4, q = f & 15;
            *(float4*)&sqs[jj][q * 4] =
                *(const float4*)&g_qs2[((size_t)(b * Mm + j0 + jj)) * Rr + 4 * q];
        }
        __syncthreads();
        float acc = 0.f;
#pragma unroll
        for (int k4 = 0; k4 < Rr; k4 += 4) {
            float4 qv = *(const float4*)&sqs[lane][k4];
            float4 tv = *(const float4*)&s_qt[w][k4];
            acc = fmaf(qv.x, tv.x, fmaf(qv.y, tv.y, fmaf(qv.z, tv.z, fmaf(qv.w, tv.w, acc))));
        }
        pv[j0 >> 5] = acc;
        prow[w][j0 + lane] = acc;
        __syncthreads();
    }

    float av[8];
#pragma unroll
    for (int r = 0; r < 8; r++) av[r] = fabsf(pv[r]);
    unsigned um = 0;
#pragma unroll
    for (int r = 0; r < 8; r++) um = max(um, __float_as_uint(av[r]));
    um = __reduce_max_sync(0xffffffffu, um);
    float hi = __uint_as_float(um), lo = 0.f;
    int cl = 256;
    for (int it = 0; it < 32 && cl > 32; it++) {
        float mid = 0.5f * (lo + hi);
        int c = 0;
#pragma unroll
        for (int r = 0; r < 8; r++) c += (av[r] > mid);
        c = (int)__reduce_add_sync(0xffffffffu, (unsigned)c);
        if (c >= 16) { lo = mid; cl = c; } else { hi = mid; }
    }

    wkeys[w][lane] = 0ull;
    __syncwarp();
    int base = 0;
#pragma unroll
    for (int r = 0; r < 8; r++) {
        bool p = av[r] > lo;
        unsigned msk = __ballot_sync(0xffffffffu, p);
        if (p) {
            int pos = base + __popc(msk & ((1u << lane) - 1));
            if (pos < 32)
                wkeys[w][pos] =
                    ((ull)__float_as_uint(av[r]) << 32) | (unsigned)(~(r * 32 + lane));
        }
        base += __popc(msk);
    }
    __syncwarp();

    ull key = wkeys[w][lane];
#pragma unroll
    for (int k = 2; k <= 32; k <<= 1) {
#pragma unroll
        for (int j = k >> 1; j; j >>= 1) {
            ull other = __shfl_xor_sync(0xffffffffu, key, j);
            bool dirDesc = ((lane & k) == 0);
            bool upper = (lane & j) != 0;
            bool takeMax = (dirDesc != upper);
            ull mx2 = key > other ? key : other;
            ull mn2 = key > other ? other : key;
            key = takeMax ? mx2 : mn2;
        }
    }

    {
        bool valid = lane < 16;
        float a = __uint_as_float((unsigned)(key >> 32));
        int idx = (int)(~(unsigned)key);
        float maxa = __shfl_sync(0xffffffffu, a, 0);
        float sel = valid ? prow[w][idx] : 0.f;
        float e = valid ? expf(a - maxa) : 0.f;
        float sum = e;
#pragma unroll
        for (int off = 8; off; off >>= 1) sum += __shfl_xor_sync(0xffffffffu, sum, off, 16);
        float sgn = (sel > 0.f) ? 1.f : ((sel < 0.f) ? -1.f : 0.f);
        float edge = sgn * e / sum;
        if (valid) { s_edge[w][lane] = edge; s_eidx[w][lane] = idx; }
    }
    __syncthreads();

    for (int r = 0; r < 8; r++) {
        int bi = b * Mm + i0 + r;
        int d = tid;
        float a0 = g_mem_val1[(size_t)bi * Dd + d];
        float a1 = g_mem_val1[(size_t)bi * Dd + d + 256];
#pragma unroll
        for (int k = 0; k < 16; k++) {
            const float* mv = g_mem_val1 + ((size_t)(b * Mm + s_eidx[r][k])) * Dd;
            float ek = s_edge[r][k];
            a0 = fmaf(ek, mv[d], a0);
            a1 = fmaf(ek, mv[d + 256], a1);
        }
        float mu, ri;
        block_ln_512(a0, a1, mu, ri, swr);
        float* o = out_final + (size_t)bi * Dd;
        o[d]       = (a0 - mu) * ri * ln_g[d] + ln_b[d];
        o[d + 256] = (a1 - mu) * ri * ln_g[d + 256] + ln_b[d + 256];
        __syncthreads();
    }
}

// ---------------- host launch ----------------
extern "C" void kernel_launch(void* const* d_in, const int* in_sizes, int n_in,
                              void* d_out, int out_size) {
    (void)in_sizes; (void)n_in; (void)out_size;
    const float* token_val   = (const float*)d_in[0];
    const float* token_state = (const float*)d_in[1];
    const float* init_state  = (const float*)d_in[2];
    const float* init_val    = (const float*)d_in[3];
    const float* rUs_w = (const float*)d_in[4];
    const float* rUs_b = (const float*)d_in[5];
    const float* rUt_w = (const float*)d_in[6];
    const float* rUt_b = (const float*)d_in[7];
    const float* r_w   = (const float*)d_in[8];
    const float* pUs_w = (const float*)d_in[9];
    const float* pUs_b = (const float*)d_in[10];
    const float* pUt_w = (const float*)d_in[11];
    const float* pUt_b = (const float*)d_in[12];
    const float* p_w   = (const float*)d_in[13];
    const float* ln_g  = (const float*)d_in[14];
    const float* ln_b  = (const float*)d_in[15];
    float* out = (float*)d_out;

    float *p_mv0, *p_mv1, *p_qt, *p_qs2, *p_st0, *p_st1raw, *p_st1;
    float *p_Wh, *p_Wl, *p_pt2h, *p_pt2l;
    cudaGetSymbolAddress((void**)&p_mv0, g_mem_val0);
    cudaGetSymbolAddress((void**)&p_mv1, g_mem_val1);
    cudaGetSymbolAddress((void**)&p_qt, g_qt);
    cudaGetSymbolAddress((void**)&p_qs2, g_qs2);
    cudaGetSymbolAddress((void**)&p_st0, g_mem_state0);
    cudaGetSymbolAddress((void**)&p_st1raw, g_state1_raw);
    cudaGetSymbolAddress((void**)&p_st1, g_state1);
    cudaGetSymbolAddress((void**)&p_Wh, g_Wh);
    cudaGetSymbolAddress((void**)&p_Wl, g_Wl);
    cudaGetSymbolAddress((void**)&p_pt2h, g_pt2_h);
    cudaGetSymbolAddress((void**)&p_pt2l, g_pt2_l);

    const int SC_SMEM = 4 * 128 * 72 * 4;  // 147456 bytes
    cudaFuncSetAttribute(scores_tc_kernel,
                         cudaFuncAttributeMaxDynamicSharedMemorySize, SC_SMEM);
    cudaFuncSetAttribute(gemm_ps_tc,
                         cudaFuncAttributeMaxDynamicSharedMemorySize, PS_SMEM_BYTES);

    // pre-split W for the ps GEMM
    split_kernel<<<(Dd * Rr + 255) / 256, 256>>>(rUs_w, p_Wh, p_Wl, Dd * Rr);
    // mem_val0 = LN(init_val); mem_state0 = sss(init_state)
    ln_rows_kernel<<<Mm, 256>>>(init_val, p_mv0, ln_g, ln_b);
    sss_kernel<<<1, 256>>>(init_state, p_st0);
    // pt2 = (mem_val0 @ rUt + b) * r_w * 0.1  -> written pre-split
    gemm_proj<32><<<dim3(Mm / 32, 1), 256>>>(
        p_mv0, nullptr, rUt_w, rUt_b, r_w, nullptr, p_pt2h, p_pt2l,
        nullptr, nullptr, nullptr, nullptr, nullptr, nullptr, nullptr, nullptr);
    // ps = token_val @ rUs + b  -> written pre-split (tensor cores, cp.async)
    gemm_ps_tc<<<(Bb * Ss) / 128, 256, PS_SMEM_BYTES>>>(token_val, rUs_b);
    // scores = pt2 . ps  (pure MMA from pre-split tiles)
    scores_tc_kernel<<<dim3(Ss / 128, Mm / 128, Bb), 256, SC_SMEM>>>();
    // write phase: bisection topk + edges + gather-add + LN; raw state update
    write_kernel<<<Bb * Mm, 256>>>(token_val, token_state, ln_g, ln_b);
    // state1 = signed_softmax_state(state1_raw)
    sss_kernel<<<Bb, 256>>>(p_st1raw, p_st1);
    // fused: y=0 -> qt ; y=1 -> qs2 (state folded into rows)
    gemm_proj<32><<<dim3((Bb * Mm) / 32, 2), 256>>>(
        p_mv1, p_qt, pUt_w, pUt_b, p_w, nullptr, nullptr, nullptr,
        p_mv1, p_qs2, pUs_w, pUs_b, nullptr, p_st1, nullptr, nullptr);
    // propagation (8 rows/block, warp bisection) + final LN -> out
    prop8_kernel<<<(Bb * Mm) / 8, 256>>>(out, ln_g, ln_b);
}

// round 11
// speedup vs baseline: 1.1296x; 1.1296x over previous
#include <cuda_runtime.h>
#include <math.h>
#include <stdint.h>

// Problem shapes (fixed by the dataset)
constexpr int Bb = 16;    // batch
constexpr int Ss = 2048;  // tokens
constexpr int Dd = 512;   // dim
constexpr int Mm = 256;   // memory slots
constexpr int Rr = 64;    // low rank
constexpr float EPS = 1e-5f;
constexpr float STATE_MASS = 4.0f;
constexpr float LRS = 0.1f;

typedef unsigned long long ull;

// ---------------- scratch (static device globals; no allocs) ----------------
__device__ float g_scores[(size_t)Bb * Mm * Ss];   // 33.5 MB (L2-resident) [b][m][s]
__device__ float g_ps_h[(size_t)Bb * Ss * Rr];     // ps split hi
__device__ float g_ps_l[(size_t)Bb * Ss * Rr];     // ps split lo
__device__ float g_mem_val0[(size_t)Mm * Dd];      // LN(init_val), batch-independent
__device__ float g_pt2_h[(size_t)Mm * Rr];         // pt2 split hi
__device__ float g_pt2_l[(size_t)Mm * Rr];         // pt2 split lo
__device__ float g_Wh[(size_t)Dd * Rr];            // rUs_w split hi
__device__ float g_Wl[(size_t)Dd * Rr];            // rUs_w split lo
__device__ float g_Wth[(size_t)Dd * Rr];           // (rUt_w * r_w * LRS) split hi
__device__ float g_Wtl[(size_t)Dd * Rr];           // (rUt_w * r_w * LRS) split lo
__device__ float g_bt2[Rr];                        // rUt_b * r_w * LRS
__device__ float g_mem_state0[Mm];                 // signed-softmax-state(init_state)
__device__ float g_mem_val1[(size_t)Bb * Mm * Dd]; // post-write, post-LN
__device__ float g_state1_raw[(size_t)Bb * Mm];
__device__ float g_state1[(size_t)Bb * Mm];
__device__ float g_qt[(size_t)Bb * Mm * Rr];       // (mem_val1@pUt + b) * p_w * 0.1
__device__ float g_qs2[(size_t)Bb * Mm * Rr];      // (mem_val1@pUs + b) * state1[b,j]

// ---------------- tf32 / cp.async helpers ----------------
__device__ __forceinline__ uint32_t f2tf32(float x) {
    uint32_t r;
    asm("cvt.rna.tf32.f32 %0, %1;" : "=r"(r) : "f"(x));
    return r;
}

__device__ __forceinline__ void cpa16(void* dst_smem, const void* src) {
    uint32_t d = (uint32_t)__cvta_generic_to_shared(dst_smem);
    asm volatile("cp.async.ca.shared.global [%0], [%1], 16;" :: "r"(d), "l"(src));
}
#define CP_COMMIT() asm volatile("cp.async.commit_group;")
#define CP_WAIT(n)  asm volatile("cp.async.wait_group %0;" :: "n"(n))

#define MMA_TF32(C, A, B0, B1)                                                  \
    asm volatile(                                                               \
        "mma.sync.aligned.m16n8k8.row.col.f32.tf32.tf32.f32 "                   \
        "{%0,%1,%2,%3}, {%4,%5,%6,%7}, {%8,%9}, {%0,%1,%2,%3};"                 \
        : "+f"((C)[0]), "+f"((C)[1]), "+f"((C)[2]), "+f"((C)[3])                \
        : "r"((A)[0]), "r"((A)[1]), "r"((A)[2]), "r"((A)[3]), "r"(B0), "r"(B1))

// ---------------- kernel: split an array into tf32 hi/lo ----------------
__global__ void split_kernel(const float* __restrict__ src, float* __restrict__ dh,
                             float* __restrict__ dl, int n) {
    int i = blockIdx.x * blockDim.x + threadIdx.x;
    if (i < n) {
        float v = src[i];
        float hf = __uint_as_float(f2tf32(v));
        dh[i] = hf;
        dl[i] = __uint_as_float(f2tf32(v - hf));
    }
}

// split with per-column scale: v = src[i] * sc[i % Rr] * LRS
__global__ void split_scaled_kernel(const float* __restrict__ src,
                                    const float* __restrict__ sc,
                                    float* __restrict__ dh, float* __restrict__ dl, int n) {
    int i = blockIdx.x * blockDim.x + threadIdx.x;
    if (i < n) {
        float v = src[i] * sc[i & (Rr - 1)] * LRS;
        float hf = __uint_as_float(f2tf32(v));
        dh[i] = hf;
        dl[i] = __uint_as_float(f2tf32(v - hf));
    }
}

__global__ void scale_bias_kernel(const float* __restrict__ b, const float* __restrict__ sc,
                                  float* __restrict__ out) {
    int i = threadIdx.x;
    if (i < Rr) out[i] = b[i] * sc[i] * LRS;
}

// ---------------- shared helpers ----------------
__device__ __forceinline__ void block_ln_512(float a0, float a1, float& mu, float& ri,
                                             float* swr) {
    float ps = a0 + a1;
    float pq = fmaf(a0, a0, a1 * a1);
#pragma unroll
    for (int off = 16; off; off >>= 1) {
        ps += __shfl_down_sync(0xffffffffu, ps, off);
        pq += __shfl_down_sync(0xffffffffu, pq, off);
    }
    int tid = threadIdx.x, wid = tid >> 5, lane = tid & 31;
    if (lane == 0) { swr[wid] = ps; swr[8 + wid] = pq; }
    __syncthreads();
    if (tid == 0) {
        float s = 0.f, q = 0.f;
#pragma unroll
        for (int i = 0; i < 8; i++) { s += swr[i]; q += swr[8 + i]; }
        float m = s * (1.0f / 512.0f);
        float v = q * (1.0f / 512.0f) - m * m;
        swr[16] = m;
        swr[17] = rsqrtf(v + EPS);
    }
    __syncthreads();
    mu = swr[16];
    ri = swr[17];
}

// ---------------- kernel: LayerNorm rows ----------------
__global__ void ln_rows_kernel(const float* __restrict__ in, float* __restrict__ out,
                               const float* __restrict__ g, const float* __restrict__ bta) {
    __shared__ float swr[18];
    int row = blockIdx.x, tid = threadIdx.x;
    const float* x = in + (size_t)row * Dd;
    float a0 = x[tid], a1 = x[tid + 256];
    float mu, ri;
    block_ln_512(a0, a1, mu, ri, swr);
    float* o = out + (size_t)row * Dd;
    o[tid]       = (a0 - mu) * ri * g[tid] + bta[tid];
    o[tid + 256] = (a1 - mu) * ri * g[tid + 256] + bta[tid + 256];
}

// ---------------- kernel: signed softmax state over 256 slots ----------------
__global__ void sss_kernel(const float* __restrict__ in, float* __restrict__ out) {
    int tid = threadIdx.x;
    const float* x = in + (size_t)blockIdx.x * Mm;
    float v = x[tid];
    float a = fabsf(v);
    __shared__ float swr[8];
    __shared__ float s_bc[2];
    int wid = tid >> 5, lane = tid & 31;
    float m = a;
#pragma unroll
    for (int off = 16; off; off >>= 1) m = fmaxf(m, __shfl_down_sync(0xffffffffu, m, off));
    if (lane == 0) swr[wid] = m;
    __syncthreads();
    if (tid == 0) {
        float mm = swr[0];
#pragma unroll
        for (int i = 1; i < 8; i++) mm = fmaxf(mm, swr[i]);
        s_bc[0] = mm;
    }
    __syncthreads();
    float e = expf(a - s_bc[0]);
    float s = e;
#pragma unroll
    for (int off = 16; off; off >>= 1) s += __shfl_down_sync(0xffffffffu, s, off);
    __syncthreads();
    if (lane == 0) swr[wid] = s;
    __syncthreads();
    if (tid == 0) {
        float ss = 0.f;
#pragma unroll
        for (int i = 0; i < 8; i++) ss += swr[i];
        s_bc[1] = ss;
    }
    __syncthreads();
    float sgn = (v > 0.f) ? 1.f : ((v < 0.f) ? -1.f : 0.f);
    out[(size_t)blockIdx.x * Mm + tid] = sgn * e / s_bc[1] * STATE_MASS;
}

// ---------------- scalar tiled projection (qt / qs2 only) ----------------
template <int RT>
__global__ __launch_bounds__(256) void gemm_proj(
    const float* __restrict__ X0,
    float* __restrict__ out0, const float* __restrict__ W0, const float* __restrict__ b0,
    const float* __restrict__ rs0, const float* __restrict__ rowsc0,
    const float* __restrict__ X1,
    float* __restrict__ out1, const float* __restrict__ W1, const float* __restrict__ b1,
    const float* __restrict__ rs1, const float* __restrict__ rowsc1) {
    constexpr int RPT = RT / 16;
    constexpr int XSTR = RT + 4;
    __shared__ float sx[16 * XSTR];
    __shared__ float sw[16 * 68];

    int tid = threadIdx.x;
    int set = blockIdx.y;
    int row0 = blockIdx.x * RT;
    const float* X     = set ? X1 : X0;
    const float* W     = set ? W1 : W0;
    const float* bias  = set ? b1 : b0;
    const float* rs    = set ? rs1 : rs0;
    const float* rowsc = set ? rowsc1 : rowsc0;
    float* out         = set ? out1 : out0;

    int rowg = tid >> 4;
    int colg = tid & 15;

    float acc[RPT][4];
#pragma unroll
    for (int r = 0; r < RPT; r++)
#pragma unroll
        for (int c = 0; c < 4; c++) acc[r][c] = 0.f;

    for (int k0 = 0; k0 < Dd; k0 += 16) {
        constexpr int NV = RT * 16 / 4;
#pragma unroll
        for (int t = 0; t < (NV + 255) / 256; t++) {
            int f = tid + 256 * t;
            if ((NV % 256 == 0) || (f < NV)) {
                int row = f >> 2, q = f & 3;
                float4 v = *(const float4*)&X[(size_t)(row0 + row) * Dd + k0 + 4 * q];
                sx[(4 * q + 0) * XSTR + row] = v.x;
                sx[(4 * q + 1) * XSTR + row] = v.y;
                sx[(4 * q + 2) * XSTR + row] = v.z;
                sx[(4 * q + 3) * XSTR + row] = v.w;
            }
        }
        {
            int k = tid >> 4, c = tid & 15;
            float4 v = *(const float4*)&W[(size_t)(k0 + k) * Rr + 4 * c];
            *(float4*)&sw[k * 68 + 4 * c] = v;
        }
        __syncthreads();
#pragma unroll
        for (int kk = 0; kk < 16; kk++) {
            float4 wv = *(const float4*)&sw[kk * 68 + colg * 4];
            float xr[RPT];
            float2 x0 = *(const float2*)&sx[kk * XSTR + rowg * RPT];
            xr[0] = x0.x; xr[1] = x0.y;
#pragma unroll
            for (int r = 0; r < RPT; r++) {
                acc[r][0] = fmaf(xr[r], wv.x, acc[r][0]);
                acc[r][1] = fmaf(xr[r], wv.y, acc[r][1]);
                acc[r][2] = fmaf(xr[r], wv.z, acc[r][2]);
                acc[r][3] = fmaf(xr[r], wv.w, acc[r][3]);
            }
        }
        __syncthreads();
    }

    float4 bv = *(const float4*)&bias[colg * 4];
    float s0 = 1.f, s1 = 1.f, s2 = 1.f, s3 = 1.f;
    if (rs) {
        float4 rv = *(const float4*)&rs[colg * 4];
        s0 = rv.x * LRS; s1 = rv.y * LRS; s2 = rv.z * LRS; s3 = rv.w * LRS;
    }
#pragma unroll
    for (int r = 0; r < RPT; r++) {
        int row = row0 + rowg * RPT + r;
        float rsc = rowsc ? rowsc[row] : 1.f;
        float4 o;
        o.x = (acc[r][0] + bv.x) * s0 * rsc;
        o.y = (acc[r][1] + bv.y) * s1 * rsc;
        o.z = (acc[r][2] + bv.z) * s2 * rsc;
        o.w = (acc[r][3] + bv.w) * s3 * rsc;
        *(float4*)&out[(size_t)row * Rr + colg * 4] = o;
    }
}

// ---------------- tensor-core projection GEMM (fused ps + pt2) ----------
// Blocks [0,split): out = X0 @ W0 + b0 ; blocks [split,..): X1 @ W1 + b1.
// 3xTF32, cp.async 3-stage, pre-split W, split hi/lo outputs.
constexpr int PS_XOFF = 0;               // per-stage X offset (floats)
constexpr int PS_WHOFF = 128 * 20;       // per-stage Wh offset
constexpr int PS_WLOFF = 128 * 20 + 16 * 72;
constexpr int PS_STAGE = 128 * 20 + 2 * 16 * 72;  // floats per stage = 4864
constexpr int PS_SMEM_BYTES = 3 * PS_STAGE * 4;   // 58368

__global__ __launch_bounds__(256) void gemm_ps_tc(
    int split,
    const float* __restrict__ X0, const float* __restrict__ b0,
    const float* __restrict__ Wh0, const float* __restrict__ Wl0,
    float* __restrict__ oh0, float* __restrict__ ol0,
    const float* __restrict__ X1, const float* __restrict__ b1,
    const float* __restrict__ Wh1, const float* __restrict__ Wl1,
    float* __restrict__ oh1, float* __restrict__ ol1) {
    extern __shared__ __align__(16) float smp[];
    int tid = threadIdx.x, w = tid >> 5, lane = tid & 31;
    int g = lane >> 2, tg = lane & 3;
    int set = ((int)blockIdx.x >= split);
    int rowblk = set ? (int)blockIdx.x - split : (int)blockIdx.x;
    const float* X    = set ? X1 : X0;
    const float* bias = set ? b1 : b0;
    const float* Wh   = set ? Wh1 : Wh0;
    const float* Wl   = set ? Wl1 : Wl0;
    float* oh         = set ? oh1 : oh0;
    float* ol         = set ? ol1 : ol0;
    int row0 = rowblk * 128;
    int wm = w >> 1, wn = w & 1;

    int lr = tid >> 2, lq = (tid & 3) * 4;   // X cp.async coords (rows lr, lr+64)
    int wk = tid >> 4, wc = (tid & 15) * 4;  // W cp.async coords

    float acc[2][4][4];
#pragma unroll
    for (int mt = 0; mt < 2; mt++)
#pragma unroll
        for (int nt = 0; nt < 4; nt++)
#pragma unroll
            for (int c = 0; c < 4; c++) acc[mt][nt][c] = 0.f;

#pragma unroll
    for (int pc = 0; pc < 2; pc++) {
        int k0 = pc * 16;
        float* st = smp + pc * PS_STAGE;
        cpa16(st + PS_XOFF + lr * 20 + lq,        &X[(size_t)(row0 + lr) * Dd + k0 + lq]);
        cpa16(st + PS_XOFF + (lr + 64) * 20 + lq, &X[(size_t)(row0 + lr + 64) * Dd + k0 + lq]);
        cpa16(st + PS_WHOFF + wk * 72 + wc,       &Wh[(size_t)(k0 + wk) * Rr + wc]);
        cpa16(st + PS_WLOFF + wk * 72 + wc,       &Wl[(size_t)(k0 + wk) * Rr + wc]);
        CP_COMMIT();
    }

    for (int c = 0; c < 32; c++) {
        CP_WAIT(1);
        __syncthreads();
        float* st = smp + (c % 3) * PS_STAGE;
        float* sx = st + PS_XOFF;
        float* swh = st + PS_WHOFF;
        float* swl = st + PS_WLOFF;
#pragma unroll
        for (int ks = 0; ks < 2; ks++) {
            int kk = ks * 8;
            uint32_t ah[2][4], al[2][4];
#pragma unroll
            for (int mt = 0; mt < 2; mt++) {
                int r = wm * 32 + mt * 16;
                float x0 = sx[(r + g) * 20 + kk + tg];
                float x1 = sx[(r + g + 8) * 20 + kk + tg];
                float x2 = sx[(r + g) * 20 + kk + tg + 4];
                float x3 = sx[(r + g + 8) * 20 + kk + tg + 4];
                ah[mt][0] = f2tf32(x0); al[mt][0] = f2tf32(x0 - __uint_as_float(ah[mt][0]));
                ah[mt][1] = f2tf32(x1); al[mt][1] = f2tf32(x1 - __uint_as_float(ah[mt][1]));
                ah[mt][2] = f2tf32(x2); al[mt][2] = f2tf32(x2 - __uint_as_float(ah[mt][2]));
                ah[mt][3] = f2tf32(x3); al[mt][3] = f2tf32(x3 - __uint_as_float(ah[mt][3]));
            }
#pragma unroll
            for (int nt = 0; nt < 4; nt++) {
                int cc = wn * 32 + nt * 8 + g;
                uint32_t bh0 = __float_as_uint(swh[(kk + tg) * 72 + cc]);
                uint32_t bh1 = __float_as_uint(swh[(kk + tg + 4) * 72 + cc]);
                uint32_t bl0 = __float_as_uint(swl[(kk + tg) * 72 + cc]);
                uint32_t bl1 = __float_as_uint(swl[(kk + tg + 4) * 72 + cc]);
#pragma unroll
                for (int mt = 0; mt < 2; mt++) {
                    MMA_TF32(acc[mt][nt], ah[mt], bh0, bh1);
                    MMA_TF32(acc[mt][nt], ah[mt], bl0, bl1);
                    MMA_TF32(acc[mt][nt], al[mt], bh0, bh1);
                }
            }
        }
        __syncthreads();
        int nc = c + 2;
        if (nc < 32) {
            int k0 = nc * 16;
            float* s2 = smp + (nc % 3) * PS_STAGE;
            cpa16(s2 + PS_XOFF + lr * 20 + lq,        &X[(size_t)(row0 + lr) * Dd + k0 + lq]);
            cpa16(s2 + PS_XOFF + (lr + 64) * 20 + lq, &X[(size_t)(row0 + lr + 64) * Dd + k0 + lq]);
            cpa16(s2 + PS_WHOFF + wk * 72 + wc,       &Wh[(size_t)(k0 + wk) * Rr + wc]);
            cpa16(s2 + PS_WLOFF + wk * 72 + wc,       &Wl[(size_t)(k0 + wk) * Rr + wc]);
        }
        CP_COMMIT();
    }

    // epilogue: add bias, split to hi/lo, store
#pragma unroll
    for (int mt = 0; mt < 2; mt++) {
        int r = row0 + wm * 32 + mt * 16 + g;
#pragma unroll
        for (int nt = 0; nt < 4; nt++) {
            int c = wn * 32 + nt * 8 + 2 * tg;
            float b0v = bias[c], b1v = bias[c + 1];
            float v00 = acc[mt][nt][0] + b0v, v01 = acc[mt][nt][1] + b1v;
            float v10 = acc[mt][nt][2] + b0v, v11 = acc[mt][nt][3] + b1v;
            float h00 = __uint_as_float(f2tf32(v00));
            float h01 = __uint_as_float(f2tf32(v01));
            float h10 = __uint_as_float(f2tf32(v10));
            float h11 = __uint_as_float(f2tf32(v11));
            *(float2*)&oh[(size_t)r * Rr + c]       = make_float2(h00, h01);
            *(float2*)&oh[(size_t)(r + 8) * Rr + c] = make_float2(h10, h11);
            *(float2*)&ol[(size_t)r * Rr + c] = make_float2(
                __uint_as_float(f2tf32(v00 - h00)), __uint_as_float(f2tf32(v01 - h01)));
            *(float2*)&ol[(size_t)(r + 8) * Rr + c] = make_float2(
                __uint_as_float(f2tf32(v10 - h10)), __uint_as_float(f2tf32(v11 - h11)));
        }
    }
}

// ---------------- tensor-core scores GEMM: pure MMA from pre-split tiles ----------
// Block 128 m x 128 s; all four K=64 tiles staged once (147.5 KB dynamic smem).
__global__ __launch_bounds__(256) void scores_tc_kernel() {
    extern __shared__ __align__(16) float smc[];
    float (*sah)[72] = (float(*)[72])smc;                    // pt2 hi [m][k]
    float (*sal)[72] = (float(*)[72])(smc + 128 * 72);       // pt2 lo
    float (*sbh)[72] = (float(*)[72])(smc + 2 * 128 * 72);   // ps hi [s][k]
    float (*sbl)[72] = (float(*)[72])(smc + 3 * 128 * 72);   // ps lo
    int tid = threadIdx.x, w = tid >> 5, lane = tid & 31;
    int g = lane >> 2, tg = lane & 3;
    int b = blockIdx.z;
    int m0 = blockIdx.y * 128;
    int s0 = blockIdx.x * 128;
    int wm = w >> 1, wn = w & 1;

#pragma unroll
    for (int t = 0; t < 8; t++) {
        int f = tid + 256 * t;
        int r = f >> 4, q = (f & 15) * 4;
        cpa16(&sah[r][q], &g_pt2_h[(size_t)(m0 + r) * Rr + q]);
        cpa16(&sal[r][q], &g_pt2_l[(size_t)(m0 + r) * Rr + q]);
        cpa16(&sbh[r][q], &g_ps_h[((size_t)b * Ss + s0 + r) * Rr + q]);
        cpa16(&sbl[r][q], &g_ps_l[((size_t)b * Ss + s0 + r) * Rr + q]);
    }
    CP_COMMIT();

    float acc[2][8][4];
#pragma unroll
    for (int mt = 0; mt < 2; mt++)
#pragma unroll
        for (int nt = 0; nt < 8; nt++)
#pragma unroll
            for (int c = 0; c < 4; c++) acc[mt][nt][c] = 0.f;

    CP_WAIT(0);
    __syncthreads();

#pragma unroll
    for (int ks = 0; ks < 8; ks++) {
        int kk = ks * 8;
        uint32_t ah[2][4], al[2][4];
#pragma unroll
        for (int mt = 0; mt < 2; mt++) {
            int r = wm * 32 + mt * 16;
            ah[mt][0] = __float_as_uint(sah[r + g][kk + tg]);
            ah[mt][1] = __float_as_uint(sah[r + g + 8][kk + tg]);
            ah[mt][2] = __float_as_uint(sah[r + g][kk + tg + 4]);
            ah[mt][3] = __float_as_uint(sah[r + g + 8][kk + tg + 4]);
            al[mt][0] = __float_as_uint(sal[r + g][kk + tg]);
            al[mt][1] = __float_as_uint(sal[r + g + 8][kk + tg]);
            al[mt][2] = __float_as_uint(sal[r + g][kk + tg + 4]);
            al[mt][3] = __float_as_uint(sal[r + g + 8][kk + tg + 4]);
        }
#pragma unroll
        for (int nt = 0; nt < 8; nt++) {
            int cc = wn * 64 + nt * 8 + g;
            uint32_t bh0 = __float_as_uint(sbh[cc][kk + tg]);
            uint32_t bh1 = __float_as_uint(sbh[cc][kk + tg + 4]);
            uint32_t bl0 = __float_as_uint(sbl[cc][kk + tg]);
            uint32_t bl1 = __float_as_uint(sbl[cc][kk + tg + 4]);
#pragma unroll
            for (int mt = 0; mt < 2; mt++) {
                MMA_TF32(acc[mt][nt], ah[mt], bh0, bh1);
                MMA_TF32(acc[mt][nt], ah[mt], bl0, bl1);
                MMA_TF32(acc[mt][nt], al[mt], bh0, bh1);
            }
        }
    }

#pragma unroll
    for (int mt = 0; mt < 2; mt++) {
        int m = m0 + wm * 32 + mt * 16 + g;
#pragma unroll
        for (int nt = 0; nt < 8; nt++) {
            int s = s0 + wn * 64 + nt * 8 + 2 * tg;
            *(float2*)&g_scores[((size_t)(b * Mm + m)) * Ss + s] =
                make_float2(acc[mt][nt][0], acc[mt][nt][1]);
            *(float2*)&g_scores[((size_t)(b * Mm + m + 8)) * Ss + s] =
                make_float2(acc[mt][nt][2], acc[mt][nt][3]);
        }
    }
}

// ---------------- write phase: count-bisection top-16 + edges + gather + LN ----------------
__global__ __launch_bounds__(256) void write_kernel(
    const float* __restrict__ token_val, const float* __restrict__ token_state,
    const float* __restrict__ ln_g, const float* __restrict__ ln_b) {
    int bm = blockIdx.x;
    int b = bm >> 8, m = bm & 255;
    int tid = threadIdx.x, w = tid >> 5, lane = tid & 31;
    __shared__ ull skeys[64];
    __shared__ float swr[18];
    __shared__ int s_ic[8];
    __shared__ int s_tot;
    __shared__ float s_edge[16];
    __shared__ int s_eidx[16];

    const float* row = g_scores + (size_t)bm * Ss;

    float aa[8];
#pragma unroll
    for (int j = 0; j < 8; j++) aa[j] = fabsf(row[tid + 256 * j]);

    {
        unsigned um = 0;
#pragma unroll
        for (int j = 0; j < 8; j++) um = max(um, __float_as_uint(aa[j]));
        um = __reduce_max_sync(0xffffffffu, um);
        if (lane == 0) s_ic[w] = (int)um;
        __syncthreads();
        if (tid == 0) {
            unsigned mm = (unsigned)s_ic[0];
#pragma unroll
            for (int i = 1; i < 8; i++) mm = max(mm, (unsigned)s_ic[i]);
            swr[16] = __uint_as_float(mm);
        }
        __syncthreads();
    }
    float hi = swr[16], lo = 0.f;
    int cl = Ss;

    for (int it = 0; it < 32 && cl > 64; it++) {
        float mid = 0.5f * (lo + hi);
        int c = 0;
#pragma unroll
        for (int j = 0; j < 8; j++) c += (aa[j] > mid);
        c = (int)__reduce_add_sync(0xffffffffu, (unsigned)c);
        if (lane == 0) s_ic[w] = c;
        __syncthreads();
        if (tid == 0) {
            int t = 0;
#pragma unroll
            for (int i = 0; i < 8; i++) t += s_ic[i];
            s_tot = t;
        }
        __syncthreads();
        int tot = s_tot;
        if (tot >= 16) { lo = mid; cl = tot; } else { hi = mid; }
        __syncthreads();
    }

    if (tid == 0) s_tot = 0;
    if (tid < 64) skeys[tid] = 0ull;
    __syncthreads();
#pragma unroll
    for (int j = 0; j < 8; j++) {
        if (aa[j] > lo) {
            int p = atomicAdd(&s_tot, 1);
            if (p < 64)
                skeys[p] = ((ull)__float_as_uint(aa[j]) << 32) | (unsigned)(~(tid + 256 * j));
        }
    }
    __syncthreads();

    for (int k = 2; k <= 64; k <<= 1) {
        for (int j = k >> 1; j; j >>= 1) {
            int i = tid, l = i ^ j;
            if (i < 64 && l > i) {
                ull a = skeys[i], bq = skeys[l];
                bool sw2 = ((i & k) == 0) ? (a < bq) : (a > bq);
                if (sw2) { skeys[i] = bq; skeys[l] = a; }
            }
            __syncthreads();
        }
    }

    if (w == 0) {
        bool valid = lane < 16;
        ull key = skeys[valid ? lane : 0];
        float a = __uint_as_float((unsigned)(key >> 32));
        int idx = (int)(~(unsigned)key);
        float maxa = __shfl_sync(0xffffffffu, a, 0);
        float sel = valid ? row[idx] : 0.f;
        float e = valid ? expf(a - maxa) : 0.f;
        float sum = e;
#pragma unroll
        for (int off = 8; off; off >>= 1) sum += __shfl_xor_sync(0xffffffffu, sum, off, 16);
        float sgn = (sel > 0.f) ? 1.f : ((sel < 0.f) ? -1.f : 0.f);
        float edge = sgn * e / sum;
        if (valid) { s_edge[lane] = edge; s_eidx[lane] = idx; }
        float c = valid ? edge * token_state[(size_t)b * Ss + idx] : 0.f;
#pragma unroll
        for (int off = 8; off; off >>= 1) c += __shfl_xor_sync(0xffffffffu, c, off, 16);
        if (lane == 0) g_state1_raw[bm] = g_mem_state0[m] + c;
    }
    __syncthreads();

    int d = tid;
    float a0 = g_mem_val0[(size_t)m * Dd + d];
    float a1 = g_mem_val0[(size_t)m * Dd + d + 256];
#pragma unroll
    for (int k = 0; k < 16; k++) {
        const float* tv = token_val + ((size_t)b * Ss + s_eidx[k]) * Dd;
        float ek = s_edge[k];
        a0 = fmaf(ek, tv[d], a0);
        a1 = fmaf(ek, tv[d + 256], a1);
    }
    float mu, ri;
    block_ln_512(a0, a1, mu, ri, swr);
    float* o = g_mem_val1 + (size_t)bm * Dd;
    o[d]       = (a0 - mu) * ri * ln_g[d] + ln_b[d];
    o[d + 256] = (a1 - mu) * ri * ln_g[d + 256] + ln_b[d + 256];
}

// ---------------- propagation: 8 rows/block, per-warp bisection top-16 ----------------
__global__ __launch_bounds__(256) void prop8_kernel(
    float* __restrict__ out_final, const float* __restrict__ ln_g,
    const float* __restrict__ ln_b) {
    int b = blockIdx.x >> 5;
    int i0 = (blockIdx.x & 31) * 8;
    int tid = threadIdx.x, w = tid >> 5, lane = tid & 31;
    __shared__ float s_qt[8][68];
    __shared__ float sqs[32][68];
    __shared__ float prow[8][256];
    __shared__ ull wkeys[8][32];
    __shared__ float s_edge[8][16];
    __shared__ int s_eidx[8][16];
    __shared__ float swr[18];

    if (tid < 128) {
        int r = tid >> 4, q = tid & 15;
        *(float4*)&s_qt[r][q * 4] =
            *(const float4*)&g_qt[((size_t)(b * Mm + i0 + r)) * Rr + 4 * q];
    }
    __syncthreads();

    float pv[8];
    for (int j0 = 0; j0 < Mm; j0 += 32) {
#pragma unroll
        for (int t = 0; t < 2; t++) {
            int f = tid + 256 * t;
            int jj = f >> 4, q = f & 15;
            *(float4*)&sqs[jj][q * 4] =
                *(const float4*)&g_qs2[((size_t)(b * Mm + j0 + jj)) * Rr + 4 * q];
        }
        __syncthreads();
        float acc = 0.f;
#pragma unroll
        for (int k4 = 0; k4 < Rr; k4 += 4) {
            float4 qv = *(const float4*)&sqs[lane][k4];
            float4 tv = *(const float4*)&s_qt[w][k4];
            acc = fmaf(qv.x, tv.x, fmaf(qv.y, tv.y, fmaf(qv.z, tv.z, fmaf(qv.w, tv.w, acc))));
        }
        pv[j0 >> 5] = acc;
        prow[w][j0 + lane] = acc;
        __syncthreads();
    }

    float av[8];
#pragma unroll
    for (int r = 0; r < 8; r++) av[r] = fabsf(pv[r]);
    unsigned um = 0;
#pragma unroll
    for (int r = 0; r < 8; r++) um = max(um, __float_as_uint(av[r]));
    um = __reduce_max_sync(0xffffffffu, um);
    float hi = __uint_as_float(um), lo = 0.f;
    int cl = 256;
    for (int it = 0; it < 32 && cl > 32; it++) {
        float mid = 0.5f * (lo + hi);
        int c = 0;
#pragma unroll
        for (int r = 0; r < 8; r++) c += (av[r] > mid);
        c = (int)__reduce_add_sync(0xffffffffu, (unsigned)c);
        if (c >= 16) { lo = mid; cl = c; } else { hi = mid; }
    }

    wkeys[w][lane] = 0ull;
    __syncwarp();
    int base = 0;
#pragma unroll
    for (int r = 0; r < 8; r++) {
        bool p = av[r] > lo;
        unsigned msk = __ballot_sync(0xffffffffu, p);
        if (p) {
            int pos = base + __popc(msk & ((1u << lane) - 1));
            if (pos < 32)
                wkeys[w][pos] =
                    ((ull)__float_as_uint(av[r]) << 32) | (unsigned)(~(r * 32 + lane));
        }
        base += __popc(msk);
    }
    __syncwarp();

    ull key = wkeys[w][lane];
#pragma unroll
    for (int k = 2; k <= 32; k <<= 1) {
#pragma unroll
        for (int j = k >> 1; j; j >>= 1) {
            ull other = __shfl_xor_sync(0xffffffffu, key, j);
            bool dirDesc = ((lane & k) == 0);
            bool upper = (lane & j) != 0;
            bool takeMax = (dirDesc != upper);
            ull mx2 = key > other ? key : other;
            ull mn2 = key > other ? other : key;
            key = takeMax ? mx2 : mn2;
        }
    }

    {
        bool valid = lane < 16;
        float a = __uint_as_float((unsigned)(key >> 32));
        int idx = (int)(~(unsigned)key);
        float maxa = __shfl_sync(0xffffffffu, a, 0);
        float sel = valid ? prow[w][idx] : 0.f;
        float e = valid ? expf(a - maxa) : 0.f;
        float sum = e;
#pragma unroll
        for (int off = 8; off; off >>= 1) sum += __shfl_xor_sync(0xffffffffu, sum, off, 16);
        float sgn = (sel > 0.f) ? 1.f : ((sel < 0.f) ? -1.f : 0.f);
        float edge = sgn * e / sum;
        if (valid) { s_edge[w][lane] = edge; s_eidx[w][lane] = idx; }
    }
    __syncthreads();

    for (int r = 0; r < 8; r++) {
        int bi = b * Mm + i0 + r;
        int d = tid;
        float a0 = g_mem_val1[(size_t)bi * Dd + d];
        float a1 = g_mem_val1[(size_t)bi * Dd + d + 256];
#pragma unroll
        for (int k = 0; k < 16; k++) {
            const float* mv = g_mem_val1 + ((size_t)(b * Mm + s_eidx[r][k])) * Dd;
            float ek = s_edge[r][k];
            a0 = fmaf(ek, mv[d], a0);
            a1 = fmaf(ek, mv[d + 256], a1);
        }
        float mu, ri;
        block_ln_512(a0, a1, mu, ri, swr);
        float* o = out_final + (size_t)bi * Dd;
        o[d]       = (a0 - mu) * ri * ln_g[d] + ln_b[d];
        o[d + 256] = (a1 - mu) * ri * ln_g[d + 256] + ln_b[d + 256];
        __syncthreads();
    }
}

// ---------------- host launch ----------------
extern "C" void kernel_launch(void* const* d_in, const int* in_sizes, int n_in,
                              void* d_out, int out_size) {
    (void)in_sizes; (void)n_in; (void)out_size;
    const float* token_val   = (const float*)d_in[0];
    const float* token_state = (const float*)d_in[1];
    const float* init_state  = (const float*)d_in[2];
    const float* init_val    = (const float*)d_in[3];
    const float* rUs_w = (const float*)d_in[4];
    const float* rUs_b = (const float*)d_in[5];
    const float* rUt_w = (const float*)d_in[6];
    const float* rUt_b = (const float*)d_in[7];
    const float* r_w   = (const float*)d_in[8];
    const float* pUs_w = (const float*)d_in[9];
    const float* pUs_b = (const float*)d_in[10];
    const float* pUt_w = (const float*)d_in[11];
    const float* pUt_b = (const float*)d_in[12];
    const float* p_w   = (const float*)d_in[13];
    const float* ln_g  = (const float*)d_in[14];
    const float* ln_b  = (const float*)d_in[15];
    float* out = (float*)d_out;

    float *p_mv0, *p_mv1, *p_qt, *p_qs2, *p_st0, *p_st1raw, *p_st1;
    float *p_Wh, *p_Wl, *p_Wth, *p_Wtl, *p_bt2, *p_pt2h, *p_pt2l, *p_psh, *p_psl;
    cudaGetSymbolAddress((void**)&p_mv0, g_mem_val0);
    cudaGetSymbolAddress((void**)&p_mv1, g_mem_val1);
    cudaGetSymbolAddress((void**)&p_qt, g_qt);
    cudaGetSymbolAddress((void**)&p_qs2, g_qs2);
    cudaGetSymbolAddress((void**)&p_st0, g_mem_state0);
    cudaGetSymbolAddress((void**)&p_st1raw, g_state1_raw);
    cudaGetSymbolAddress((void**)&p_st1, g_state1);
    cudaGetSymbolAddress((void**)&p_Wh, g_Wh);
    cudaGetSymbolAddress((void**)&p_Wl, g_Wl);
    cudaGetSymbolAddress((void**)&p_Wth, g_Wth);
    cudaGetSymbolAddress((void**)&p_Wtl, g_Wtl);
    cudaGetSymbolAddress((void**)&p_bt2, g_bt2);
    cudaGetSymbolAddress((void**)&p_pt2h, g_pt2_h);
    cudaGetSymbolAddress((void**)&p_pt2l, g_pt2_l);
    cudaGetSymbolAddress((void**)&p_psh, g_ps_h);
    cudaGetSymbolAddress((void**)&p_psl, g_ps_l);

    const int SC_SMEM = 4 * 128 * 72 * 4;  // 147456 bytes
    cudaFuncSetAttribute(scores_tc_kernel,
                         cudaFuncAttributeMaxDynamicSharedMemorySize, SC_SMEM);
    cudaFuncSetAttribute(gemm_ps_tc,
                         cudaFuncAttributeMaxDynamicSharedMemorySize, PS_SMEM_BYTES);

    // pre-split weights: rUs_w raw; rUt_w scaled by r_w*LRS (column scale commutes)
    split_kernel<<<(Dd * Rr + 255) / 256, 256>>>(rUs_w, p_Wh, p_Wl, Dd * Rr);
    split_scaled_kernel<<<(Dd * Rr + 255) / 256, 256>>>(rUt_w, r_w, p_Wth, p_Wtl, Dd * Rr);
    scale_bias_kernel<<<1, 64>>>(rUt_b, r_w, p_bt2);
    // mem_val0 = LN(init_val); mem_state0 = sss(init_state)
    ln_rows_kernel<<<Mm, 256>>>(init_val, p_mv0, ln_g, ln_b);
    sss_kernel<<<1, 256>>>(init_state, p_st0);
    // fused TC projection: blocks [0,256) -> ps; [256,258) -> pt2 (both written pre-split)
    gemm_ps_tc<<<(Bb * Ss) / 128 + Mm / 128, 256, PS_SMEM_BYTES>>>(
        (Bb * Ss) / 128,
        token_val, rUs_b, p_Wh, p_Wl, p_psh, p_psl,
        p_mv0, p_bt2, p_Wth, p_Wtl, p_pt2h, p_pt2l);
    // scores = pt2 . ps  (pure MMA from pre-split tiles)
    scores_tc_kernel<<<dim3(Ss / 128, Mm / 128, Bb), 256, SC_SMEM>>>();
    // write phase: bisection topk + edges + gather-add + LN; raw state update
    write_kernel<<<Bb * Mm, 256>>>(token_val, token_state, ln_g, ln_b);
    // state1 = signed_softmax_state(state1_raw)
    sss_kernel<<<Bb, 256>>>(p_st1raw, p_st1);
    // fused: y=0 -> qt ; y=1 -> qs2 (state folded into rows)
    gemm_proj<32><<<dim3((Bb * Mm) / 32, 2), 256>>>(
        p_mv1, p_qt, pUt_w, pUt_b, p_w, nullptr,
        p_mv1, p_qs2, pUs_w, pUs_b, nullptr, p_st1);
    // propagation (8 rows/block, warp bisection) + final LN -> out
    prop8_kernel<<<(Bb * Mm) / 8, 256>>>(out, ln_g, ln_b);
}

// round 12
// speedup vs baseline: 1.1614x; 1.0281x over previous
#include <cuda_runtime.h>
#include <math.h>
#include <stdint.h>

// Problem shapes (fixed by the dataset)
constexpr int Bb = 16;    // batch
constexpr int Ss = 2048;  // tokens
constexpr int Dd = 512;   // dim
constexpr int Mm = 256;   // memory slots
constexpr int Rr = 64;    // low rank
constexpr float EPS = 1e-5f;
constexpr float STATE_MASS = 4.0f;
constexpr float LRS = 0.1f;

typedef unsigned long long ull;

// ---------------- scratch (static device globals; no allocs) ----------------
__device__ float g_scores[(size_t)Bb * Mm * Ss];   // 33.5 MB (L2-resident) [b][m][s]
__device__ float g_ps_h[(size_t)Bb * Ss * Rr];     // ps split hi
__device__ float g_ps_l[(size_t)Bb * Ss * Rr];     // ps split lo
__device__ float g_mem_val0[(size_t)Mm * Dd];      // LN(init_val), batch-independent
__device__ float g_pt2_h[(size_t)Mm * Rr];         // pt2 split hi
__device__ float g_pt2_l[(size_t)Mm * Rr];         // pt2 split lo
__device__ float g_Wh[(size_t)Dd * Rr];            // rUs_w split hi
__device__ float g_Wl[(size_t)Dd * Rr];            // rUs_w split lo
__device__ float g_Wth[(size_t)Dd * Rr];           // (rUt_w * r_w * LRS) split hi
__device__ float g_Wtl[(size_t)Dd * Rr];           // (rUt_w * r_w * LRS) split lo
__device__ float g_bt2[Rr];                        // rUt_b * r_w * LRS
__device__ float g_mem_state0[Mm];                 // signed-softmax-state(init_state)
__device__ float g_mem_val1[(size_t)Bb * Mm * Dd]; // post-write, post-LN
__device__ float g_state1_raw[(size_t)Bb * Mm];
__device__ float g_state1[(size_t)Bb * Mm];
__device__ float g_qt[(size_t)Bb * Mm * Rr];       // (mem_val1@pUt + b) * p_w * 0.1
__device__ float g_qs2[(size_t)Bb * Mm * Rr];      // (mem_val1@pUs + b) * state1[b,j]

// ---------------- tf32 / cp.async helpers ----------------
__device__ __forceinline__ uint32_t f2tf32(float x) {
    uint32_t r;
    asm("cvt.rna.tf32.f32 %0, %1;" : "=r"(r) : "f"(x));
    return r;
}

__device__ __forceinline__ void cpa16(void* dst_smem, const void* src) {
    uint32_t d = (uint32_t)__cvta_generic_to_shared(dst_smem);
    asm volatile("cp.async.ca.shared.global [%0], [%1], 16;" :: "r"(d), "l"(src));
}
#define CP_COMMIT() asm volatile("cp.async.commit_group;")
#define CP_WAIT(n)  asm volatile("cp.async.wait_group %0;" :: "n"(n))

#define MMA_TF32(C, A, B0, B1)                                                  \
    asm volatile(                                                               \
        "mma.sync.aligned.m16n8k8.row.col.f32.tf32.tf32.f32 "                   \
        "{%0,%1,%2,%3}, {%4,%5,%6,%7}, {%8,%9}, {%0,%1,%2,%3};"                 \
        : "+f"((C)[0]), "+f"((C)[1]), "+f"((C)[2]), "+f"((C)[3])                \
        : "r"((A)[0]), "r"((A)[1]), "r"((A)[2]), "r"((A)[3]), "r"(B0), "r"(B1))

// ---------------- shared helpers ----------------
__device__ __forceinline__ void block_ln_512(float a0, float a1, float& mu, float& ri,
                                             float* swr) {
    float ps = a0 + a1;
    float pq = fmaf(a0, a0, a1 * a1);
#pragma unroll
    for (int off = 16; off; off >>= 1) {
        ps += __shfl_down_sync(0xffffffffu, ps, off);
        pq += __shfl_down_sync(0xffffffffu, pq, off);
    }
    int tid = threadIdx.x, wid = tid >> 5, lane = tid & 31;
    if (lane == 0) { swr[wid] = ps; swr[8 + wid] = pq; }
    __syncthreads();
    if (tid == 0) {
        float s = 0.f, q = 0.f;
#pragma unroll
        for (int i = 0; i < 8; i++) { s += swr[i]; q += swr[8 + i]; }
        float m = s * (1.0f / 512.0f);
        float v = q * (1.0f / 512.0f) - m * m;
        swr[16] = m;
        swr[17] = rsqrtf(v + EPS);
    }
    __syncthreads();
    mu = swr[16];
    ri = swr[17];
}

__device__ __forceinline__ void split2(float v, float& h, float& l) {
    h = __uint_as_float(f2tf32(v));
    l = __uint_as_float(f2tf32(v - h));
}

// ---------------- fused prologue kernel ----------------
// blocks [0,256): LN rows of init_val -> g_mem_val0
// blocks [256,272): split rUs_w -> g_Wh/g_Wl
// blocks [272,288): split rUt_w * r_w * LRS -> g_Wth/g_Wtl
// block 288: signed-softmax-state(init_state) -> g_mem_state0
// block 289: g_bt2 = rUt_b * r_w * LRS
__global__ __launch_bounds__(256) void prep_kernel(
    const float* __restrict__ init_val, const float* __restrict__ init_state,
    const float* __restrict__ rUs_w, const float* __restrict__ rUt_w,
    const float* __restrict__ rUt_b, const float* __restrict__ r_w,
    const float* __restrict__ ln_g, const float* __restrict__ ln_b) {
    __shared__ float swr[18];
    __shared__ float s_bc[2];
    int blk = blockIdx.x, tid = threadIdx.x;
    int wid = tid >> 5, lane = tid & 31;

    if (blk < 256) {
        const float* x = init_val + (size_t)blk * Dd;
        float a0 = x[tid], a1 = x[tid + 256];
        float mu, ri;
        block_ln_512(a0, a1, mu, ri, swr);
        float* o = g_mem_val0 + (size_t)blk * Dd;
        o[tid]       = (a0 - mu) * ri * ln_g[tid] + ln_b[tid];
        o[tid + 256] = (a1 - mu) * ri * ln_g[tid + 256] + ln_b[tid + 256];
    } else if (blk < 272) {
        int base = (blk - 256) * 2048 + tid * 8;
#pragma unroll
        for (int q = 0; q < 2; q++) {
            float4 v = *(const float4*)&rUs_w[base + 4 * q];
            float4 h, l;
            split2(v.x, h.x, l.x); split2(v.y, h.y, l.y);
            split2(v.z, h.z, l.z); split2(v.w, h.w, l.w);
            *(float4*)&g_Wh[base + 4 * q] = h;
            *(float4*)&g_Wl[base + 4 * q] = l;
        }
    } else if (blk < 288) {
        int base = (blk - 272) * 2048 + tid * 8;
#pragma unroll
        for (int q = 0; q < 2; q++) {
            int i = base + 4 * q;
            float4 v = *(const float4*)&rUt_w[i];
            v.x *= r_w[(i + 0) & 63] * LRS;
            v.y *= r_w[(i + 1) & 63] * LRS;
            v.z *= r_w[(i + 2) & 63] * LRS;
            v.w *= r_w[(i + 3) & 63] * LRS;
            float4 h, l;
            split2(v.x, h.x, l.x); split2(v.y, h.y, l.y);
            split2(v.z, h.z, l.z); split2(v.w, h.w, l.w);
            *(float4*)&g_Wth[i] = h;
            *(float4*)&g_Wtl[i] = l;
        }
    } else if (blk == 288) {
        float v = init_state[tid];
        float a = fabsf(v);
        float m = a;
#pragma unroll
        for (int off = 16; off; off >>= 1) m = fmaxf(m, __shfl_down_sync(0xffffffffu, m, off));
        if (lane == 0) swr[wid] = m;
        __syncthreads();
        if (tid == 0) {
            float mm = swr[0];
#pragma unroll
            for (int i = 1; i < 8; i++) mm = fmaxf(mm, swr[i]);
            s_bc[0] = mm;
        }
        __syncthreads();
        float e = expf(a - s_bc[0]);
        float s = e;
#pragma unroll
        for (int off = 16; off; off >>= 1) s += __shfl_down_sync(0xffffffffu, s, off);
        __syncthreads();
        if (lane == 0) swr[wid] = s;
        __syncthreads();
        if (tid == 0) {
            float ss = 0.f;
#pragma unroll
            for (int i = 0; i < 8; i++) ss += swr[i];
            s_bc[1] = ss;
        }
        __syncthreads();
        float sgn = (v > 0.f) ? 1.f : ((v < 0.f) ? -1.f : 0.f);
        g_mem_state0[tid] = sgn * e / s_bc[1] * STATE_MASS;
    } else {
        if (tid < Rr) g_bt2[tid] = rUt_b[tid] * r_w[tid] * LRS;
    }
}

// ---------------- kernel: signed softmax state over 256 slots ----------------
__global__ void sss_kernel(const float* __restrict__ in, float* __restrict__ out) {
    int tid = threadIdx.x;
    const float* x = in + (size_t)blockIdx.x * Mm;
    float v = x[tid];
    float a = fabsf(v);
    __shared__ float swr[8];
    __shared__ float s_bc[2];
    int wid = tid >> 5, lane = tid & 31;
    float m = a;
#pragma unroll
    for (int off = 16; off; off >>= 1) m = fmaxf(m, __shfl_down_sync(0xffffffffu, m, off));
    if (lane == 0) swr[wid] = m;
    __syncthreads();
    if (tid == 0) {
        float mm = swr[0];
#pragma unroll
        for (int i = 1; i < 8; i++) mm = fmaxf(mm, swr[i]);
        s_bc[0] = mm;
    }
    __syncthreads();
    float e = expf(a - s_bc[0]);
    float s = e;
#pragma unroll
    for (int off = 16; off; off >>= 1) s += __shfl_down_sync(0xffffffffu, s, off);
    __syncthreads();
    if (lane == 0) swr[wid] = s;
    __syncthreads();
    if (tid == 0) {
        float ss = 0.f;
#pragma unroll
        for (int i = 0; i < 8; i++) ss += swr[i];
        s_bc[1] = ss;
    }
    __syncthreads();
    float sgn = (v > 0.f) ? 1.f : ((v < 0.f) ? -1.f : 0.f);
    out[(size_t)blockIdx.x * Mm + tid] = sgn * e / s_bc[1] * STATE_MASS;
}

// ---------------- scalar tiled projection (qt / qs2 only) ----------------
template <int RT>
__global__ __launch_bounds__(256) void gemm_proj(
    const float* __restrict__ X0,
    float* __restrict__ out0, const float* __restrict__ W0, const float* __restrict__ b0,
    const float* __restrict__ rs0, const float* __restrict__ rowsc0,
    const float* __restrict__ X1,
    float* __restrict__ out1, const float* __restrict__ W1, const float* __restrict__ b1,
    const float* __restrict__ rs1, const float* __restrict__ rowsc1) {
    constexpr int RPT = RT / 16;
    constexpr int XSTR = RT + 4;
    __shared__ float sx[16 * XSTR];
    __shared__ float sw[16 * 68];

    int tid = threadIdx.x;
    int set = blockIdx.y;
    int row0 = blockIdx.x * RT;
    const float* X     = set ? X1 : X0;
    const float* W     = set ? W1 : W0;
    const float* bias  = set ? b1 : b0;
    const float* rs    = set ? rs1 : rs0;
    const float* rowsc = set ? rowsc1 : rowsc0;
    float* out         = set ? out1 : out0;

    int rowg = tid >> 4;
    int colg = tid & 15;

    float acc[RPT][4];
#pragma unroll
    for (int r = 0; r < RPT; r++)
#pragma unroll
        for (int c = 0; c < 4; c++) acc[r][c] = 0.f;

    for (int k0 = 0; k0 < Dd; k0 += 16) {
        constexpr int NV = RT * 16 / 4;
#pragma unroll
        for (int t = 0; t < (NV + 255) / 256; t++) {
            int f = tid + 256 * t;
            if ((NV % 256 == 0) || (f < NV)) {
                int row = f >> 2, q = f & 3;
                float4 v = *(const float4*)&X[(size_t)(row0 + row) * Dd + k0 + 4 * q];
                sx[(4 * q + 0) * XSTR + row] = v.x;
                sx[(4 * q + 1) * XSTR + row] = v.y;
                sx[(4 * q + 2) * XSTR + row] = v.z;
                sx[(4 * q + 3) * XSTR + row] = v.w;
            }
        }
        {
            int k = tid >> 4, c = tid & 15;
            float4 v = *(const float4*)&W[(size_t)(k0 + k) * Rr + 4 * c];
            *(float4*)&sw[k * 68 + 4 * c] = v;
        }
        __syncthreads();
#pragma unroll
        for (int kk = 0; kk < 16; kk++) {
            float4 wv = *(const float4*)&sw[kk * 68 + colg * 4];
            float xr[RPT];
            float2 x0 = *(const float2*)&sx[kk * XSTR + rowg * RPT];
            xr[0] = x0.x; xr[1] = x0.y;
#pragma unroll
            for (int r = 0; r < RPT; r++) {
                acc[r][0] = fmaf(xr[r], wv.x, acc[r][0]);
                acc[r][1] = fmaf(xr[r], wv.y, acc[r][1]);
                acc[r][2] = fmaf(xr[r], wv.z, acc[r][2]);
                acc[r][3] = fmaf(xr[r], wv.w, acc[r][3]);
            }
        }
        __syncthreads();
    }

    float4 bv = *(const float4*)&bias[colg * 4];
    float s0 = 1.f, s1 = 1.f, s2 = 1.f, s3 = 1.f;
    if (rs) {
        float4 rv = *(const float4*)&rs[colg * 4];
        s0 = rv.x * LRS; s1 = rv.y * LRS; s2 = rv.z * LRS; s3 = rv.w * LRS;
    }
#pragma unroll
    for (int r = 0; r < RPT; r++) {
        int row = row0 + rowg * RPT + r;
        float rsc = rowsc ? rowsc[row] : 1.f;
        float4 o;
        o.x = (acc[r][0] + bv.x) * s0 * rsc;
        o.y = (acc[r][1] + bv.y) * s1 * rsc;
        o.z = (acc[r][2] + bv.z) * s2 * rsc;
        o.w = (acc[r][3] + bv.w) * s3 * rsc;
        *(float4*)&out[(size_t)row * Rr + colg * 4] = o;
    }
}

// ---------------- tensor-core projection GEMM (fused ps + pt2) ----------
constexpr int PS_XOFF = 0;               // per-stage X offset (floats)
constexpr int PS_WHOFF = 128 * 20;       // per-stage Wh offset
constexpr int PS_WLOFF = 128 * 20 + 16 * 72;
constexpr int PS_STAGE = 128 * 20 + 2 * 16 * 72;  // floats per stage = 4864
constexpr int PS_SMEM_BYTES = 3 * PS_STAGE * 4;   // 58368

__global__ __launch_bounds__(256) void gemm_ps_tc(
    int split,
    const float* __restrict__ X0, const float* __restrict__ b0,
    const float* __restrict__ Wh0, const float* __restrict__ Wl0,
    float* __restrict__ oh0, float* __restrict__ ol0,
    const float* __restrict__ X1, const float* __restrict__ b1,
    const float* __restrict__ Wh1, const float* __restrict__ Wl1,
    float* __restrict__ oh1, float* __restrict__ ol1) {
    extern __shared__ __align__(16) float smp[];
    int tid = threadIdx.x, w = tid >> 5, lane = tid & 31;
    int g = lane >> 2, tg = lane & 3;
    int set = ((int)blockIdx.x >= split);
    int rowblk = set ? (int)blockIdx.x - split : (int)blockIdx.x;
    const float* X    = set ? X1 : X0;
    const float* bias = set ? b1 : b0;
    const float* Wh   = set ? Wh1 : Wh0;
    const float* Wl   = set ? Wl1 : Wl0;
    float* oh         = set ? oh1 : oh0;
    float* ol         = set ? ol1 : ol0;
    int row0 = rowblk * 128;
    int wm = w >> 1, wn = w & 1;

    int lr = tid >> 2, lq = (tid & 3) * 4;
    int wk = tid >> 4, wc = (tid & 15) * 4;

    float acc[2][4][4];
#pragma unroll
    for (int mt = 0; mt < 2; mt++)
#pragma unroll
        for (int nt = 0; nt < 4; nt++)
#pragma unroll
            for (int c = 0; c < 4; c++) acc[mt][nt][c] = 0.f;

#pragma unroll
    for (int pc = 0; pc < 2; pc++) {
        int k0 = pc * 16;
        float* st = smp + pc * PS_STAGE;
        cpa16(st + PS_XOFF + lr * 20 + lq,        &X[(size_t)(row0 + lr) * Dd + k0 + lq]);
        cpa16(st + PS_XOFF + (lr + 64) * 20 + lq, &X[(size_t)(row0 + lr + 64) * Dd + k0 + lq]);
        cpa16(st + PS_WHOFF + wk * 72 + wc,       &Wh[(size_t)(k0 + wk) * Rr + wc]);
        cpa16(st + PS_WLOFF + wk * 72 + wc,       &Wl[(size_t)(k0 + wk) * Rr + wc]);
        CP_COMMIT();
    }

    for (int c = 0; c < 32; c++) {
        CP_WAIT(1);
        __syncthreads();
        float* st = smp + (c % 3) * PS_STAGE;
        float* sx = st + PS_XOFF;
        float* swh = st + PS_WHOFF;
        float* swl = st + PS_WLOFF;
#pragma unroll
        for (int ks = 0; ks < 2; ks++) {
            int kk = ks * 8;
            uint32_t ah[2][4], al[2][4];
#pragma unroll
            for (int mt = 0; mt < 2; mt++) {
                int r = wm * 32 + mt * 16;
                float x0 = sx[(r + g) * 20 + kk + tg];
                float x1 = sx[(r + g + 8) * 20 + kk + tg];
                float x2 = sx[(r + g) * 20 + kk + tg + 4];
                float x3 = sx[(r + g + 8) * 20 + kk + tg + 4];
                ah[mt][0] = f2tf32(x0); al[mt][0] = f2tf32(x0 - __uint_as_float(ah[mt][0]));
                ah[mt][1] = f2tf32(x1); al[mt][1] = f2tf32(x1 - __uint_as_float(ah[mt][1]));
                ah[mt][2] = f2tf32(x2); al[mt][2] = f2tf32(x2 - __uint_as_float(ah[mt][2]));
                ah[mt][3] = f2tf32(x3); al[mt][3] = f2tf32(x3 - __uint_as_float(ah[mt][3]));
            }
#pragma unroll
            for (int nt = 0; nt < 4; nt++) {
                int cc = wn * 32 + nt * 8 + g;
                uint32_t bh0 = __float_as_uint(swh[(kk + tg) * 72 + cc]);
                uint32_t bh1 = __float_as_uint(swh[(kk + tg + 4) * 72 + cc]);
                uint32_t bl0 = __float_as_uint(swl[(kk + tg) * 72 + cc]);
                uint32_t bl1 = __float_as_uint(swl[(kk + tg + 4) * 72 + cc]);
#pragma unroll
                for (int mt = 0; mt < 2; mt++) {
                    MMA_TF32(acc[mt][nt], ah[mt], bh0, bh1);
                    MMA_TF32(acc[mt][nt], ah[mt], bl0, bl1);
                    MMA_TF32(acc[mt][nt], al[mt], bh0, bh1);
                }
            }
        }
        __syncthreads();
        int nc = c + 2;
        if (nc < 32) {
            int k0 = nc * 16;
            float* s2 = smp + (nc % 3) * PS_STAGE;
            cpa16(s2 + PS_XOFF + lr * 20 + lq,        &X[(size_t)(row0 + lr) * Dd + k0 + lq]);
            cpa16(s2 + PS_XOFF + (lr + 64) * 20 + lq, &X[(size_t)(row0 + lr + 64) * Dd + k0 + lq]);
            cpa16(s2 + PS_WHOFF + wk * 72 + wc,       &Wh[(size_t)(k0 + wk) * Rr + wc]);
            cpa16(s2 + PS_WLOFF + wk * 72 + wc,       &Wl[(size_t)(k0 + wk) * Rr + wc]);
        }
        CP_COMMIT();
    }

#pragma unroll
    for (int mt = 0; mt < 2; mt++) {
        int r = row0 + wm * 32 + mt * 16 + g;
#pragma unroll
        for (int nt = 0; nt < 4; nt++) {
            int c = wn * 32 + nt * 8 + 2 * tg;
            float b0v = bias[c], b1v = bias[c + 1];
            float v00 = acc[mt][nt][0] + b0v, v01 = acc[mt][nt][1] + b1v;
            float v10 = acc[mt][nt][2] + b0v, v11 = acc[mt][nt][3] + b1v;
            float h00 = __uint_as_float(f2tf32(v00));
            float h01 = __uint_as_float(f2tf32(v01));
            float h10 = __uint_as_float(f2tf32(v10));
            float h11 = __uint_as_float(f2tf32(v11));
            *(float2*)&oh[(size_t)r * Rr + c]       = make_float2(h00, h01);
            *(float2*)&oh[(size_t)(r + 8) * Rr + c] = make_float2(h10, h11);
            *(float2*)&ol[(size_t)r * Rr + c] = make_float2(
                __uint_as_float(f2tf32(v00 - h00)), __uint_as_float(f2tf32(v01 - h01)));
            *(float2*)&ol[(size_t)(r + 8) * Rr + c] = make_float2(
                __uint_as_float(f2tf32(v10 - h10)), __uint_as_float(f2tf32(v11 - h11)));
        }
    }
}

// ---------------- tensor-core scores GEMM: pure MMA from pre-split tiles ----------
__global__ __launch_bounds__(256) void scores_tc_kernel() {
    extern __shared__ __align__(16) float smc[];
    float (*sah)[72] = (float(*)[72])smc;
    float (*sal)[72] = (float(*)[72])(smc + 128 * 72);
    float (*sbh)[72] = (float(*)[72])(smc + 2 * 128 * 72);
    float (*sbl)[72] = (float(*)[72])(smc + 3 * 128 * 72);
    int tid = threadIdx.x, w = tid >> 5, lane = tid & 31;
    int g = lane >> 2, tg = lane & 3;
    int b = blockIdx.z;
    int m0 = blockIdx.y * 128;
    int s0 = blockIdx.x * 128;
    int wm = w >> 1, wn = w & 1;

#pragma unroll
    for (int t = 0; t < 8; t++) {
        int f = tid + 256 * t;
        int r = f >> 4, q = (f & 15) * 4;
        cpa16(&sah[r][q], &g_pt2_h[(size_t)(m0 + r) * Rr + q]);
        cpa16(&sal[r][q], &g_pt2_l[(size_t)(m0 + r) * Rr + q]);
        cpa16(&sbh[r][q], &g_ps_h[((size_t)b * Ss + s0 + r) * Rr + q]);
        cpa16(&sbl[r][q], &g_ps_l[((size_t)b * Ss + s0 + r) * Rr + q]);
    }
    CP_COMMIT();

    float acc[2][8][4];
#pragma unroll
    for (int mt = 0; mt < 2; mt++)
#pragma unroll
        for (int nt = 0; nt < 8; nt++)
#pragma unroll
            for (int c = 0; c < 4; c++) acc[mt][nt][c] = 0.f;

    CP_WAIT(0);
    __syncthreads();

#pragma unroll
    for (int ks = 0; ks < 8; ks++) {
        int kk = ks * 8;
        uint32_t ah[2][4], al[2][4];
#pragma unroll
        for (int mt = 0; mt < 2; mt++) {
            int r = wm * 32 + mt * 16;
            ah[mt][0] = __float_as_uint(sah[r + g][kk + tg]);
            ah[mt][1] = __float_as_uint(sah[r + g + 8][kk + tg]);
            ah[mt][2] = __float_as_uint(sah[r + g][kk + tg + 4]);
            ah[mt][3] = __float_as_uint(sah[r + g + 8][kk + tg + 4]);
            al[mt][0] = __float_as_uint(sal[r + g][kk + tg]);
            al[mt][1] = __float_as_uint(sal[r + g + 8][kk + tg]);
            al[mt][2] = __float_as_uint(sal[r + g][kk + tg + 4]);
            al[mt][3] = __float_as_uint(sal[r + g + 8][kk + tg + 4]);
        }
#pragma unroll
        for (int nt = 0; nt < 8; nt++) {
            int cc = wn * 64 + nt * 8 + g;
            uint32_t bh0 = __float_as_uint(sbh[cc][kk + tg]);
            uint32_t bh1 = __float_as_uint(sbh[cc][kk + tg + 4]);
            uint32_t bl0 = __float_as_uint(sbl[cc][kk + tg]);
            uint32_t bl1 = __float_as_uint(sbl[cc][kk + tg + 4]);
#pragma unroll
            for (int mt = 0; mt < 2; mt++) {
                MMA_TF32(acc[mt][nt], ah[mt], bh0, bh1);
                MMA_TF32(acc[mt][nt], ah[mt], bl0, bl1);
                MMA_TF32(acc[mt][nt], al[mt], bh0, bh1);
            }
        }
    }

#pragma unroll
    for (int mt = 0; mt < 2; mt++) {
        int m = m0 + wm * 32 + mt * 16 + g;
#pragma unroll
        for (int nt = 0; nt < 8; nt++) {
            int s = s0 + wn * 64 + nt * 8 + 2 * tg;
            *(float2*)&g_scores[((size_t)(b * Mm + m)) * Ss + s] =
                make_float2(acc[mt][nt][0], acc[mt][nt][1]);
            *(float2*)&g_scores[((size_t)(b * Mm + m + 8)) * Ss + s] =
                make_float2(acc[mt][nt][2], acc[mt][nt][3]);
        }
    }
}

// ---------------- write phase: low-sync bisection top-16 + warp-register sort ----------------
__global__ __launch_bounds__(256) void write_kernel(
    const float* __restrict__ token_val, const float* __restrict__ token_state,
    const float* __restrict__ ln_g, const float* __restrict__ ln_b) {
    int bm = blockIdx.x;
    int b = bm >> 8, m = bm & 255;
    int tid = threadIdx.x, w = tid >> 5, lane = tid & 31;
    __shared__ ull skeys[64];
    __shared__ float swr[18];
    __shared__ int s_cnt[32];
    __shared__ unsigned s_maxu;
    __shared__ int s_tot;
    __shared__ float s_edge[16];
    __shared__ int s_eidx[16];

    const float* row = g_scores + (size_t)bm * Ss;

    float aa[8];
#pragma unroll
    for (int j = 0; j < 8; j++) aa[j] = fabsf(row[tid + 256 * j]);

    // init shared (counters, max, compaction slots, keys)
    if (tid < 32) s_cnt[tid] = 0;
    if (tid < 64) skeys[tid] = 0ull;
    if (tid == 64) s_maxu = 0u;
    if (tid == 65) s_tot = 0;
    __syncthreads();

    // block max via atomicMax
    {
        unsigned um = 0;
#pragma unroll
        for (int j = 0; j < 8; j++) um = max(um, __float_as_uint(aa[j]));
        um = __reduce_max_sync(0xffffffffu, um);
        if (lane == 0) atomicMax(&s_maxu, um);
    }
    __syncthreads();
    float hi = __uint_as_float(s_maxu), lo = 0.f;
    int cl = Ss;

    // bisection: one __syncthreads per iteration (per-iteration counters)
    for (int it = 0; it < 32 && cl > 64; it++) {
        float mid = 0.5f * (lo + hi);
        int c = 0;
#pragma unroll
        for (int j = 0; j < 8; j++) c += (aa[j] > mid);
        c = (int)__reduce_add_sync(0xffffffffu, (unsigned)c);
        if (lane == 0) atomicAdd(&s_cnt[it], c);
        __syncthreads();
        int tot = s_cnt[it];
        if (tot >= 16) { lo = mid; cl = tot; } else { hi = mid; }
    }

    // compact survivors (<= 64) into skeys
#pragma unroll
    for (int j = 0; j < 8; j++) {
        if (aa[j] > lo) {
            int p = atomicAdd(&s_tot, 1);
            if (p < 64)
                skeys[p] = ((ull)__float_as_uint(aa[j]) << 32) | (unsigned)(~(tid + 256 * j));
        }
    }
    __syncthreads();

    // warp 0: register bitonic sort of 64 keys (2/lane), descending; then edges
    if (w == 0) {
        ull v0 = skeys[lane];        // element e = lane
        ull v1 = skeys[lane + 32];   // element e = lane + 32
#pragma unroll
        for (int k = 2; k <= 64; k <<= 1) {
#pragma unroll
            for (int j = k >> 1; j; j >>= 1) {
                if (j == 32) {
                    // pair (e, e+32) within thread; desc region ((e & 64)==0) always
                    ull mx = v0 > v1 ? v0 : v1;
                    ull mn = v0 > v1 ? v1 : v0;
                    v0 = mx; v1 = mn;
                } else {
                    {
                        ull other = __shfl_xor_sync(0xffffffffu, v0, j);
                        int e = lane;
                        bool takeMax = ((e & k) == 0) != ((e & j) != 0);
                        ull mx = v0 > other ? v0 : other;
                        ull mn = v0 > other ? other : v0;
                        v0 = takeMax ? mx : mn;
                    }
                    {
                        ull other = __shfl_xor_sync(0xffffffffu, v1, j);
                        int e = lane + 32;
                        bool takeMax = ((e & k) == 0) != ((e & j) != 0);
                        ull mx = v1 > other ? v1 : other;
                        ull mn = v1 > other ? other : v1;
                        v1 = takeMax ? mx : mn;
                    }
                }
            }
        }
        // sorted descending over e: top-16 = v0 of lanes 0..15
        bool valid = lane < 16;
        ull key = v0;
        float a = __uint_as_float((unsigned)(key >> 32));
        int idx = (int)(~(unsigned)key);
        float maxa = __shfl_sync(0xffffffffu, a, 0);
        float sel = valid ? row[idx] : 0.f;
        float e = valid ? expf(a - maxa) : 0.f;
        float sum = e;
#pragma unroll
        for (int off = 8; off; off >>= 1) sum += __shfl_xor_sync(0xffffffffu, sum, off, 16);
        float sgn = (sel > 0.f) ? 1.f : ((sel < 0.f) ? -1.f : 0.f);
        float edge = sgn * e / sum;
        if (valid) { s_edge[lane] = edge; s_eidx[lane] = idx; }
        float c = valid ? edge * token_state[(size_t)b * Ss + idx] : 0.f;
#pragma unroll
        for (int off = 8; off; off >>= 1) c += __shfl_xor_sync(0xffffffffu, c, off, 16);
        if (lane == 0) g_state1_raw[bm] = g_mem_state0[m] + c;
    }
    __syncthreads();

    // value update + LN
    int d = tid;
    float a0 = g_mem_val0[(size_t)m * Dd + d];
    float a1 = g_mem_val0[(size_t)m * Dd + d + 256];
#pragma unroll
    for (int k = 0; k < 16; k++) {
        const float* tv = token_val + ((size_t)b * Ss + s_eidx[k]) * Dd;
        float ek = s_edge[k];
        a0 = fmaf(ek, tv[d], a0);
        a1 = fmaf(ek, tv[d + 256], a1);
    }
    float mu, ri;
    block_ln_512(a0, a1, mu, ri, swr);
    float* o = g_mem_val1 + (size_t)bm * Dd;
    o[d]       = (a0 - mu) * ri * ln_g[d] + ln_b[d];
    o[d + 256] = (a1 - mu) * ri * ln_g[d + 256] + ln_b[d + 256];
}

// ---------------- propagation: 8 rows/block, per-warp bisection top-16 ----------------
__global__ __launch_bounds__(256) void prop8_kernel(
    float* __restrict__ out_final, const float* __restrict__ ln_g,
    const float* __restrict__ ln_b) {
    int b = blockIdx.x >> 5;
    int i0 = (blockIdx.x & 31) * 8;
    int tid = threadIdx.x, w = tid >> 5, lane = tid & 31;
    __shared__ float s_qt[8][68];
    __shared__ float sqs[32][68];
    __shared__ float prow[8][256];
    __shared__ ull wkeys[8][32];
    __shared__ float s_edge[8][16];
    __shared__ int s_eidx[8][16];
    __shared__ float swr[18];

    if (tid < 128) {
        int r = tid >> 4, q = tid & 15;
        *(float4*)&s_qt[r][q * 4] =
            *(const float4*)&g_qt[((size_t)(b * Mm + i0 + r)) * Rr + 4 * q];
    }
    __syncthreads();

    float pv[8];
    for (int j0 = 0; j0 < Mm; j0 += 32) {
#pragma unroll
        for (int t = 0; t < 2; t++) {
            int f = tid + 256 * t;
            int jj = f >> 4, q = f & 15;
            *(float4*)&sqs[jj][q * 4] =
                *(const float4*)&g_qs2[((size_t)(b * Mm + j0 + jj)) * Rr + 4 * q];
        }
        __syncthreads();
        float acc = 0.f;
#pragma unroll
        for (int k4 = 0; k4 < Rr; k4 += 4) {
            float4 qv = *(const float4*)&sqs[lane][k4];
            float4 tv = *(const float4*)&s_qt[w][k4];
            acc = fmaf(qv.x, tv.x, fmaf(qv.y, tv.y, fmaf(qv.z, tv.z, fmaf(qv.w, tv.w, acc))));
        }
        pv[j0 >> 5] = acc;
        prow[w][j0 + lane] = acc;
        __syncthreads();
    }

    float av[8];
#pragma unroll
    for (int r = 0; r < 8; r++) av[r] = fabsf(pv[r]);
    unsigned um = 0;
#pragma unroll
    for (int r = 0; r < 8; r++) um = max(um, __float_as_uint(av[r]));
    um = __reduce_max_sync(0xffffffffu, um);
    float hi = __uint_as_float(um), lo = 0.f;
    int cl = 256;
    for (int it = 0; it < 32 && cl > 32; it++) {
        float mid = 0.5f * (lo + hi);
        int c = 0;
#pragma unroll
        for (int r = 0; r < 8; r++) c += (av[r] > mid);
        c = (int)__reduce_add_sync(0xffffffffu, (unsigned)c);
        if (c >= 16) { lo = mid; cl = c; } else { hi = mid; }
    }

    wkeys[w][lane] = 0ull;
    __syncwarp();
    int base = 0;
#pragma unroll
    for (int r = 0; r < 8; r++) {
        bool p = av[r] > lo;
        unsigned msk = __ballot_sync(0xffffffffu, p);
        if (p) {
            int pos = base + __popc(msk & ((1u << lane) - 1));
            if (pos < 32)
                wkeys[w][pos] =
                    ((ull)__float_as_uint(av[r]) << 32) | (unsigned)(~(r * 32 + lane));
        }
        base += __popc(msk);
    }
    __syncwarp();

    ull key = wkeys[w][lane];
#pragma unroll
    for (int k = 2; k <= 32; k <<= 1) {
#pragma unroll
        for (int j = k >> 1; j; j >>= 1) {
            ull other = __shfl_xor_sync(0xffffffffu, key, j);
            bool dirDesc = ((lane & k) == 0);
            bool upper = (lane & j) != 0;
            bool takeMax = (dirDesc != upper);
            ull mx2 = key > other ? key : other;
            ull mn2 = key > other ? other : key;
            key = takeMax ? mx2 : mn2;
        }
    }

    {
        bool valid = lane < 16;
        float a = __uint_as_float((unsigned)(key >> 32));
        int idx = (int)(~(unsigned)key);
        float maxa = __shfl_sync(0xffffffffu, a, 0);
        float sel = valid ? prow[w][idx] : 0.f;
        float e = valid ? expf(a - maxa) : 0.f;
        float sum = e;
#pragma unroll
        for (int off = 8; off; off >>= 1) sum += __shfl_xor_sync(0xffffffffu, sum, off, 16);
        float sgn = (sel > 0.f) ? 1.f : ((sel < 0.f) ? -1.f : 0.f);
        float edge = sgn * e / sum;
        if (valid) { s_edge[w][lane] = edge; s_eidx[w][lane] = idx; }
    }
    __syncthreads();

    for (int r = 0; r < 8; r++) {
        int bi = b * Mm + i0 + r;
        int d = tid;
        float a0 = g_mem_val1[(size_t)bi * Dd + d];
        float a1 = g_mem_val1[(size_t)bi * Dd + d + 256];
#pragma unroll
        for (int k = 0; k < 16; k++) {
            const float* mv = g_mem_val1 + ((size_t)(b * Mm + s_eidx[r][k])) * Dd;
            float ek = s_edge[r][k];
            a0 = fmaf(ek, mv[d], a0);
            a1 = fmaf(ek, mv[d + 256], a1);
        }
        float mu, ri;
        block_ln_512(a0, a1, mu, ri, swr);
        float* o = out_final + (size_t)bi * Dd;
        o[d]       = (a0 - mu) * ri * ln_g[d] + ln_b[d];
        o[d + 256] = (a1 - mu) * ri * ln_g[d + 256] + ln_b[d + 256];
        __syncthreads();
    }
}

// ---------------- host launch ----------------
extern "C" void kernel_launch(void* const* d_in, const int* in_sizes, int n_in,
                              void* d_out, int out_size) {
    (void)in_sizes; (void)n_in; (void)out_size;
    const float* token_val   = (const float*)d_in[0];
    const float* token_state = (const float*)d_in[1];
    const float* init_state  = (const float*)d_in[2];
    const float* init_val    = (const float*)d_in[3];
    const float* rUs_w = (const float*)d_in[4];
    const float* rUs_b = (const float*)d_in[5];
    const float* rUt_w = (const float*)d_in[6];
    const float* rUt_b = (const float*)d_in[7];
    const float* r_w   = (const float*)d_in[8];
    const float* pUs_w = (const float*)d_in[9];
    const float* pUs_b = (const float*)d_in[10];
    const float* pUt_w = (const float*)d_in[11];
    const float* pUt_b = (const float*)d_in[12];
    const float* p_w   = (const float*)d_in[13];
    const float* ln_g  = (const float*)d_in[14];
    const float* ln_b  = (const float*)d_in[15];
    float* out = (float*)d_out;

    float *p_mv0, *p_mv1, *p_qt, *p_qs2, *p_st1raw, *p_st1;
    float *p_Wh, *p_Wl, *p_Wth, *p_Wtl, *p_bt2, *p_pt2h, *p_pt2l, *p_psh, *p_psl;
    cudaGetSymbolAddress((void**)&p_mv0, g_mem_val0);
    cudaGetSymbolAddress((void**)&p_mv1, g_mem_val1);
    cudaGetSymbolAddress((void**)&p_qt, g_qt);
    cudaGetSymbolAddress((void**)&p_qs2, g_qs2);
    cudaGetSymbolAddress((void**)&p_st1raw, g_state1_raw);
    cudaGetSymbolAddress((void**)&p_st1, g_state1);
    cudaGetSymbolAddress((void**)&p_Wh, g_Wh);
    cudaGetSymbolAddress((void**)&p_Wl, g_Wl);
    cudaGetSymbolAddress((void**)&p_Wth, g_Wth);
    cudaGetSymbolAddress((void**)&p_Wtl, g_Wtl);
    cudaGetSymbolAddress((void**)&p_bt2, g_bt2);
    cudaGetSymbolAddress((void**)&p_pt2h, g_pt2_h);
    cudaGetSymbolAddress((void**)&p_pt2l, g_pt2_l);
    cudaGetSymbolAddress((void**)&p_psh, g_ps_h);
    cudaGetSymbolAddress((void**)&p_psl, g_ps_l);

    const int SC_SMEM = 4 * 128 * 72 * 4;  // 147456 bytes
    cudaFuncSetAttribute(scores_tc_kernel,
                         cudaFuncAttributeMaxDynamicSharedMemorySize, SC_SMEM);
    cudaFuncSetAttribute(gemm_ps_tc,
                         cudaFuncAttributeMaxDynamicSharedMemorySize, PS_SMEM_BYTES);

    // fused prologue: LN(init_val), sss(init_state), split rUs_w, split rUt_w*r_w*LRS, bias
    prep_kernel<<<290, 256>>>(init_val, init_state, rUs_w, rUt_w, rUt_b, r_w, ln_g, ln_b);
    // fused TC projection: blocks [0,256) -> ps; [256,258) -> pt2 (both written pre-split)
    gemm_ps_tc<<<(Bb * Ss) / 128 + Mm / 128, 256, PS_SMEM_BYTES>>>(
        (Bb * Ss) / 128,
        token_val, rUs_b, p_Wh, p_Wl, p_psh, p_psl,
        p_mv0, p_bt2, p_Wth, p_Wtl, p_pt2h, p_pt2l);
    // scores = pt2 . ps  (pure MMA from pre-split tiles)
    scores_tc_kernel<<<dim3(Ss / 128, Mm / 128, Bb), 256, SC_SMEM>>>();
    // write phase: low-sync bisection topk + edges + gather-add + LN; raw state update
    write_kernel<<<Bb * Mm, 256>>>(token_val, token_state, ln_g, ln_b);
    // state1 = signed_softmax_state(state1_raw)
    sss_kernel<<<Bb, 256>>>(p_st1raw, p_st1);
    // fused: y=0 -> qt ; y=1 -> qs2 (state folded into rows)
    gemm_proj<32><<<dim3((Bb * Mm) / 32, 2), 256>>>(
        p_mv1, p_qt, pUt_w, pUt_b, p_w, nullptr,
        p_mv1, p_qs2, pUs_w, pUs_b, nullptr, p_st1);
    // propagation (8 rows/block, warp bisection) + final LN -> out
    prop8_kernel<<<(Bb * Mm) / 8, 256>>>(out, ln_g, ln_b);
}

// round 13
// speedup vs baseline: 1.2449x; 1.0719x over previous
#include <cuda_runtime.h>
#include <math.h>
#include <stdint.h>

// Problem shapes (fixed by the dataset)
constexpr int Bb = 16;    // batch
constexpr int Ss = 2048;  // tokens
constexpr int Dd = 512;   // dim
constexpr int Mm = 256;   // memory slots
constexpr int Rr = 64;    // low rank
constexpr float EPS = 1e-5f;
constexpr float STATE_MASS = 4.0f;
constexpr float LRS = 0.1f;

typedef unsigned long long ull;

// ---------------- scratch (static device globals; no allocs) ----------------
__device__ float g_scores[(size_t)Bb * Mm * Ss];   // 33.5 MB (L2-resident) [b][m][s]
__device__ float g_ps_h[(size_t)Bb * Ss * Rr];     // ps split hi
__device__ float g_ps_l[(size_t)Bb * Ss * Rr];     // ps split lo
__device__ float g_mem_val0[(size_t)Mm * Dd];      // LN(init_val), batch-independent
__device__ float g_pt2_h[(size_t)Mm * Rr];         // pt2 split hi
__device__ float g_pt2_l[(size_t)Mm * Rr];         // pt2 split lo
__device__ float g_Wh[(size_t)Dd * Rr];            // rUs_w split hi
__device__ float g_Wl[(size_t)Dd * Rr];            // rUs_w split lo
__device__ float g_Wth[(size_t)Dd * Rr];           // (rUt_w * r_w * LRS) split hi
__device__ float g_Wtl[(size_t)Dd * Rr];           // (rUt_w * r_w * LRS) split lo
__device__ float g_Wpsh[(size_t)Dd * Rr];          // pUs_w split hi
__device__ float g_Wpsl[(size_t)Dd * Rr];          // pUs_w split lo
__device__ float g_Wpth[(size_t)Dd * Rr];          // (pUt_w * p_w * LRS) split hi
__device__ float g_Wptl[(size_t)Dd * Rr];          // (pUt_w * p_w * LRS) split lo
__device__ float g_bt2[Rr];                        // rUt_b * r_w * LRS
__device__ float g_bqt[Rr];                        // pUt_b * p_w * LRS
__device__ float g_mem_state0[Mm];                 // signed-softmax-state(init_state)
__device__ float g_mem_val1[(size_t)Bb * Mm * Dd]; // post-write, post-LN
__device__ float g_state1_raw[(size_t)Bb * Mm];
__device__ float g_state1[(size_t)Bb * Mm];
__device__ float g_qt[(size_t)Bb * Mm * Rr];       // (mem_val1@pUt + b) * p_w * 0.1
__device__ float g_qs2[(size_t)Bb * Mm * Rr];      // (mem_val1@pUs + b) * state1[b,j]

// ---------------- tf32 / cp.async helpers ----------------
__device__ __forceinline__ uint32_t f2tf32(float x) {
    uint32_t r;
    asm("cvt.rna.tf32.f32 %0, %1;" : "=r"(r) : "f"(x));
    return r;
}

__device__ __forceinline__ void cpa16(void* dst_smem, const void* src) {
    uint32_t d = (uint32_t)__cvta_generic_to_shared(dst_smem);
    asm volatile("cp.async.ca.shared.global [%0], [%1], 16;" :: "r"(d), "l"(src));
}
#define CP_COMMIT() asm volatile("cp.async.commit_group;")
#define CP_WAIT(n)  asm volatile("cp.async.wait_group %0;" :: "n"(n))

#define MMA_TF32(C, A, B0, B1)                                                  \
    asm volatile(                                                               \
        "mma.sync.aligned.m16n8k8.row.col.f32.tf32.tf32.f32 "                   \
        "{%0,%1,%2,%3}, {%4,%5,%6,%7}, {%8,%9}, {%0,%1,%2,%3};"                 \
        : "+f"((C)[0]), "+f"((C)[1]), "+f"((C)[2]), "+f"((C)[3])                \
        : "r"((A)[0]), "r"((A)[1]), "r"((A)[2]), "r"((A)[3]), "r"(B0), "r"(B1))

// ---------------- shared helpers ----------------
__device__ __forceinline__ void block_ln_512(float a0, float a1, float& mu, float& ri,
                                             float* swr) {
    float ps = a0 + a1;
    float pq = fmaf(a0, a0, a1 * a1);
#pragma unroll
    for (int off = 16; off; off >>= 1) {
        ps += __shfl_down_sync(0xffffffffu, ps, off);
        pq += __shfl_down_sync(0xffffffffu, pq, off);
    }
    int tid = threadIdx.x, wid = tid >> 5, lane = tid & 31;
    if (lane == 0) { swr[wid] = ps; swr[8 + wid] = pq; }
    __syncthreads();
    if (tid == 0) {
        float s = 0.f, q = 0.f;
#pragma unroll
        for (int i = 0; i < 8; i++) { s += swr[i]; q += swr[8 + i]; }
        float m = s * (1.0f / 512.0f);
        float v = q * (1.0f / 512.0f) - m * m;
        swr[16] = m;
        swr[17] = rsqrtf(v + EPS);
    }
    __syncthreads();
    mu = swr[16];
    ri = swr[17];
}

__device__ __forceinline__ void split2(float v, float& h, float& l) {
    h = __uint_as_float(f2tf32(v));
    l = __uint_as_float(f2tf32(v - h));
}

// ---------------- fused prologue kernel ----------------
// [0,256): LN rows of init_val; [256,272): split rUs_w; [272,288): split rUt_w*r_w*LRS;
// [288,304): split pUs_w; [304,320): split pUt_w*p_w*LRS; 320: sss(init_state); 321: biases.
__global__ __launch_bounds__(256) void prep_kernel(
    const float* __restrict__ init_val, const float* __restrict__ init_state,
    const float* __restrict__ rUs_w, const float* __restrict__ rUt_w,
    const float* __restrict__ rUt_b, const float* __restrict__ r_w,
    const float* __restrict__ pUs_w, const float* __restrict__ pUt_w,
    const float* __restrict__ pUt_b, const float* __restrict__ p_w,
    const float* __restrict__ ln_g, const float* __restrict__ ln_b) {
    __shared__ float swr[18];
    __shared__ float s_bc[2];
    int blk = blockIdx.x, tid = threadIdx.x;
    int wid = tid >> 5, lane = tid & 31;

    if (blk < 256) {
        const float* x = init_val + (size_t)blk * Dd;
        float a0 = x[tid], a1 = x[tid + 256];
        float mu, ri;
        block_ln_512(a0, a1, mu, ri, swr);
        float* o = g_mem_val0 + (size_t)blk * Dd;
        o[tid]       = (a0 - mu) * ri * ln_g[tid] + ln_b[tid];
        o[tid + 256] = (a1 - mu) * ri * ln_g[tid + 256] + ln_b[tid + 256];
    } else if (blk < 320) {
        int grp = (blk - 256) >> 4;        // 0: rUs, 1: rUt*r_w, 2: pUs, 3: pUt*p_w
        int base = ((blk - 256) & 15) * 2048 + tid * 8;
        const float* src = grp == 0 ? rUs_w : grp == 1 ? rUt_w : grp == 2 ? pUs_w : pUt_w;
        const float* sc  = grp == 1 ? r_w : grp == 3 ? p_w : nullptr;
        float* dh = grp == 0 ? g_Wh : grp == 1 ? g_Wth : grp == 2 ? g_Wpsh : g_Wpth;
        float* dl = grp == 0 ? g_Wl : grp == 1 ? g_Wtl : grp == 2 ? g_Wpsl : g_Wptl;
#pragma unroll
        for (int q = 0; q < 2; q++) {
            int i = base + 4 * q;
            float4 v = *(const float4*)&src[i];
            if (sc) {
                v.x *= sc[(i + 0) & 63] * LRS;
                v.y *= sc[(i + 1) & 63] * LRS;
                v.z *= sc[(i + 2) & 63] * LRS;
                v.w *= sc[(i + 3) & 63] * LRS;
            }
            float4 h, l;
            split2(v.x, h.x, l.x); split2(v.y, h.y, l.y);
            split2(v.z, h.z, l.z); split2(v.w, h.w, l.w);
            *(float4*)&dh[i] = h;
            *(float4*)&dl[i] = l;
        }
    } else if (blk == 320) {
        float v = init_state[tid];
        float a = fabsf(v);
        float m = a;
#pragma unroll
        for (int off = 16; off; off >>= 1) m = fmaxf(m, __shfl_down_sync(0xffffffffu, m, off));
        if (lane == 0) swr[wid] = m;
        __syncthreads();
        if (tid == 0) {
            float mm = swr[0];
#pragma unroll
            for (int i = 1; i < 8; i++) mm = fmaxf(mm, swr[i]);
            s_bc[0] = mm;
        }
        __syncthreads();
        float e = expf(a - s_bc[0]);
        float s = e;
#pragma unroll
        for (int off = 16; off; off >>= 1) s += __shfl_down_sync(0xffffffffu, s, off);
        __syncthreads();
        if (lane == 0) swr[wid] = s;
        __syncthreads();
        if (tid == 0) {
            float ss = 0.f;
#pragma unroll
            for (int i = 0; i < 8; i++) ss += swr[i];
            s_bc[1] = ss;
        }
        __syncthreads();
        float sgn = (v > 0.f) ? 1.f : ((v < 0.f) ? -1.f : 0.f);
        g_mem_state0[tid] = sgn * e / s_bc[1] * STATE_MASS;
    } else {
        if (tid < Rr) g_bt2[tid] = rUt_b[tid] * r_w[tid] * LRS;
        else if (tid < 2 * Rr) g_bqt[tid - Rr] = pUt_b[tid - Rr] * p_w[tid - Rr] * LRS;
    }
}

// ---------------- kernel: signed softmax state over 256 slots ----------------
__global__ void sss_kernel(const float* __restrict__ in, float* __restrict__ out) {
    int tid = threadIdx.x;
    const float* x = in + (size_t)blockIdx.x * Mm;
    float v = x[tid];
    float a = fabsf(v);
    __shared__ float swr[8];
    __shared__ float s_bc[2];
    int wid = tid >> 5, lane = tid & 31;
    float m = a;
#pragma unroll
    for (int off = 16; off; off >>= 1) m = fmaxf(m, __shfl_down_sync(0xffffffffu, m, off));
    if (lane == 0) swr[wid] = m;
    __syncthreads();
    if (tid == 0) {
        float mm = swr[0];
#pragma unroll
        for (int i = 1; i < 8; i++) mm = fmaxf(mm, swr[i]);
        s_bc[0] = mm;
    }
    __syncthreads();
    float e = expf(a - s_bc[0]);
    float s = e;
#pragma unroll
    for (int off = 16; off; off >>= 1) s += __shfl_down_sync(0xffffffffu, s, off);
    __syncthreads();
    if (lane == 0) swr[wid] = s;
    __syncthreads();
    if (tid == 0) {
        float ss = 0.f;
#pragma unroll
        for (int i = 0; i < 8; i++) ss += swr[i];
        s_bc[1] = ss;
    }
    __syncthreads();
    float sgn = (v > 0.f) ? 1.f : ((v < 0.f) ? -1.f : 0.f);
    out[(size_t)blockIdx.x * Mm + tid] = sgn * e / s_bc[1] * STATE_MASS;
}

// ---------------- tensor-core projection GEMM (dual parameter set) ----------
// Blocks [0,split): set 0; [split,..): set 1. 3xTF32, cp.async 3-stage, pre-split W.
// Output mode per set: if ol != nullptr -> split hi/lo to oh/ol.
//                      else            -> raw fp32 to oh, scaled by rsc[row] if rsc.
constexpr int PS_XOFF = 0;
constexpr int PS_WHOFF = 128 * 20;
constexpr int PS_WLOFF = 128 * 20 + 16 * 72;
constexpr int PS_STAGE = 128 * 20 + 2 * 16 * 72;  // floats per stage = 4864
constexpr int PS_SMEM_BYTES = 3 * PS_STAGE * 4;   // 58368

__global__ __launch_bounds__(256) void gemm_tc_proj(
    int split,
    const float* __restrict__ X0, const float* __restrict__ b0,
    const float* __restrict__ Wh0, const float* __restrict__ Wl0,
    float* __restrict__ oh0, float* __restrict__ ol0, const float* __restrict__ rsc0,
    const float* __restrict__ X1, const float* __restrict__ b1,
    const float* __restrict__ Wh1, const float* __restrict__ Wl1,
    float* __restrict__ oh1, float* __restrict__ ol1, const float* __restrict__ rsc1) {
    extern __shared__ __align__(16) float smp[];
    int tid = threadIdx.x, w = tid >> 5, lane = tid & 31;
    int g = lane >> 2, tg = lane & 3;
    int set = ((int)blockIdx.x >= split);
    int rowblk = set ? (int)blockIdx.x - split : (int)blockIdx.x;
    const float* X    = set ? X1 : X0;
    const float* bias = set ? b1 : b0;
    const float* Wh   = set ? Wh1 : Wh0;
    const float* Wl   = set ? Wl1 : Wl0;
    float* oh         = set ? oh1 : oh0;
    float* ol         = set ? ol1 : ol0;
    const float* rsc  = set ? rsc1 : rsc0;
    int row0 = rowblk * 128;
    int wm = w >> 1, wn = w & 1;

    int lr = tid >> 2, lq = (tid & 3) * 4;
    int wk = tid >> 4, wc = (tid & 15) * 4;

    float acc[2][4][4];
#pragma unroll
    for (int mt = 0; mt < 2; mt++)
#pragma unroll
        for (int nt = 0; nt < 4; nt++)
#pragma unroll
            for (int c = 0; c < 4; c++) acc[mt][nt][c] = 0.f;

#pragma unroll
    for (int pc = 0; pc < 2; pc++) {
        int k0 = pc * 16;
        float* st = smp + pc * PS_STAGE;
        cpa16(st + PS_XOFF + lr * 20 + lq,        &X[(size_t)(row0 + lr) * Dd + k0 + lq]);
        cpa16(st + PS_XOFF + (lr + 64) * 20 + lq, &X[(size_t)(row0 + lr + 64) * Dd + k0 + lq]);
        cpa16(st + PS_WHOFF + wk * 72 + wc,       &Wh[(size_t)(k0 + wk) * Rr + wc]);
        cpa16(st + PS_WLOFF + wk * 72 + wc,       &Wl[(size_t)(k0 + wk) * Rr + wc]);
        CP_COMMIT();
    }

    for (int c = 0; c < 32; c++) {
        CP_WAIT(1);
        __syncthreads();
        float* st = smp + (c % 3) * PS_STAGE;
        float* sx = st + PS_XOFF;
        float* swh = st + PS_WHOFF;
        float* swl = st + PS_WLOFF;
#pragma unroll
        for (int ks = 0; ks < 2; ks++) {
            int kk = ks * 8;
            uint32_t ah[2][4], al[2][4];
#pragma unroll
            for (int mt = 0; mt < 2; mt++) {
                int r = wm * 32 + mt * 16;
                float x0 = sx[(r + g) * 20 + kk + tg];
                float x1 = sx[(r + g + 8) * 20 + kk + tg];
                float x2 = sx[(r + g) * 20 + kk + tg + 4];
                float x3 = sx[(r + g + 8) * 20 + kk + tg + 4];
                ah[mt][0] = f2tf32(x0); al[mt][0] = f2tf32(x0 - __uint_as_float(ah[mt][0]));
                ah[mt][1] = f2tf32(x1); al[mt][1] = f2tf32(x1 - __uint_as_float(ah[mt][1]));
                ah[mt][2] = f2tf32(x2); al[mt][2] = f2tf32(x2 - __uint_as_float(ah[mt][2]));
                ah[mt][3] = f2tf32(x3); al[mt][3] = f2tf32(x3 - __uint_as_float(ah[mt][3]));
            }
#pragma unroll
            for (int nt = 0; nt < 4; nt++) {
                int cc = wn * 32 + nt * 8 + g;
                uint32_t bh0 = __float_as_uint(swh[(kk + tg) * 72 + cc]);
                uint32_t bh1 = __float_as_uint(swh[(kk + tg + 4) * 72 + cc]);
                uint32_t bl0 = __float_as_uint(swl[(kk + tg) * 72 + cc]);
                uint32_t bl1 = __float_as_uint(swl[(kk + tg + 4) * 72 + cc]);
#pragma unroll
                for (int mt = 0; mt < 2; mt++) {
                    MMA_TF32(acc[mt][nt], ah[mt], bh0, bh1);
                    MMA_TF32(acc[mt][nt], ah[mt], bl0, bl1);
                    MMA_TF32(acc[mt][nt], al[mt], bh0, bh1);
                }
            }
        }
        __syncthreads();
        int nc = c + 2;
        if (nc < 32) {
            int k0 = nc * 16;
            float* s2 = smp + (nc % 3) * PS_STAGE;
            cpa16(s2 + PS_XOFF + lr * 20 + lq,        &X[(size_t)(row0 + lr) * Dd + k0 + lq]);
            cpa16(s2 + PS_XOFF + (lr + 64) * 20 + lq, &X[(size_t)(row0 + lr + 64) * Dd + k0 + lq]);
            cpa16(s2 + PS_WHOFF + wk * 72 + wc,       &Wh[(size_t)(k0 + wk) * Rr + wc]);
            cpa16(s2 + PS_WLOFF + wk * 72 + wc,       &Wl[(size_t)(k0 + wk) * Rr + wc]);
        }
        CP_COMMIT();
    }

#pragma unroll
    for (int mt = 0; mt < 2; mt++) {
        int r = row0 + wm * 32 + mt * 16 + g;
#pragma unroll
        for (int nt = 0; nt < 4; nt++) {
            int c = wn * 32 + nt * 8 + 2 * tg;
            float b0v = bias[c], b1v = bias[c + 1];
            float v00 = acc[mt][nt][0] + b0v, v01 = acc[mt][nt][1] + b1v;
            float v10 = acc[mt][nt][2] + b0v, v11 = acc[mt][nt][3] + b1v;
            if (ol) {
                float h00 = __uint_as_float(f2tf32(v00));
                float h01 = __uint_as_float(f2tf32(v01));
                float h10 = __uint_as_float(f2tf32(v10));
                float h11 = __uint_as_float(f2tf32(v11));
                *(float2*)&oh[(size_t)r * Rr + c]       = make_float2(h00, h01);
                *(float2*)&oh[(size_t)(r + 8) * Rr + c] = make_float2(h10, h11);
                *(float2*)&ol[(size_t)r * Rr + c] = make_float2(
                    __uint_as_float(f2tf32(v00 - h00)), __uint_as_float(f2tf32(v01 - h01)));
                *(float2*)&ol[(size_t)(r + 8) * Rr + c] = make_float2(
                    __uint_as_float(f2tf32(v10 - h10)), __uint_as_float(f2tf32(v11 - h11)));
            } else {
                float r0s = rsc ? rsc[r] : 1.f;
                float r1s = rsc ? rsc[r + 8] : 1.f;
                *(float2*)&oh[(size_t)r * Rr + c]       = make_float2(v00 * r0s, v01 * r0s);
                *(float2*)&oh[(size_t)(r + 8) * Rr + c] = make_float2(v10 * r1s, v11 * r1s);
            }
        }
    }
}

// ---------------- tensor-core scores GEMM: pure MMA from pre-split tiles ----------
__global__ __launch_bounds__(256) void scores_tc_kernel() {
    extern __shared__ __align__(16) float smc[];
    float (*sah)[72] = (float(*)[72])smc;
    float (*sal)[72] = (float(*)[72])(smc + 128 * 72);
    float (*sbh)[72] = (float(*)[72])(smc + 2 * 128 * 72);
    float (*sbl)[72] = (float(*)[72])(smc + 3 * 128 * 72);
    int tid = threadIdx.x, w = tid >> 5, lane = tid & 31;
    int g = lane >> 2, tg = lane & 3;
    int b = blockIdx.z;
    int m0 = blockIdx.y * 128;
    int s0 = blockIdx.x * 128;
    int wm = w >> 1, wn = w & 1;

#pragma unroll
    for (int t = 0; t < 8; t++) {
        int f = tid + 256 * t;
        int r = f >> 4, q = (f & 15) * 4;
        cpa16(&sah[r][q], &g_pt2_h[(size_t)(m0 + r) * Rr + q]);
        cpa16(&sal[r][q], &g_pt2_l[(size_t)(m0 + r) * Rr + q]);
        cpa16(&sbh[r][q], &g_ps_h[((size_t)b * Ss + s0 + r) * Rr + q]);
        cpa16(&sbl[r][q], &g_ps_l[((size_t)b * Ss + s0 + r) * Rr + q]);
    }
    CP_COMMIT();

    float acc[2][8][4];
#pragma unroll
    for (int mt = 0; mt < 2; mt++)
#pragma unroll
        for (int nt = 0; nt < 8; nt++)
#pragma unroll
            for (int c = 0; c < 4; c++) acc[mt][nt][c] = 0.f;

    CP_WAIT(0);
    __syncthreads();

#pragma unroll
    for (int ks = 0; ks < 8; ks++) {
        int kk = ks * 8;
        uint32_t ah[2][4], al[2][4];
#pragma unroll
        for (int mt = 0; mt < 2; mt++) {
            int r = wm * 32 + mt * 16;
            ah[mt][0] = __float_as_uint(sah[r + g][kk + tg]);
            ah[mt][1] = __float_as_uint(sah[r + g + 8][kk + tg]);
            ah[mt][2] = __float_as_uint(sah[r + g][kk + tg + 4]);
            ah[mt][3] = __float_as_uint(sah[r + g + 8][kk + tg + 4]);
            al[mt][0] = __float_as_uint(sal[r + g][kk + tg]);
            al[mt][1] = __float_as_uint(sal[r + g + 8][kk + tg]);
            al[mt][2] = __float_as_uint(sal[r + g][kk + tg + 4]);
            al[mt][3] = __float_as_uint(sal[r + g + 8][kk + tg + 4]);
        }
#pragma unroll
        for (int nt = 0; nt < 8; nt++) {
            int cc = wn * 64 + nt * 8 + g;
            uint32_t bh0 = __float_as_uint(sbh[cc][kk + tg]);
            uint32_t bh1 = __float_as_uint(sbh[cc][kk + tg + 4]);
            uint32_t bl0 = __float_as_uint(sbl[cc][kk + tg]);
            uint32_t bl1 = __float_as_uint(sbl[cc][kk + tg + 4]);
#pragma unroll
            for (int mt = 0; mt < 2; mt++) {
                MMA_TF32(acc[mt][nt], ah[mt], bh0, bh1);
                MMA_TF32(acc[mt][nt], ah[mt], bl0, bl1);
                MMA_TF32(acc[mt][nt], al[mt], bh0, bh1);
            }
        }
    }

#pragma unroll
    for (int mt = 0; mt < 2; mt++) {
        int m = m0 + wm * 32 + mt * 16 + g;
#pragma unroll
        for (int nt = 0; nt < 8; nt++) {
            int s = s0 + wn * 64 + nt * 8 + 2 * tg;
            *(float2*)&g_scores[((size_t)(b * Mm + m)) * Ss + s] =
                make_float2(acc[mt][nt][0], acc[mt][nt][1]);
            *(float2*)&g_scores[((size_t)(b * Mm + m + 8)) * Ss + s] =
                make_float2(acc[mt][nt][2], acc[mt][nt][3]);
        }
    }
}

// ---------------- write phase: warp-local bisection + 128-key register sort ----------------
__global__ __launch_bounds__(256) void write_kernel(
    const float* __restrict__ token_val, const float* __restrict__ token_state,
    const float* __restrict__ ln_g, const float* __restrict__ ln_b) {
    int bm = blockIdx.x;
    int b = bm >> 8, m = bm & 255;
    int tid = threadIdx.x, w = tid >> 5, lane = tid & 31;
    __shared__ ull skeys[128];
    __shared__ ull wk[8][32];
    __shared__ float swr[18];
    __shared__ float s_edge[16];
    __shared__ int s_eidx[16];

    const float* row = g_scores + (size_t)bm * Ss;

    // warp chunk [w*256, w*256+256): 8 values/thread
    int base = w * 256 + lane;
    float aa[8];
#pragma unroll
    for (int j = 0; j < 8; j++) aa[j] = fabsf(row[base + 32 * j]);

    // warp-local bisection to <=32 survivors (no block syncs)
    unsigned um = 0;
#pragma unroll
    for (int j = 0; j < 8; j++) um = max(um, __float_as_uint(aa[j]));
    um = __reduce_max_sync(0xffffffffu, um);
    float hi = __uint_as_float(um), lo = 0.f;
    int cl = 256;
    for (int it = 0; it < 32 && cl > 32; it++) {
        float mid = 0.5f * (lo + hi);
        int c = 0;
#pragma unroll
        for (int j = 0; j < 8; j++) c += (aa[j] > mid);
        c = (int)__reduce_add_sync(0xffffffffu, (unsigned)c);
        if (c >= 16) { lo = mid; cl = c; } else { hi = mid; }
    }

    // ballot-compact survivors into wk[w]
    wk[w][lane] = 0ull;
    __syncwarp();
    int bc = 0;
#pragma unroll
    for (int j = 0; j < 8; j++) {
        bool p = aa[j] > lo;
        unsigned msk = __ballot_sync(0xffffffffu, p);
        if (p) {
            int pos = bc + __popc(msk & ((1u << lane) - 1));
            if (pos < 32)
                wk[w][pos] = ((ull)__float_as_uint(aa[j]) << 32) | (unsigned)(~(base + 32 * j));
        }
        bc += __popc(msk);
    }
    __syncwarp();

    // warp sort-32 descending
    ull key = wk[w][lane];
#pragma unroll
    for (int k = 2; k <= 32; k <<= 1) {
#pragma unroll
        for (int j = k >> 1; j; j >>= 1) {
            ull other = __shfl_xor_sync(0xffffffffu, key, j);
            bool takeMax = ((lane & k) == 0) != ((lane & j) != 0);
            ull mx = key > other ? key : other;
            ull mn = key > other ? other : key;
            key = takeMax ? mx : mn;
        }
    }
    if (lane < 16) skeys[w * 16 + lane] = key;  // warp's sorted top-16
    __syncthreads();

    // warp 0: register bitonic sort of 128 keys (4/lane, element e = lane + 32*slot)
    if (w == 0) {
        ull v[4];
#pragma unroll
        for (int s = 0; s < 4; s++) v[s] = skeys[lane + 32 * s];
#pragma unroll
        for (int k = 2; k <= 128; k <<= 1) {
#pragma unroll
            for (int j = k >> 1; j; j >>= 1) {
                if (j >= 32) {
                    int d = j >> 5;  // 1 or 2
#pragma unroll
                    for (int s = 0; s < 4; s++) {
                        int p = s ^ d;
                        if (p > s) {
                            int e = lane + 32 * s;
                            bool desc = ((e & k) == 0);
                            bool sw2 = desc ? (v[s] < v[p]) : (v[s] > v[p]);
                            if (sw2) { ull t = v[s]; v[s] = v[p]; v[p] = t; }
                        }
                    }
                } else {
#pragma unroll
                    for (int s = 0; s < 4; s++) {
                        ull other = __shfl_xor_sync(0xffffffffu, v[s], j);
                        int e = lane + 32 * s;
                        bool takeMax = ((e & k) == 0) != ((lane & j) != 0);
                        ull mx = v[s] > other ? v[s] : other;
                        ull mn = v[s] > other ? other : v[s];
                        v[s] = takeMax ? mx : mn;
                    }
                }
            }
        }
        // descending over e: top-16 = v[0] of lanes 0..15
        bool valid = lane < 16;
        ull kk2 = v[0];
        float a = __uint_as_float((unsigned)(kk2 >> 32));
        int idx = (int)(~(unsigned)kk2);
        float maxa = __shfl_sync(0xffffffffu, a, 0);
        float sel = valid ? row[idx] : 0.f;
        float e = valid ? expf(a - maxa) : 0.f;
        float sum = e;
#pragma unroll
        for (int off = 8; off; off >>= 1) sum += __shfl_xor_sync(0xffffffffu, sum, off, 16);
        float sgn = (sel > 0.f) ? 1.f : ((sel < 0.f) ? -1.f : 0.f);
        float edge = sgn * e / sum;
        if (valid) { s_edge[lane] = edge; s_eidx[lane] = idx; }
        float c = valid ? edge * token_state[(size_t)b * Ss + idx] : 0.f;
#pragma unroll
        for (int off = 8; off; off >>= 1) c += __shfl_xor_sync(0xffffffffu, c, off, 16);
        if (lane == 0) g_state1_raw[bm] = g_mem_state0[m] + c;
    }
    __syncthreads();

    // value update + LN
    int d = tid;
    float a0 = g_mem_val0[(size_t)m * Dd + d];
    float a1 = g_mem_val0[(size_t)m * Dd + d + 256];
#pragma unroll
    for (int k = 0; k < 16; k++) {
        const float* tv = token_val + ((size_t)b * Ss + s_eidx[k]) * Dd;
        float ek = s_edge[k];
        a0 = fmaf(ek, tv[d], a0);
        a1 = fmaf(ek, tv[d + 256], a1);
    }
    float mu, ri;
    block_ln_512(a0, a1, mu, ri, swr);
    float* o = g_mem_val1 + (size_t)bm * Dd;
    o[d]       = (a0 - mu) * ri * ln_g[d] + ln_b[d];
    o[d + 256] = (a1 - mu) * ri * ln_g[d + 256] + ln_b[d + 256];
}

// ---------------- propagation: 8 rows/block, per-warp bisection top-16 ----------------
__global__ __launch_bounds__(256) void prop8_kernel(
    float* __restrict__ out_final, const float* __restrict__ ln_g,
    const float* __restrict__ ln_b) {
    int b = blockIdx.x >> 5;
    int i0 = (blockIdx.x & 31) * 8;
    int tid = threadIdx.x, w = tid >> 5, lane = tid & 31;
    __shared__ float s_qt[8][68];
    __shared__ float sqs[32][68];
    __shared__ float prow[8][256];
    __shared__ ull wkeys[8][32];
    __shared__ float s_edge[8][16];
    __shared__ int s_eidx[8][16];
    __shared__ float swr[18];

    if (tid < 128) {
        int r = tid >> 4, q = tid & 15;
        *(float4*)&s_qt[r][q * 4] =
            *(const float4*)&g_qt[((size_t)(b * Mm + i0 + r)) * Rr + 4 * q];
    }
    __syncthreads();

    float pv[8];
    for (int j0 = 0; j0 < Mm; j0 += 32) {
#pragma unroll
        for (int t = 0; t < 2; t++) {
            int f = tid + 256 * t;
            int jj = f >> 4, q = f & 15;
            *(float4*)&sqs[jj][q * 4] =
                *(const float4*)&g_qs2[((size_t)(b * Mm + j0 + jj)) * Rr + 4 * q];
        }
        __syncthreads();
        float acc = 0.f;
#pragma unroll
        for (int k4 = 0; k4 < Rr; k4 += 4) {
            float4 qv = *(const float4*)&sqs[lane][k4];
            float4 tv = *(const float4*)&s_qt[w][k4];
            acc = fmaf(qv.x, tv.x, fmaf(qv.y, tv.y, fmaf(qv.z, tv.z, fmaf(qv.w, tv.w, acc))));
        }
        pv[j0 >> 5] = acc;
        prow[w][j0 + lane] = acc;
        __syncthreads();
    }

    float av[8];
#pragma unroll
    for (int r = 0; r < 8; r++) av[r] = fabsf(pv[r]);
    unsigned um = 0;
#pragma unroll
    for (int r = 0; r < 8; r++) um = max(um, __float_as_uint(av[r]));
    um = __reduce_max_sync(0xffffffffu, um);
    float hi = __uint_as_float(um), lo = 0.f;
    int cl = 256;
    for (int it = 0; it < 32 && cl > 32; it++) {
        float mid = 0.5f * (lo + hi);
        int c = 0;
#pragma unroll
        for (int r = 0; r < 8; r++) c += (av[r] > mid);
        c = (int)__reduce_add_sync(0xffffffffu, (unsigned)c);
        if (c >= 16) { lo = mid; cl = c; } else { hi = mid; }
    }

    wkeys[w][lane] = 0ull;
    __syncwarp();
    int base = 0;
#pragma unroll
    for (int r = 0; r < 8; r++) {
        bool p = av[r] > lo;
        unsigned msk = __ballot_sync(0xffffffffu, p);
        if (p) {
            int pos = base + __popc(msk & ((1u << lane) - 1));
            if (pos < 32)
                wkeys[w][pos] =
                    ((ull)__float_as_uint(av[r]) << 32) | (unsigned)(~(r * 32 + lane));
        }
        base += __popc(msk);
    }
    __syncwarp();

    ull key = wkeys[w][lane];
#pragma unroll
    for (int k = 2; k <= 32; k <<= 1) {
#pragma unroll
        for (int j = k >> 1; j; j >>= 1) {
            ull other = __shfl_xor_sync(0xffffffffu, key, j);
            bool takeMax = ((lane & k) == 0) != ((lane & j) != 0);
            ull mx2 = key > other ? key : other;
            ull mn2 = key > other ? other : key;
            key = takeMax ? mx2 : mn2;
        }
    }

    {
        bool valid = lane < 16;
        float a = __uint_as_float((unsigned)(key >> 32));
        int idx = (int)(~(unsigned)key);
        float maxa = __shfl_sync(0xffffffffu, a, 0);
        float sel = valid ? prow[w][idx] : 0.f;
        float e = valid ? expf(a - maxa) : 0.f;
        float sum = e;
#pragma unroll
        for (int off = 8; off; off >>= 1) sum += __shfl_xor_sync(0xffffffffu, sum, off, 16);
        float sgn = (sel > 0.f) ? 1.f : ((sel < 0.f) ? -1.f : 0.f);
        float edge = sgn * e / sum;
        if (valid) { s_edge[w][lane] = edge; s_eidx[w][lane] = idx; }
    }
    __syncthreads();

    for (int r = 0; r < 8; r++) {
        int bi = b * Mm + i0 + r;
        int d = tid;
        float a0 = g_mem_val1[(size_t)bi * Dd + d];
        float a1 = g_mem_val1[(size_t)bi * Dd + d + 256];
#pragma unroll
        for (int k = 0; k < 16; k++) {
            const float* mv = g_mem_val1 + ((size_t)(b * Mm + s_eidx[r][k])) * Dd;
            float ek = s_edge[r][k];
            a0 = fmaf(ek, mv[d], a0);
            a1 = fmaf(ek, mv[d + 256], a1);
        }
        float mu, ri;
        block_ln_512(a0, a1, mu, ri, swr);
        float* o = out_final + (size_t)bi * Dd;
        o[d]       = (a0 - mu) * ri * ln_g[d] + ln_b[d];
        o[d + 256] = (a1 - mu) * ri * ln_g[d + 256] + ln_b[d + 256];
        __syncthreads();
    }
}

// ---------------- host launch ----------------
extern "C" void kernel_launch(void* const* d_in, const int* in_sizes, int n_in,
                              void* d_out, int out_size) {
    (void)in_sizes; (void)n_in; (void)out_size;
    const float* token_val   = (const float*)d_in[0];
    const float* token_state = (const float*)d_in[1];
    const float* init_state  = (const float*)d_in[2];
    const float* init_val    = (const float*)d_in[3];
    const float* rUs_w = (const float*)d_in[4];
    const float* rUs_b = (const float*)d_in[5];
    const float* rUt_w = (const float*)d_in[6];
    const float* rUt_b = (const float*)d_in[7];
    const float* r_w   = (const float*)d_in[8];
    const float* pUs_w = (const float*)d_in[9];
    const float* pUs_b = (const float*)d_in[10];
    const float* pUt_w = (const float*)d_in[11];
    const float* pUt_b = (const float*)d_in[12];
    const float* p_w   = (const float*)d_in[13];
    const float* ln_g  = (const float*)d_in[14];
    const float* ln_b  = (const float*)d_in[15];
    float* out = (float*)d_out;

    float *p_mv0, *p_mv1, *p_qt, *p_qs2, *p_st1raw, *p_st1;
    float *p_Wh, *p_Wl, *p_Wth, *p_Wtl, *p_Wpsh, *p_Wpsl, *p_Wpth, *p_Wptl;
    float *p_bt2, *p_bqt, *p_pt2h, *p_pt2l, *p_psh, *p_psl;
    cudaGetSymbolAddress((void**)&p_mv0, g_mem_val0);
    cudaGetSymbolAddress((void**)&p_mv1, g_mem_val1);
    cudaGetSymbolAddress((void**)&p_qt, g_qt);
    cudaGetSymbolAddress((void**)&p_qs2, g_qs2);
    cudaGetSymbolAddress((void**)&p_st1raw, g_state1_raw);
    cudaGetSymbolAddress((void**)&p_st1, g_state1);
    cudaGetSymbolAddress((void**)&p_Wh, g_Wh);
    cudaGetSymbolAddress((void**)&p_Wl, g_Wl);
    cudaGetSymbolAddress((void**)&p_Wth, g_Wth);
    cudaGetSymbolAddress((void**)&p_Wtl, g_Wtl);
    cudaGetSymbolAddress((void**)&p_Wpsh, g_Wpsh);
    cudaGetSymbolAddress((void**)&p_Wpsl, g_Wpsl);
    cudaGetSymbolAddress((void**)&p_Wpth, g_Wpth);
    cudaGetSymbolAddress((void**)&p_Wptl, g_Wptl);
    cudaGetSymbolAddress((void**)&p_bt2, g_bt2);
    cudaGetSymbolAddress((void**)&p_bqt, g_bqt);
    cudaGetSymbolAddress((void**)&p_pt2h, g_pt2_h);
    cudaGetSymbolAddress((void**)&p_pt2l, g_pt2_l);
    cudaGetSymbolAddress((void**)&p_psh, g_ps_h);
    cudaGetSymbolAddress((void**)&p_psl, g_ps_l);

    const int SC_SMEM = 4 * 128 * 72 * 4;  // 147456 bytes
    cudaFuncSetAttribute(scores_tc_kernel,
                         cudaFuncAttributeMaxDynamicSharedMemorySize, SC_SMEM);
    cudaFuncSetAttribute(gemm_tc_proj,
                         cudaFuncAttributeMaxDynamicSharedMemorySize, PS_SMEM_BYTES);

    // fused prologue
    prep_kernel<<<322, 256>>>(init_val, init_state, rUs_w, rUt_w, rUt_b, r_w,
                              pUs_w, pUt_w, pUt_b, p_w, ln_g, ln_b);
    // fused TC projection: [0,256) -> ps (split out); [256,258) -> pt2 (split out)
    gemm_tc_proj<<<(Bb * Ss) / 128 + Mm / 128, 256, PS_SMEM_BYTES>>>(
        (Bb * Ss) / 128,
        token_val, rUs_b, p_Wh, p_Wl, p_psh, p_psl, nullptr,
        p_mv0, p_bt2, p_Wth, p_Wtl, p_pt2h, p_pt2l, nullptr);
    // scores = pt2 . ps  (pure MMA from pre-split tiles)
    scores_tc_kernel<<<dim3(Ss / 128, Mm / 128, Bb), 256, SC_SMEM>>>();
    // write phase: warp-local topk + edges + gather-add + LN; raw state update
    write_kernel<<<Bb * Mm, 256>>>(token_val, token_state, ln_g, ln_b);
    // state1 = signed_softmax_state(state1_raw)
    sss_kernel<<<Bb, 256>>>(p_st1raw, p_st1);
    // fused TC projection: [0,32) -> qt (raw); [32,64) -> qs2 (raw, rowscale = state1)
    gemm_tc_proj<<<(Bb * Mm) / 128 * 2, 256, PS_SMEM_BYTES>>>(
        (Bb * Mm) / 128,
        p_mv1, p_bqt, p_Wpth, p_Wptl, p_qt, nullptr, nullptr,
        p_mv1, pUs_b, p_Wpsh, p_Wpsl, p_qs2, nullptr, p_st1);
    // propagation (8 rows/block, warp bisection) + final LN -> out
    prop8_kernel<<<(Bb * Mm) / 8, 256>>>(out, ln_g, ln_b);
}

// round 14
// speedup vs baseline: 1.3920x; 1.1182x over previous
#include <cuda_runtime.h>
#include <math.h>
#include <stdint.h>

// Problem shapes (fixed by the dataset)
constexpr int Bb = 16;    // batch
constexpr int Ss = 2048;  // tokens
constexpr int Dd = 512;   // dim
constexpr int Mm = 256;   // memory slots
constexpr int Rr = 64;    // low rank
constexpr float EPS = 1e-5f;
constexpr float STATE_MASS = 4.0f;
constexpr float LRS = 0.1f;

typedef unsigned long long ull;

// ---------------- scratch (static device globals; no allocs) ----------------
__device__ float g_scores[(size_t)Bb * Mm * Ss];   // 33.5 MB (L2-resident) [b][m][s]
__device__ float g_ps_h[(size_t)Bb * Ss * Rr];     // ps split hi
__device__ float g_ps_l[(size_t)Bb * Ss * Rr];     // ps split lo
__device__ float g_mem_val0[(size_t)Mm * Dd];      // LN(init_val), batch-independent
__device__ float g_pt2_h[(size_t)Mm * Rr];         // pt2 split hi
__device__ float g_pt2_l[(size_t)Mm * Rr];         // pt2 split lo
__device__ float g_Wh[(size_t)Dd * Rr];            // rUs_w split hi
__device__ float g_Wl[(size_t)Dd * Rr];            // rUs_w split lo
__device__ float g_Wth[(size_t)Dd * Rr];           // (rUt_w * r_w * LRS) split hi
__device__ float g_Wtl[(size_t)Dd * Rr];           // (rUt_w * r_w * LRS) split lo
__device__ float g_Wpsh[(size_t)Dd * Rr];          // pUs_w split hi
__device__ float g_Wpsl[(size_t)Dd * Rr];          // pUs_w split lo
__device__ float g_Wpth[(size_t)Dd * Rr];          // (pUt_w * p_w * LRS) split hi
__device__ float g_Wptl[(size_t)Dd * Rr];          // (pUt_w * p_w * LRS) split lo
__device__ float g_bt2[Rr];                        // rUt_b * r_w * LRS
__device__ float g_bqt[Rr];                        // pUt_b * p_w * LRS
__device__ float g_mem_state0[Mm];                 // signed-softmax-state(init_state)
__device__ float g_mem_val1[(size_t)Bb * Mm * Dd]; // post-write, post-LN
__device__ float g_state1_raw[(size_t)Bb * Mm];
__device__ float g_state1[(size_t)Bb * Mm];
__device__ float g_qt[(size_t)Bb * Mm * Rr];       // (mem_val1@pUt + b) * p_w * 0.1
__device__ float g_qs2[(size_t)Bb * Mm * Rr];      // (mem_val1@pUs + b) * state1[b,j]

// ---------------- tf32 / cp.async helpers ----------------
__device__ __forceinline__ uint32_t f2tf32(float x) {
    uint32_t r;
    asm("cvt.rna.tf32.f32 %0, %1;" : "=r"(r) : "f"(x));
    return r;
}

__device__ __forceinline__ void cpa16(void* dst_smem, const void* src) {
    uint32_t d = (uint32_t)__cvta_generic_to_shared(dst_smem);
    asm volatile("cp.async.ca.shared.global [%0], [%1], 16;" :: "r"(d), "l"(src));
}
#define CP_COMMIT() asm volatile("cp.async.commit_group;")
#define CP_WAIT(n)  asm volatile("cp.async.wait_group %0;" :: "n"(n))

#define MMA_TF32(C, A, B0, B1)                                                  \
    asm volatile(                                                               \
        "mma.sync.aligned.m16n8k8.row.col.f32.tf32.tf32.f32 "                   \
        "{%0,%1,%2,%3}, {%4,%5,%6,%7}, {%8,%9}, {%0,%1,%2,%3};"                 \
        : "+f"((C)[0]), "+f"((C)[1]), "+f"((C)[2]), "+f"((C)[3])                \
        : "r"((A)[0]), "r"((A)[1]), "r"((A)[2]), "r"((A)[3]), "r"(B0), "r"(B1))

// ---------------- shared helpers ----------------
__device__ __forceinline__ void block_ln_512(float a0, float a1, float& mu, float& ri,
                                             float* swr) {
    float ps = a0 + a1;
    float pq = fmaf(a0, a0, a1 * a1);
#pragma unroll
    for (int off = 16; off; off >>= 1) {
        ps += __shfl_down_sync(0xffffffffu, ps, off);
        pq += __shfl_down_sync(0xffffffffu, pq, off);
    }
    int tid = threadIdx.x, wid = tid >> 5, lane = tid & 31;
    if (lane == 0) { swr[wid] = ps; swr[8 + wid] = pq; }
    __syncthreads();
    if (tid == 0) {
        float s = 0.f, q = 0.f;
#pragma unroll
        for (int i = 0; i < 8; i++) { s += swr[i]; q += swr[8 + i]; }
        float m = s * (1.0f / 512.0f);
        float v = q * (1.0f / 512.0f) - m * m;
        swr[16] = m;
        swr[17] = rsqrtf(v + EPS);
    }
    __syncthreads();
    mu = swr[16];
    ri = swr[17];
}

__device__ __forceinline__ void split2(float v, float& h, float& l) {
    h = __uint_as_float(f2tf32(v));
    l = __uint_as_float(f2tf32(v - h));
}

// ---------------- fused prologue kernel ----------------
__global__ __launch_bounds__(256) void prep_kernel(
    const float* __restrict__ init_val, const float* __restrict__ init_state,
    const float* __restrict__ rUs_w, const float* __restrict__ rUt_w,
    const float* __restrict__ rUt_b, const float* __restrict__ r_w,
    const float* __restrict__ pUs_w, const float* __restrict__ pUt_w,
    const float* __restrict__ pUt_b, const float* __restrict__ p_w,
    const float* __restrict__ ln_g, const float* __restrict__ ln_b) {
    __shared__ float swr[18];
    __shared__ float s_bc[2];
    int blk = blockIdx.x, tid = threadIdx.x;
    int wid = tid >> 5, lane = tid & 31;

    if (blk < 256) {
        const float* x = init_val + (size_t)blk * Dd;
        float a0 = x[tid], a1 = x[tid + 256];
        float mu, ri;
        block_ln_512(a0, a1, mu, ri, swr);
        float* o = g_mem_val0 + (size_t)blk * Dd;
        o[tid]       = (a0 - mu) * ri * ln_g[tid] + ln_b[tid];
        o[tid + 256] = (a1 - mu) * ri * ln_g[tid + 256] + ln_b[tid + 256];
    } else if (blk < 320) {
        int grp = (blk - 256) >> 4;        // 0: rUs, 1: rUt*r_w, 2: pUs, 3: pUt*p_w
        int base = ((blk - 256) & 15) * 2048 + tid * 8;
        const float* src = grp == 0 ? rUs_w : grp == 1 ? rUt_w : grp == 2 ? pUs_w : pUt_w;
        const float* sc  = grp == 1 ? r_w : grp == 3 ? p_w : nullptr;
        float* dh = grp == 0 ? g_Wh : grp == 1 ? g_Wth : grp == 2 ? g_Wpsh : g_Wpth;
        float* dl = grp == 0 ? g_Wl : grp == 1 ? g_Wtl : grp == 2 ? g_Wpsl : g_Wptl;
#pragma unroll
        for (int q = 0; q < 2; q++) {
            int i = base + 4 * q;
            float4 v = *(const float4*)&src[i];
            if (sc) {
                v.x *= sc[(i + 0) & 63] * LRS;
                v.y *= sc[(i + 1) & 63] * LRS;
                v.z *= sc[(i + 2) & 63] * LRS;
                v.w *= sc[(i + 3) & 63] * LRS;
            }
            float4 h, l;
            split2(v.x, h.x, l.x); split2(v.y, h.y, l.y);
            split2(v.z, h.z, l.z); split2(v.w, h.w, l.w);
            *(float4*)&dh[i] = h;
            *(float4*)&dl[i] = l;
        }
    } else if (blk == 320) {
        float v = init_state[tid];
        float a = fabsf(v);
        float m = a;
#pragma unroll
        for (int off = 16; off; off >>= 1) m = fmaxf(m, __shfl_down_sync(0xffffffffu, m, off));
        if (lane == 0) swr[wid] = m;
        __syncthreads();
        if (tid == 0) {
            float mm = swr[0];
#pragma unroll
            for (int i = 1; i < 8; i++) mm = fmaxf(mm, swr[i]);
            s_bc[0] = mm;
        }
        __syncthreads();
        float e = expf(a - s_bc[0]);
        float s = e;
#pragma unroll
        for (int off = 16; off; off >>= 1) s += __shfl_down_sync(0xffffffffu, s, off);
        __syncthreads();
        if (lane == 0) swr[wid] = s;
        __syncthreads();
        if (tid == 0) {
            float ss = 0.f;
#pragma unroll
            for (int i = 0; i < 8; i++) ss += swr[i];
            s_bc[1] = ss;
        }
        __syncthreads();
        float sgn = (v > 0.f) ? 1.f : ((v < 0.f) ? -1.f : 0.f);
        g_mem_state0[tid] = sgn * e / s_bc[1] * STATE_MASS;
    } else {
        if (tid < Rr) g_bt2[tid] = rUt_b[tid] * r_w[tid] * LRS;
        else if (tid < 2 * Rr) g_bqt[tid - Rr] = pUt_b[tid - Rr] * p_w[tid - Rr] * LRS;
    }
}

// ---------------- kernel: signed softmax state over 256 slots ----------------
__global__ void sss_kernel(const float* __restrict__ in, float* __restrict__ out) {
    int tid = threadIdx.x;
    const float* x = in + (size_t)blockIdx.x * Mm;
    float v = x[tid];
    float a = fabsf(v);
    __shared__ float swr[8];
    __shared__ float s_bc[2];
    int wid = tid >> 5, lane = tid & 31;
    float m = a;
#pragma unroll
    for (int off = 16; off; off >>= 1) m = fmaxf(m, __shfl_down_sync(0xffffffffu, m, off));
    if (lane == 0) swr[wid] = m;
    __syncthreads();
    if (tid == 0) {
        float mm = swr[0];
#pragma unroll
        for (int i = 1; i < 8; i++) mm = fmaxf(mm, swr[i]);
        s_bc[0] = mm;
    }
    __syncthreads();
    float e = expf(a - s_bc[0]);
    float s = e;
#pragma unroll
    for (int off = 16; off; off >>= 1) s += __shfl_down_sync(0xffffffffu, s, off);
    __syncthreads();
    if (lane == 0) swr[wid] = s;
    __syncthreads();
    if (tid == 0) {
        float ss = 0.f;
#pragma unroll
        for (int i = 0; i < 8; i++) ss += swr[i];
        s_bc[1] = ss;
    }
    __syncthreads();
    float sgn = (v > 0.f) ? 1.f : ((v < 0.f) ? -1.f : 0.f);
    out[(size_t)blockIdx.x * Mm + tid] = sgn * e / s_bc[1] * STATE_MASS;
}

// ---------------- tensor-core projection GEMM (dual parameter set) ----------
constexpr int PS_XOFF = 0;
constexpr int PS_WHOFF = 128 * 20;
constexpr int PS_WLOFF = 128 * 20 + 16 * 72;
constexpr int PS_STAGE = 128 * 20 + 2 * 16 * 72;  // floats per stage = 4864
constexpr int PS_SMEM_BYTES = 3 * PS_STAGE * 4;   // 58368

__global__ __launch_bounds__(256) void gemm_tc_proj(
    int split,
    const float* __restrict__ X0, const float* __restrict__ b0,
    const float* __restrict__ Wh0, const float* __restrict__ Wl0,
    float* __restrict__ oh0, float* __restrict__ ol0, const float* __restrict__ rsc0,
    const float* __restrict__ X1, const float* __restrict__ b1,
    const float* __restrict__ Wh1, const float* __restrict__ Wl1,
    float* __restrict__ oh1, float* __restrict__ ol1, const float* __restrict__ rsc1) {
    extern __shared__ __align__(16) float smp[];
    int tid = threadIdx.x, w = tid >> 5, lane = tid & 31;
    int g = lane >> 2, tg = lane & 3;
    int set = ((int)blockIdx.x >= split);
    int rowblk = set ? (int)blockIdx.x - split : (int)blockIdx.x;
    const float* X    = set ? X1 : X0;
    const float* bias = set ? b1 : b0;
    const float* Wh   = set ? Wh1 : Wh0;
    const float* Wl   = set ? Wl1 : Wl0;
    float* oh         = set ? oh1 : oh0;
    float* ol         = set ? ol1 : ol0;
    const float* rsc  = set ? rsc1 : rsc0;
    int row0 = rowblk * 128;
    int wm = w >> 1, wn = w & 1;

    int lr = tid >> 2, lq = (tid & 3) * 4;
    int wk = tid >> 4, wc = (tid & 15) * 4;

    float acc[2][4][4];
#pragma unroll
    for (int mt = 0; mt < 2; mt++)
#pragma unroll
        for (int nt = 0; nt < 4; nt++)
#pragma unroll
            for (int c = 0; c < 4; c++) acc[mt][nt][c] = 0.f;

#pragma unroll
    for (int pc = 0; pc < 2; pc++) {
        int k0 = pc * 16;
        float* st = smp + pc * PS_STAGE;
        cpa16(st + PS_XOFF + lr * 20 + lq,        &X[(size_t)(row0 + lr) * Dd + k0 + lq]);
        cpa16(st + PS_XOFF + (lr + 64) * 20 + lq, &X[(size_t)(row0 + lr + 64) * Dd + k0 + lq]);
        cpa16(st + PS_WHOFF + wk * 72 + wc,       &Wh[(size_t)(k0 + wk) * Rr + wc]);
        cpa16(st + PS_WLOFF + wk * 72 + wc,       &Wl[(size_t)(k0 + wk) * Rr + wc]);
        CP_COMMIT();
    }

    for (int c = 0; c < 32; c++) {
        CP_WAIT(1);
        __syncthreads();
        float* st = smp + (c % 3) * PS_STAGE;
        float* sx = st + PS_XOFF;
        float* swh = st + PS_WHOFF;
        float* swl = st + PS_WLOFF;
#pragma unroll
        for (int ks = 0; ks < 2; ks++) {
            int kk = ks * 8;
            uint32_t ah[2][4], al[2][4];
#pragma unroll
            for (int mt = 0; mt < 2; mt++) {
                int r = wm * 32 + mt * 16;
                float x0 = sx[(r + g) * 20 + kk + tg];
                float x1 = sx[(r + g + 8) * 20 + kk + tg];
                float x2 = sx[(r + g) * 20 + kk + tg + 4];
                float x3 = sx[(r + g + 8) * 20 + kk + tg + 4];
                ah[mt][0] = f2tf32(x0); al[mt][0] = f2tf32(x0 - __uint_as_float(ah[mt][0]));
                ah[mt][1] = f2tf32(x1); al[mt][1] = f2tf32(x1 - __uint_as_float(ah[mt][1]));
                ah[mt][2] = f2tf32(x2); al[mt][2] = f2tf32(x2 - __uint_as_float(ah[mt][2]));
                ah[mt][3] = f2tf32(x3); al[mt][3] = f2tf32(x3 - __uint_as_float(ah[mt][3]));
            }
#pragma unroll
            for (int nt = 0; nt < 4; nt++) {
                int cc = wn * 32 + nt * 8 + g;
                uint32_t bh0 = __float_as_uint(swh[(kk + tg) * 72 + cc]);
                uint32_t bh1 = __float_as_uint(swh[(kk + tg + 4) * 72 + cc]);
                uint32_t bl0 = __float_as_uint(swl[(kk + tg) * 72 + cc]);
                uint32_t bl1 = __float_as_uint(swl[(kk + tg + 4) * 72 + cc]);
#pragma unroll
                for (int mt = 0; mt < 2; mt++) {
                    MMA_TF32(acc[mt][nt], ah[mt], bh0, bh1);
                    MMA_TF32(acc[mt][nt], ah[mt], bl0, bl1);
                    MMA_TF32(acc[mt][nt], al[mt], bh0, bh1);
                }
            }
        }
        __syncthreads();
        int nc = c + 2;
        if (nc < 32) {
            int k0 = nc * 16;
            float* s2 = smp + (nc % 3) * PS_STAGE;
            cpa16(s2 + PS_XOFF + lr * 20 + lq,        &X[(size_t)(row0 + lr) * Dd + k0 + lq]);
            cpa16(s2 + PS_XOFF + (lr + 64) * 20 + lq, &X[(size_t)(row0 + lr + 64) * Dd + k0 + lq]);
            cpa16(s2 + PS_WHOFF + wk * 72 + wc,       &Wh[(size_t)(k0 + wk) * Rr + wc]);
            cpa16(s2 + PS_WLOFF + wk * 72 + wc,       &Wl[(size_t)(k0 + wk) * Rr + wc]);
        }
        CP_COMMIT();
    }

#pragma unroll
    for (int mt = 0; mt < 2; mt++) {
        int r = row0 + wm * 32 + mt * 16 + g;
#pragma unroll
        for (int nt = 0; nt < 4; nt++) {
            int c = wn * 32 + nt * 8 + 2 * tg;
            float b0v = bias[c], b1v = bias[c + 1];
            float v00 = acc[mt][nt][0] + b0v, v01 = acc[mt][nt][1] + b1v;
            float v10 = acc[mt][nt][2] + b0v, v11 = acc[mt][nt][3] + b1v;
            if (ol) {
                float h00 = __uint_as_float(f2tf32(v00));
                float h01 = __uint_as_float(f2tf32(v01));
                float h10 = __uint_as_float(f2tf32(v10));
                float h11 = __uint_as_float(f2tf32(v11));
                *(float2*)&oh[(size_t)r * Rr + c]       = make_float2(h00, h01);
                *(float2*)&oh[(size_t)(r + 8) * Rr + c] = make_float2(h10, h11);
                *(float2*)&ol[(size_t)r * Rr + c] = make_float2(
                    __uint_as_float(f2tf32(v00 - h00)), __uint_as_float(f2tf32(v01 - h01)));
                *(float2*)&ol[(size_t)(r + 8) * Rr + c] = make_float2(
                    __uint_as_float(f2tf32(v10 - h10)), __uint_as_float(f2tf32(v11 - h11)));
            } else {
                float r0s = rsc ? rsc[r] : 1.f;
                float r1s = rsc ? rsc[r + 8] : 1.f;
                *(float2*)&oh[(size_t)r * Rr + c]       = make_float2(v00 * r0s, v01 * r0s);
                *(float2*)&oh[(size_t)(r + 8) * Rr + c] = make_float2(v10 * r1s, v11 * r1s);
            }
        }
    }
}

// ---------------- tensor-core scores GEMM: pure MMA from pre-split tiles ----------
__global__ __launch_bounds__(256) void scores_tc_kernel() {
    extern __shared__ __align__(16) float smc[];
    float (*sah)[72] = (float(*)[72])smc;
    float (*sal)[72] = (float(*)[72])(smc + 128 * 72);
    float (*sbh)[72] = (float(*)[72])(smc + 2 * 128 * 72);
    float (*sbl)[72] = (float(*)[72])(smc + 3 * 128 * 72);
    int tid = threadIdx.x, w = tid >> 5, lane = tid & 31;
    int g = lane >> 2, tg = lane & 3;
    int b = blockIdx.z;
    int m0 = blockIdx.y * 128;
    int s0 = blockIdx.x * 128;
    int wm = w >> 1, wn = w & 1;

#pragma unroll
    for (int t = 0; t < 8; t++) {
        int f = tid + 256 * t;
        int r = f >> 4, q = (f & 15) * 4;
        cpa16(&sah[r][q], &g_pt2_h[(size_t)(m0 + r) * Rr + q]);
        cpa16(&sal[r][q], &g_pt2_l[(size_t)(m0 + r) * Rr + q]);
        cpa16(&sbh[r][q], &g_ps_h[((size_t)b * Ss + s0 + r) * Rr + q]);
        cpa16(&sbl[r][q], &g_ps_l[((size_t)b * Ss + s0 + r) * Rr + q]);
    }
    CP_COMMIT();

    float acc[2][8][4];
#pragma unroll
    for (int mt = 0; mt < 2; mt++)
#pragma unroll
        for (int nt = 0; nt < 8; nt++)
#pragma unroll
            for (int c = 0; c < 4; c++) acc[mt][nt][c] = 0.f;

    CP_WAIT(0);
    __syncthreads();

#pragma unroll
    for (int ks = 0; ks < 8; ks++) {
        int kk = ks * 8;
        uint32_t ah[2][4], al[2][4];
#pragma unroll
        for (int mt = 0; mt < 2; mt++) {
            int r = wm * 32 + mt * 16;
            ah[mt][0] = __float_as_uint(sah[r + g][kk + tg]);
            ah[mt][1] = __float_as_uint(sah[r + g + 8][kk + tg]);
            ah[mt][2] = __float_as_uint(sah[r + g][kk + tg + 4]);
            ah[mt][3] = __float_as_uint(sah[r + g + 8][kk + tg + 4]);
            al[mt][0] = __float_as_uint(sal[r + g][kk + tg]);
            al[mt][1] = __float_as_uint(sal[r + g + 8][kk + tg]);
            al[mt][2] = __float_as_uint(sal[r + g][kk + tg + 4]);
            al[mt][3] = __float_as_uint(sal[r + g + 8][kk + tg + 4]);
        }
#pragma unroll
        for (int nt = 0; nt < 8; nt++) {
            int cc = wn * 64 + nt * 8 + g;
            uint32_t bh0 = __float_as_uint(sbh[cc][kk + tg]);
            uint32_t bh1 = __float_as_uint(sbh[cc][kk + tg + 4]);
            uint32_t bl0 = __float_as_uint(sbl[cc][kk + tg]);
            uint32_t bl1 = __float_as_uint(sbl[cc][kk + tg + 4]);
#pragma unroll
            for (int mt = 0; mt < 2; mt++) {
                MMA_TF32(acc[mt][nt], ah[mt], bh0, bh1);
                MMA_TF32(acc[mt][nt], ah[mt], bl0, bl1);
                MMA_TF32(acc[mt][nt], al[mt], bh0, bh1);
            }
        }
    }

#pragma unroll
    for (int mt = 0; mt < 2; mt++) {
        int m = m0 + wm * 32 + mt * 16 + g;
#pragma unroll
        for (int nt = 0; nt < 8; nt++) {
            int s = s0 + wn * 64 + nt * 8 + 2 * tg;
            *(float2*)&g_scores[((size_t)(b * Mm + m)) * Ss + s] =
                make_float2(acc[mt][nt][0], acc[mt][nt][1]);
            *(float2*)&g_scores[((size_t)(b * Mm + m + 8)) * Ss + s] =
                make_float2(acc[mt][nt][2], acc[mt][nt][3]);
        }
    }
}

// ---------------- write phase: warp-local bisection + 128-key register sort ----------------
__global__ __launch_bounds__(256) void write_kernel(
    const float* __restrict__ token_val, const float* __restrict__ token_state,
    const float* __restrict__ ln_g, const float* __restrict__ ln_b) {
    int bm = blockIdx.x;
    int b = bm >> 8, m = bm & 255;
    int tid = threadIdx.x, w = tid >> 5, lane = tid & 31;
    __shared__ ull skeys[128];
    __shared__ ull wk[8][32];
    __shared__ float swr[18];
    __shared__ float s_edge[16];
    __shared__ int s_eidx[16];

    const float* row = g_scores + (size_t)bm * Ss;

    int base = w * 256 + lane;
    float aa[8];
#pragma unroll
    for (int j = 0; j < 8; j++) aa[j] = fabsf(row[base + 32 * j]);

    unsigned um = 0;
#pragma unroll
    for (int j = 0; j < 8; j++) um = max(um, __float_as_uint(aa[j]));
    um = __reduce_max_sync(0xffffffffu, um);
    float hi = __uint_as_float(um), lo = 0.f;
    int cl = 256;
    for (int it = 0; it < 32 && cl > 32; it++) {
        float mid = 0.5f * (lo + hi);
        int c = 0;
#pragma unroll
        for (int j = 0; j < 8; j++) c += (aa[j] > mid);
        c = (int)__reduce_add_sync(0xffffffffu, (unsigned)c);
        if (c >= 16) { lo = mid; cl = c; } else { hi = mid; }
    }

    wk[w][lane] = 0ull;
    __syncwarp();
    int bc = 0;
#pragma unroll
    for (int j = 0; j < 8; j++) {
        bool p = aa[j] > lo;
        unsigned msk = __ballot_sync(0xffffffffu, p);
        if (p) {
            int pos = bc + __popc(msk & ((1u << lane) - 1));
            if (pos < 32)
                wk[w][pos] = ((ull)__float_as_uint(aa[j]) << 32) | (unsigned)(~(base + 32 * j));
        }
        bc += __popc(msk);
    }
    __syncwarp();

    ull key = wk[w][lane];
#pragma unroll
    for (int k = 2; k <= 32; k <<= 1) {
#pragma unroll
        for (int j = k >> 1; j; j >>= 1) {
            ull other = __shfl_xor_sync(0xffffffffu, key, j);
            bool takeMax = ((lane & k) == 0) != ((lane & j) != 0);
            ull mx = key > other ? key : other;
            ull mn = key > other ? other : key;
            key = takeMax ? mx : mn;
        }
    }
    if (lane < 16) skeys[w * 16 + lane] = key;
    __syncthreads();

    if (w == 0) {
        ull v[4];
#pragma unroll
        for (int s = 0; s < 4; s++) v[s] = skeys[lane + 32 * s];
#pragma unroll
        for (int k = 2; k <= 128; k <<= 1) {
#pragma unroll
            for (int j = k >> 1; j; j >>= 1) {
                if (j >= 32) {
                    int d = j >> 5;
#pragma unroll
                    for (int s = 0; s < 4; s++) {
                        int p = s ^ d;
                        if (p > s) {
                            int e = lane + 32 * s;
                            bool desc = ((e & k) == 0);
                            bool sw2 = desc ? (v[s] < v[p]) : (v[s] > v[p]);
                            if (sw2) { ull t = v[s]; v[s] = v[p]; v[p] = t; }
                        }
                    }
                } else {
#pragma unroll
                    for (int s = 0; s < 4; s++) {
                        ull other = __shfl_xor_sync(0xffffffffu, v[s], j);
                        int e = lane + 32 * s;
                        bool takeMax = ((e & k) == 0) != ((lane & j) != 0);
                        ull mx = v[s] > other ? v[s] : other;
                        ull mn = v[s] > other ? other : v[s];
                        v[s] = takeMax ? mx : mn;
                    }
                }
            }
        }
        bool valid = lane < 16;
        ull kk2 = v[0];
        float a = __uint_as_float((unsigned)(kk2 >> 32));
        int idx = (int)(~(unsigned)kk2);
        float maxa = __shfl_sync(0xffffffffu, a, 0);
        float sel = valid ? row[idx] : 0.f;
        float e = valid ? expf(a - maxa) : 0.f;
        float sum = e;
#pragma unroll
        for (int off = 8; off; off >>= 1) sum += __shfl_xor_sync(0xffffffffu, sum, off, 16);
        float sgn = (sel > 0.f) ? 1.f : ((sel < 0.f) ? -1.f : 0.f);
        float edge = sgn * e / sum;
        if (valid) { s_edge[lane] = edge; s_eidx[lane] = idx; }
        float c = valid ? edge * token_state[(size_t)b * Ss + idx] : 0.f;
#pragma unroll
        for (int off = 8; off; off >>= 1) c += __shfl_xor_sync(0xffffffffu, c, off, 16);
        if (lane == 0) g_state1_raw[bm] = g_mem_state0[m] + c;
    }
    __syncthreads();

    int d = tid;
    float a0 = g_mem_val0[(size_t)m * Dd + d];
    float a1 = g_mem_val0[(size_t)m * Dd + d + 256];
#pragma unroll
    for (int k = 0; k < 16; k++) {
        const float* tv = token_val + ((size_t)b * Ss + s_eidx[k]) * Dd;
        float ek = s_edge[k];
        a0 = fmaf(ek, tv[d], a0);
        a1 = fmaf(ek, tv[d + 256], a1);
    }
    float mu, ri;
    block_ln_512(a0, a1, mu, ri, swr);
    float* o = g_mem_val1 + (size_t)bm * Dd;
    o[d]       = (a0 - mu) * ri * ln_g[d] + ln_b[d];
    o[d + 256] = (a1 - mu) * ri * ln_g[d + 256] + ln_b[d + 256];
}

// ---------------- propagation: 16 rows/block, one-shot staging, warp-per-row ----------------
// Dynamic smem layout (floats): sqs [256][68] | s_qt [16][68] | prow [16][256]
constexpr int PR_QS = 0;
constexpr int PR_QT = 256 * 68;
constexpr int PR_PR = 256 * 68 + 16 * 68;
constexpr int PR_SMEM_BYTES = (256 * 68 + 16 * 68 + 16 * 256) * 4;  // 90368

__global__ __launch_bounds__(256) void prop16_kernel(
    float* __restrict__ out_final, const float* __restrict__ ln_g,
    const float* __restrict__ ln_b) {
    extern __shared__ __align__(16) float smq[];
    float (*sqs)[68]  = (float(*)[68])(smq + PR_QS);
    float (*s_qt)[68] = (float(*)[68])(smq + PR_QT);
    float (*prow)[256] = (float(*)[256])(smq + PR_PR);
    __shared__ ull wkeys[8][32];
    __shared__ float s_edge[16][16];
    __shared__ int s_eidx[16][16];

    int b = blockIdx.x >> 4;
    int i0 = (blockIdx.x & 15) * 16;
    int tid = threadIdx.x, w = tid >> 5, lane = tid & 31;

    // stage qt rows (16 x 16 float4 = 256) and qs2[b] tile (256 x 16 float4 = 4096)
    {
        int r = tid >> 4, q = (tid & 15) * 4;
        cpa16(&s_qt[r][q], &g_qt[((size_t)(b * Mm + i0 + r)) * Rr + q]);
    }
#pragma unroll
    for (int t = 0; t < 16; t++) {
        int f = tid + 256 * t;
        int r = f >> 4, q = (f & 15) * 4;
        cpa16(&sqs[r][q], &g_qs2[((size_t)(b * Mm + r)) * Rr + q]);
    }
    CP_COMMIT();
    CP_WAIT(0);
    __syncthreads();  // the only block-wide sync

    // each warp handles local rows 2w, 2w+1
#pragma unroll
    for (int rr = 0; rr < 2; rr++) {
        int row = 2 * w + rr;

        // pscores: pv[jb] = dot(qt[row], qs2[jb*32 + lane])
        float pv[8];
#pragma unroll
        for (int jb = 0; jb < 8; jb++) {
            int j = jb * 32 + lane;
            float acc = 0.f;
#pragma unroll
            for (int k4 = 0; k4 < Rr; k4 += 4) {
                float4 qv = *(const float4*)&sqs[j][k4];
                float4 tv = *(const float4*)&s_qt[row][k4];
                acc = fmaf(qv.x, tv.x, fmaf(qv.y, tv.y, fmaf(qv.z, tv.z, fmaf(qv.w, tv.w, acc))));
            }
            pv[jb] = acc;
            prow[row][j] = acc;
        }
        __syncwarp();

        // warp bisection top-16 of 256
        float av[8];
#pragma unroll
        for (int r2 = 0; r2 < 8; r2++) av[r2] = fabsf(pv[r2]);
        unsigned um = 0;
#pragma unroll
        for (int r2 = 0; r2 < 8; r2++) um = max(um, __float_as_uint(av[r2]));
        um = __reduce_max_sync(0xffffffffu, um);
        float hi = __uint_as_float(um), lo = 0.f;
        int cl = 256;
        for (int it = 0; it < 32 && cl > 32; it++) {
            float mid = 0.5f * (lo + hi);
            int c = 0;
#pragma unroll
            for (int r2 = 0; r2 < 8; r2++) c += (av[r2] > mid);
            c = (int)__reduce_add_sync(0xffffffffu, (unsigned)c);
            if (c >= 16) { lo = mid; cl = c; } else { hi = mid; }
        }

        wkeys[w][lane] = 0ull;
        __syncwarp();
        int base = 0;
#pragma unroll
        for (int r2 = 0; r2 < 8; r2++) {
            bool p = av[r2] > lo;
            unsigned msk = __ballot_sync(0xffffffffu, p);
            if (p) {
                int pos = base + __popc(msk & ((1u << lane) - 1));
                if (pos < 32)
                    wkeys[w][pos] =
                        ((ull)__float_as_uint(av[r2]) << 32) | (unsigned)(~(r2 * 32 + lane));
            }
            base += __popc(msk);
        }
        __syncwarp();

        ull key = wkeys[w][lane];
#pragma unroll
        for (int k = 2; k <= 32; k <<= 1) {
#pragma unroll
            for (int j = k >> 1; j; j >>= 1) {
                ull other = __shfl_xor_sync(0xffffffffu, key, j);
                bool takeMax = ((lane & k) == 0) != ((lane & j) != 0);
                ull mx2 = key > other ? key : other;
                ull mn2 = key > other ? other : key;
                key = takeMax ? mx2 : mn2;
            }
        }

        bool valid = lane < 16;
        float a = __uint_as_float((unsigned)(key >> 32));
        int idx = (int)(~(unsigned)key);
        float maxa = __shfl_sync(0xffffffffu, a, 0);
        float sel = valid ? prow[row][idx] : 0.f;
        float e = valid ? expf(a - maxa) : 0.f;
        float sum = e;
#pragma unroll
        for (int off = 8; off; off >>= 1) sum += __shfl_xor_sync(0xffffffffu, sum, off, 16);
        float sgn = (sel > 0.f) ? 1.f : ((sel < 0.f) ? -1.f : 0.f);
        float edge = sgn * e / sum;
        if (valid) { s_edge[row][lane] = edge; s_eidx[row][lane] = idx; }
        __syncwarp();

        // warp-local epilogue: residual gather + LN for this row
        int bi = b * Mm + i0 + row;
        float4 acc4[4];
#pragma unroll
        for (int q = 0; q < 4; q++)
            acc4[q] = *(const float4*)&g_mem_val1[(size_t)bi * Dd + (q * 32 + lane) * 4];
#pragma unroll
        for (int k = 0; k < 16; k++) {
            float ek = s_edge[row][k];
            const float* mv = g_mem_val1 + ((size_t)(b * Mm + s_eidx[row][k])) * Dd;
#pragma unroll
            for (int q = 0; q < 4; q++) {
                float4 v = *(const float4*)&mv[(q * 32 + lane) * 4];
                acc4[q].x = fmaf(ek, v.x, acc4[q].x);
                acc4[q].y = fmaf(ek, v.y, acc4[q].y);
                acc4[q].z = fmaf(ek, v.z, acc4[q].z);
                acc4[q].w = fmaf(ek, v.w, acc4[q].w);
            }
        }
        float s = 0.f, sq = 0.f;
#pragma unroll
        for (int q = 0; q < 4; q++) {
            s += acc4[q].x + acc4[q].y + acc4[q].z + acc4[q].w;
            sq = fmaf(acc4[q].x, acc4[q].x, sq);
            sq = fmaf(acc4[q].y, acc4[q].y, sq);
            sq = fmaf(acc4[q].z, acc4[q].z, sq);
            sq = fmaf(acc4[q].w, acc4[q].w, sq);
        }
#pragma unroll
        for (int off = 16; off; off >>= 1) {
            s += __shfl_down_sync(0xffffffffu, s, off);
            sq += __shfl_down_sync(0xffffffffu, sq, off);
        }
        s = __shfl_sync(0xffffffffu, s, 0);
        sq = __shfl_sync(0xffffffffu, sq, 0);
        float mu = s * (1.0f / 512.0f);
        float ri = rsqrtf(sq * (1.0f / 512.0f) - mu * mu + EPS);
#pragma unroll
        for (int q = 0; q < 4; q++) {
            int d4 = (q * 32 + lane) * 4;
            float4 gv = *(const float4*)&ln_g[d4];
            float4 bv = *(const float4*)&ln_b[d4];
            float4 o;
            o.x = (acc4[q].x - mu) * ri * gv.x + bv.x;
            o.y = (acc4[q].y - mu) * ri * gv.y + bv.y;
            o.z = (acc4[q].z - mu) * ri * gv.z + bv.z;
            o.w = (acc4[q].w - mu) * ri * gv.w + bv.w;
            *(float4*)&out_final[(size_t)bi * Dd + d4] = o;
        }
    }
}

// ---------------- host launch ----------------
extern "C" void kernel_launch(void* const* d_in, const int* in_sizes, int n_in,
                              void* d_out, int out_size) {
    (void)in_sizes; (void)n_in; (void)out_size;
    const float* token_val   = (const float*)d_in[0];
    const float* token_state = (const float*)d_in[1];
    const float* init_state  = (const float*)d_in[2];
    const float* init_val    = (const float*)d_in[3];
    const float* rUs_w = (const float*)d_in[4];
    const float* rUs_b = (const float*)d_in[5];
    const float* rUt_w = (const float*)d_in[6];
    const float* rUt_b = (const float*)d_in[7];
    const float* r_w   = (const float*)d_in[8];
    const float* pUs_w = (const float*)d_in[9];
    const float* pUs_b = (const float*)d_in[10];
    const float* pUt_w = (const float*)d_in[11];
    const float* pUt_b = (const float*)d_in[12];
    const float* p_w   = (const float*)d_in[13];
    const float* ln_g  = (const float*)d_in[14];
    const float* ln_b  = (const float*)d_in[15];
    float* out = (float*)d_out;

    float *p_mv0, *p_mv1, *p_qt, *p_qs2, *p_st1raw, *p_st1;
    float *p_Wh, *p_Wl, *p_Wth, *p_Wtl, *p_Wpsh, *p_Wpsl, *p_Wpth, *p_Wptl;
    float *p_bt2, *p_bqt, *p_pt2h, *p_pt2l, *p_psh, *p_psl;
    cudaGetSymbolAddress((void**)&p_mv0, g_mem_val0);
    cudaGetSymbolAddress((void**)&p_mv1, g_mem_val1);
    cudaGetSymbolAddress((void**)&p_qt, g_qt);
    cudaGetSymbolAddress((void**)&p_qs2, g_qs2);
    cudaGetSymbolAddress((void**)&p_st1raw, g_state1_raw);
    cudaGetSymbolAddress((void**)&p_st1, g_state1);
    cudaGetSymbolAddress((void**)&p_Wh, g_Wh);
    cudaGetSymbolAddress((void**)&p_Wl, g_Wl);
    cudaGetSymbolAddress((void**)&p_Wth, g_Wth);
    cudaGetSymbolAddress((void**)&p_Wtl, g_Wtl);
    cudaGetSymbolAddress((void**)&p_Wpsh, g_Wpsh);
    cudaGetSymbolAddress((void**)&p_Wpsl, g_Wpsl);
    cudaGetSymbolAddress((void**)&p_Wpth, g_Wpth);
    cudaGetSymbolAddress((void**)&p_Wptl, g_Wptl);
    cudaGetSymbolAddress((void**)&p_bt2, g_bt2);
    cudaGetSymbolAddress((void**)&p_bqt, g_bqt);
    cudaGetSymbolAddress((void**)&p_pt2h, g_pt2_h);
    cudaGetSymbolAddress((void**)&p_pt2l, g_pt2_l);
    cudaGetSymbolAddress((void**)&p_psh, g_ps_h);
    cudaGetSymbolAddress((void**)&p_psl, g_ps_l);

    const int SC_SMEM = 4 * 128 * 72 * 4;  // 147456 bytes
    cudaFuncSetAttribute(scores_tc_kernel,
                         cudaFuncAttributeMaxDynamicSharedMemorySize, SC_SMEM);
    cudaFuncSetAttribute(gemm_tc_proj,
                         cudaFuncAttributeMaxDynamicSharedMemorySize, PS_SMEM_BYTES);
    cudaFuncSetAttribute(prop16_kernel,
                         cudaFuncAttributeMaxDynamicSharedMemorySize, PR_SMEM_BYTES);

    // fused prologue
    prep_kernel<<<322, 256>>>(init_val, init_state, rUs_w, rUt_w, rUt_b, r_w,
                              pUs_w, pUt_w, pUt_b, p_w, ln_g, ln_b);
    // fused TC projection: [0,256) -> ps (split out); [256,258) -> pt2 (split out)
    gemm_tc_proj<<<(Bb * Ss) / 128 + Mm / 128, 256, PS_SMEM_BYTES>>>(
        (Bb * Ss) / 128,
        token_val, rUs_b, p_Wh, p_Wl, p_psh, p_psl, nullptr,
        p_mv0, p_bt2, p_Wth, p_Wtl, p_pt2h, p_pt2l, nullptr);
    // scores = pt2 . ps  (pure MMA from pre-split tiles)
    scores_tc_kernel<<<dim3(Ss / 128, Mm / 128, Bb), 256, SC_SMEM>>>();
    // write phase: warp-local topk + edges + gather-add + LN; raw state update
    write_kernel<<<Bb * Mm, 256>>>(token_val, token_state, ln_g, ln_b);
    // state1 = signed_softmax_state(state1_raw)
    sss_kernel<<<Bb, 256>>>(p_st1raw, p_st1);
    // fused TC projection: [0,32) -> qt (raw); [32,64) -> qs2 (raw, rowscale = state1)
    gemm_tc_proj<<<(Bb * Mm) / 128 * 2, 256, PS_SMEM_BYTES>>>(
        (Bb * Mm) / 128,
        p_mv1, p_bqt, p_Wpth, p_Wptl, p_qt, nullptr, nullptr,
        p_mv1, pUs_b, p_Wpsh, p_Wpsl, p_qs2, nullptr, p_st1);
    // propagation (16 rows/block, warp-per-row) + final LN -> out
    prop16_kernel<<<(Bb * Mm) / 16, 256, PR_SMEM_BYTES>>>(out, ln_g, ln_b);
}

// round 15
// speedup vs baseline: 1.4186x; 1.0191x over previous
#include <cuda_runtime.h>
#include <math.h>
#include <stdint.h>

// Problem shapes (fixed by the dataset)
constexpr int Bb = 16;    // batch
constexpr int Ss = 2048;  // tokens
constexpr int Dd = 512;   // dim
constexpr int Mm = 256;   // memory slots
constexpr int Rr = 64;    // low rank
constexpr float EPS = 1e-5f;
constexpr float STATE_MASS = 4.0f;
constexpr float LRS = 0.1f;

typedef unsigned long long ull;

// ---------------- scratch (static device globals; no allocs) ----------------
__device__ float g_scores[(size_t)Bb * Mm * Ss];   // 33.5 MB (L2-resident) [b][m][s]
__device__ float g_ps_h[(size_t)Bb * Ss * Rr];     // ps split hi
__device__ float g_ps_l[(size_t)Bb * Ss * Rr];     // ps split lo
__device__ float g_mem_val0[(size_t)Mm * Dd];      // LN(init_val), batch-independent
__device__ float g_pt2_h[(size_t)Mm * Rr];         // pt2 split hi
__device__ float g_pt2_l[(size_t)Mm * Rr];         // pt2 split lo
__device__ float g_Wh[(size_t)Dd * Rr];            // rUs_w split hi
__device__ float g_Wl[(size_t)Dd * Rr];            // rUs_w split lo
__device__ float g_Wth[(size_t)Dd * Rr];           // (rUt_w * r_w * LRS) split hi
__device__ float g_Wtl[(size_t)Dd * Rr];           // (rUt_w * r_w * LRS) split lo
__device__ float g_Wpsh[(size_t)Dd * Rr];          // pUs_w split hi
__device__ float g_Wpsl[(size_t)Dd * Rr];          // pUs_w split lo
__device__ float g_Wpth[(size_t)Dd * Rr];          // (pUt_w * p_w * LRS) split hi
__device__ float g_Wptl[(size_t)Dd * Rr];          // (pUt_w * p_w * LRS) split lo
__device__ float g_bt2[Rr];                        // rUt_b * r_w * LRS
__device__ float g_bqt[Rr];                        // pUt_b * p_w * LRS
__device__ float g_mem_state0[Mm];                 // signed-softmax-state(init_state)
__device__ float g_mem_val1[(size_t)Bb * Mm * Dd]; // post-write, post-LN
__device__ float g_state1_raw[(size_t)Bb * Mm];
__device__ float g_qt[(size_t)Bb * Mm * Rr];       // (mem_val1@pUt + b) * p_w * 0.1
__device__ float g_qs2[(size_t)Bb * Mm * Rr];      // (mem_val1@pUs + b) * state1[b,j]

// ---------------- tf32 / cp.async helpers ----------------
__device__ __forceinline__ uint32_t f2tf32(float x) {
    uint32_t r;
    asm("cvt.rna.tf32.f32 %0, %1;" : "=r"(r) : "f"(x));
    return r;
}

__device__ __forceinline__ void cpa16(void* dst_smem, const void* src) {
    uint32_t d = (uint32_t)__cvta_generic_to_shared(dst_smem);
    asm volatile("cp.async.ca.shared.global [%0], [%1], 16;" :: "r"(d), "l"(src));
}
#define CP_COMMIT() asm volatile("cp.async.commit_group;")
#define CP_WAIT(n)  asm volatile("cp.async.wait_group %0;" :: "n"(n))

#define MMA_TF32(C, A, B0, B1)                                                  \
    asm volatile(                                                               \
        "mma.sync.aligned.m16n8k8.row.col.f32.tf32.tf32.f32 "                   \
        "{%0,%1,%2,%3}, {%4,%5,%6,%7}, {%8,%9}, {%0,%1,%2,%3};"                 \
        : "+f"((C)[0]), "+f"((C)[1]), "+f"((C)[2]), "+f"((C)[3])                \
        : "r"((A)[0]), "r"((A)[1]), "r"((A)[2]), "r"((A)[3]), "r"(B0), "r"(B1))

// ---------------- shared helpers ----------------
__device__ __forceinline__ void block_ln_512(float a0, float a1, float& mu, float& ri,
                                             float* swr) {
    float ps = a0 + a1;
    float pq = fmaf(a0, a0, a1 * a1);
#pragma unroll
    for (int off = 16; off; off >>= 1) {
        ps += __shfl_down_sync(0xffffffffu, ps, off);
        pq += __shfl_down_sync(0xffffffffu, pq, off);
    }
    int tid = threadIdx.x, wid = tid >> 5, lane = tid & 31;
    if (lane == 0) { swr[wid] = ps; swr[8 + wid] = pq; }
    __syncthreads();
    if (tid == 0) {
        float s = 0.f, q = 0.f;
#pragma unroll
        for (int i = 0; i < 8; i++) { s += swr[i]; q += swr[8 + i]; }
        float m = s * (1.0f / 512.0f);
        float v = q * (1.0f / 512.0f) - m * m;
        swr[16] = m;
        swr[17] = rsqrtf(v + EPS);
    }
    __syncthreads();
    mu = swr[16];
    ri = swr[17];
}

__device__ __forceinline__ void split2(float v, float& h, float& l) {
    h = __uint_as_float(f2tf32(v));
    l = __uint_as_float(f2tf32(v - h));
}

// ---------------- fused prologue kernel ----------------
__global__ __launch_bounds__(256) void prep_kernel(
    const float* __restrict__ init_val, const float* __restrict__ init_state,
    const float* __restrict__ rUs_w, const float* __restrict__ rUt_w,
    const float* __restrict__ rUt_b, const float* __restrict__ r_w,
    const float* __restrict__ pUs_w, const float* __restrict__ pUt_w,
    const float* __restrict__ pUt_b, const float* __restrict__ p_w,
    const float* __restrict__ ln_g, const float* __restrict__ ln_b) {
    __shared__ float swr[18];
    __shared__ float s_bc[2];
    int blk = blockIdx.x, tid = threadIdx.x;
    int wid = tid >> 5, lane = tid & 31;

    if (blk < 256) {
        const float* x = init_val + (size_t)blk * Dd;
        float a0 = x[tid], a1 = x[tid + 256];
        float mu, ri;
        block_ln_512(a0, a1, mu, ri, swr);
        float* o = g_mem_val0 + (size_t)blk * Dd;
        o[tid]       = (a0 - mu) * ri * ln_g[tid] + ln_b[tid];
        o[tid + 256] = (a1 - mu) * ri * ln_g[tid + 256] + ln_b[tid + 256];
    } else if (blk < 320) {
        int grp = (blk - 256) >> 4;        // 0: rUs, 1: rUt*r_w, 2: pUs, 3: pUt*p_w
        int base = ((blk - 256) & 15) * 2048 + tid * 8;
        const float* src = grp == 0 ? rUs_w : grp == 1 ? rUt_w : grp == 2 ? pUs_w : pUt_w;
        const float* sc  = grp == 1 ? r_w : grp == 3 ? p_w : nullptr;
        float* dh = grp == 0 ? g_Wh : grp == 1 ? g_Wth : grp == 2 ? g_Wpsh : g_Wpth;
        float* dl = grp == 0 ? g_Wl : grp == 1 ? g_Wtl : grp == 2 ? g_Wpsl : g_Wptl;
#pragma unroll
        for (int q = 0; q < 2; q++) {
            int i = base + 4 * q;
            float4 v = *(const float4*)&src[i];
            if (sc) {
                v.x *= sc[(i + 0) & 63] * LRS;
                v.y *= sc[(i + 1) & 63] * LRS;
                v.z *= sc[(i + 2) & 63] * LRS;
                v.w *= sc[(i + 3) & 63] * LRS;
            }
            float4 h, l;
            split2(v.x, h.x, l.x); split2(v.y, h.y, l.y);
            split2(v.z, h.z, l.z); split2(v.w, h.w, l.w);
            *(float4*)&dh[i] = h;
            *(float4*)&dl[i] = l;
        }
    } else if (blk == 320) {
        float v = init_state[tid];
        float a = fabsf(v);
        float m = a;
#pragma unroll
        for (int off = 16; off; off >>= 1) m = fmaxf(m, __shfl_down_sync(0xffffffffu, m, off));
        if (lane == 0) swr[wid] = m;
        __syncthreads();
        if (tid == 0) {
            float mm = swr[0];
#pragma unroll
            for (int i = 1; i < 8; i++) mm = fmaxf(mm, swr[i]);
            s_bc[0] = mm;
        }
        __syncthreads();
        float e = expf(a - s_bc[0]);
        float s = e;
#pragma unroll
        for (int off = 16; off; off >>= 1) s += __shfl_down_sync(0xffffffffu, s, off);
        __syncthreads();
        if (lane == 0) swr[wid] = s;
        __syncthreads();
        if (tid == 0) {
            float ss = 0.f;
#pragma unroll
            for (int i = 0; i < 8; i++) ss += swr[i];
            s_bc[1] = ss;
        }
        __syncthreads();
        float sgn = (v > 0.f) ? 1.f : ((v < 0.f) ? -1.f : 0.f);
        g_mem_state0[tid] = sgn * e / s_bc[1] * STATE_MASS;
    } else {
        if (tid < Rr) g_bt2[tid] = rUt_b[tid] * r_w[tid] * LRS;
        else if (tid < 2 * Rr) g_bqt[tid - Rr] = pUt_b[tid - Rr] * p_w[tid - Rr] * LRS;
    }
}

// ---------------- tensor-core projection GEMM (dual parameter set) ----------
// 4-stage cp.async pipeline, ONE __syncthreads per chunk, prefetch distance 3.
// Output mode per set: ol != nullptr -> split hi/lo to oh/ol.
//                      else raw fp32 to oh; rowscale: sraw!=nullptr -> block-local
//                      signed-softmax of sraw over this block's batch; else 1.
constexpr int PS_XOFF = 0;
constexpr int PS_WHOFF = 128 * 20;
constexpr int PS_WLOFF = 128 * 20 + 16 * 72;
constexpr int PS_STAGE = 128 * 20 + 2 * 16 * 72;  // floats per stage = 4864
constexpr int PS_SMEM_BYTES = 4 * PS_STAGE * 4;   // 77824

__global__ __launch_bounds__(256) void gemm_tc_proj(
    int split,
    const float* __restrict__ X0, const float* __restrict__ b0,
    const float* __restrict__ Wh0, const float* __restrict__ Wl0,
    float* __restrict__ oh0, float* __restrict__ ol0, const float* __restrict__ sraw0,
    const float* __restrict__ X1, const float* __restrict__ b1,
    const float* __restrict__ Wh1, const float* __restrict__ Wl1,
    float* __restrict__ oh1, float* __restrict__ ol1, const float* __restrict__ sraw1) {
    extern __shared__ __align__(16) float smp[];
    __shared__ float sstate[256];
    __shared__ float swr2[10];
    int tid = threadIdx.x, w = tid >> 5, lane = tid & 31;
    int g = lane >> 2, tg = lane & 3;
    int set = ((int)blockIdx.x >= split);
    int rowblk = set ? (int)blockIdx.x - split : (int)blockIdx.x;
    const float* X    = set ? X1 : X0;
    const float* bias = set ? b1 : b0;
    const float* Wh   = set ? Wh1 : Wh0;
    const float* Wl   = set ? Wl1 : Wl0;
    float* oh         = set ? oh1 : oh0;
    float* ol         = set ? ol1 : ol0;
    const float* sraw = set ? sraw1 : sraw0;
    int row0 = rowblk * 128;
    int wm = w >> 1, wn = w & 1;

    int lr = tid >> 2, lq = (tid & 3) * 4;
    int wk = tid >> 4, wc = (tid & 15) * 4;

    float acc[2][4][4];
#pragma unroll
    for (int mt = 0; mt < 2; mt++)
#pragma unroll
        for (int nt = 0; nt < 4; nt++)
#pragma unroll
            for (int c = 0; c < 4; c++) acc[mt][nt][c] = 0.f;

    // prologue: load chunks 0,1,2 into stages 0,1,2
#pragma unroll
    for (int pc = 0; pc < 3; pc++) {
        int k0 = pc * 16;
        float* st = smp + pc * PS_STAGE;
        cpa16(st + PS_XOFF + lr * 20 + lq,        &X[(size_t)(row0 + lr) * Dd + k0 + lq]);
        cpa16(st + PS_XOFF + (lr + 64) * 20 + lq, &X[(size_t)(row0 + lr + 64) * Dd + k0 + lq]);
        cpa16(st + PS_WHOFF + wk * 72 + wc,       &Wh[(size_t)(k0 + wk) * Rr + wc]);
        cpa16(st + PS_WLOFF + wk * 72 + wc,       &Wl[(size_t)(k0 + wk) * Rr + wc]);
        CP_COMMIT();
    }

    // block-local signed softmax of state1_raw for this block's batch (qs2 rowscale)
    if (sraw) {
        int b = row0 >> 8;
        float v = sraw[b * Mm + tid];
        float a = fabsf(v);
        float m = a;
#pragma unroll
        for (int off = 16; off; off >>= 1) m = fmaxf(m, __shfl_down_sync(0xffffffffu, m, off));
        if (lane == 0) swr2[w] = m;
        __syncthreads();
        if (tid == 0) {
            float mm = swr2[0];
#pragma unroll
            for (int i = 1; i < 8; i++) mm = fmaxf(mm, swr2[i]);
            swr2[8] = mm;
        }
        __syncthreads();
        float e = expf(a - swr2[8]);
        float s = e;
#pragma unroll
        for (int off = 16; off; off >>= 1) s += __shfl_down_sync(0xffffffffu, s, off);
        __syncthreads();
        if (lane == 0) swr2[w] = s;
        __syncthreads();
        if (tid == 0) {
            float ss = 0.f;
#pragma unroll
            for (int i = 0; i < 8; i++) ss += swr2[i];
            swr2[9] = ss;
        }
        __syncthreads();
        float sgn = (v > 0.f) ? 1.f : ((v < 0.f) ? -1.f : 0.f);
        sstate[tid] = sgn * e / swr2[9] * STATE_MASS;
    }

    for (int c = 0; c < 32; c++) {
        CP_WAIT(2);
        __syncthreads();  // single barrier per chunk
        float* st = smp + (c & 3) * PS_STAGE;
        float* sx = st + PS_XOFF;
        float* swh = st + PS_WHOFF;
        float* swl = st + PS_WLOFF;
#pragma unroll
        for (int ks = 0; ks < 2; ks++) {
            int kk = ks * 8;
            uint32_t ah[2][4], al[2][4];
#pragma unroll
            for (int mt = 0; mt < 2; mt++) {
                int r = wm * 32 + mt * 16;
                float x0 = sx[(r + g) * 20 + kk + tg];
                float x1 = sx[(r + g + 8) * 20 + kk + tg];
                float x2 = sx[(r + g) * 20 + kk + tg + 4];
                float x3 = sx[(r + g + 8) * 20 + kk + tg + 4];
                ah[mt][0] = f2tf32(x0); al[mt][0] = f2tf32(x0 - __uint_as_float(ah[mt][0]));
                ah[mt][1] = f2tf32(x1); al[mt][1] = f2tf32(x1 - __uint_as_float(ah[mt][1]));
                ah[mt][2] = f2tf32(x2); al[mt][2] = f2tf32(x2 - __uint_as_float(ah[mt][2]));
                ah[mt][3] = f2tf32(x3); al[mt][3] = f2tf32(x3 - __uint_as_float(ah[mt][3]));
            }
#pragma unroll
            for (int nt = 0; nt < 4; nt++) {
                int cc = wn * 32 + nt * 8 + g;
                uint32_t bh0 = __float_as_uint(swh[(kk + tg) * 72 + cc]);
                uint32_t bh1 = __float_as_uint(swh[(kk + tg + 4) * 72 + cc]);
                uint32_t bl0 = __float_as_uint(swl[(kk + tg) * 72 + cc]);
                uint32_t bl1 = __float_as_uint(swl[(kk + tg + 4) * 72 + cc]);
#pragma unroll
                for (int mt = 0; mt < 2; mt++) {
                    MMA_TF32(acc[mt][nt], ah[mt], bh0, bh1);
                    MMA_TF32(acc[mt][nt], ah[mt], bl0, bl1);
                    MMA_TF32(acc[mt][nt], al[mt], bh0, bh1);
                }
            }
        }
        int nc = c + 3;
        if (nc < 32) {
            int k0 = nc * 16;
            float* s2 = smp + (nc & 3) * PS_STAGE;
            cpa16(s2 + PS_XOFF + lr * 20 + lq,        &X[(size_t)(row0 + lr) * Dd + k0 + lq]);
            cpa16(s2 + PS_XOFF + (lr + 64) * 20 + lq, &X[(size_t)(row0 + lr + 64) * Dd + k0 + lq]);
            cpa16(s2 + PS_WHOFF + wk * 72 + wc,       &Wh[(size_t)(k0 + wk) * Rr + wc]);
            cpa16(s2 + PS_WLOFF + wk * 72 + wc,       &Wl[(size_t)(k0 + wk) * Rr + wc]);
        }
        CP_COMMIT();
    }

#pragma unroll
    for (int mt = 0; mt < 2; mt++) {
        int r = row0 + wm * 32 + mt * 16 + g;
#pragma unroll
        for (int nt = 0; nt < 4; nt++) {
            int c = wn * 32 + nt * 8 + 2 * tg;
            float b0v = bias[c], b1v = bias[c + 1];
            float v00 = acc[mt][nt][0] + b0v, v01 = acc[mt][nt][1] + b1v;
            float v10 = acc[mt][nt][2] + b0v, v11 = acc[mt][nt][3] + b1v;
            if (ol) {
                float h00 = __uint_as_float(f2tf32(v00));
                float h01 = __uint_as_float(f2tf32(v01));
                float h10 = __uint_as_float(f2tf32(v10));
                float h11 = __uint_as_float(f2tf32(v11));
                *(float2*)&oh[(size_t)r * Rr + c]       = make_float2(h00, h01);
                *(float2*)&oh[(size_t)(r + 8) * Rr + c] = make_float2(h10, h11);
                *(float2*)&ol[(size_t)r * Rr + c] = make_float2(
                    __uint_as_float(f2tf32(v00 - h00)), __uint_as_float(f2tf32(v01 - h01)));
                *(float2*)&ol[(size_t)(r + 8) * Rr + c] = make_float2(
                    __uint_as_float(f2tf32(v10 - h10)), __uint_as_float(f2tf32(v11 - h11)));
            } else {
                float r0s = sraw ? sstate[r & 255] : 1.f;
                float r1s = sraw ? sstate[(r + 8) & 255] : 1.f;
                *(float2*)&oh[(size_t)r * Rr + c]       = make_float2(v00 * r0s, v01 * r0s);
                *(float2*)&oh[(size_t)(r + 8) * Rr + c] = make_float2(v10 * r1s, v11 * r1s);
            }
        }
    }
}

// ---------------- tensor-core scores GEMM: pure MMA from pre-split tiles ----------
__global__ __launch_bounds__(256) void scores_tc_kernel() {
    extern __shared__ __align__(16) float smc[];
    float (*sah)[72] = (float(*)[72])smc;
    float (*sal)[72] = (float(*)[72])(smc + 128 * 72);
    float (*sbh)[72] = (float(*)[72])(smc + 2 * 128 * 72);
    float (*sbl)[72] = (float(*)[72])(smc + 3 * 128 * 72);
    int tid = threadIdx.x, w = tid >> 5, lane = tid & 31;
    int g = lane >> 2, tg = lane & 3;
    int b = blockIdx.z;
    int m0 = blockIdx.y * 128;
    int s0 = blockIdx.x * 128;
    int wm = w >> 1, wn = w & 1;

#pragma unroll
    for (int t = 0; t < 8; t++) {
        int f = tid + 256 * t;
        int r = f >> 4, q = (f & 15) * 4;
        cpa16(&sah[r][q], &g_pt2_h[(size_t)(m0 + r) * Rr + q]);
        cpa16(&sal[r][q], &g_pt2_l[(size_t)(m0 + r) * Rr + q]);
        cpa16(&sbh[r][q], &g_ps_h[((size_t)b * Ss + s0 + r) * Rr + q]);
        cpa16(&sbl[r][q], &g_ps_l[((size_t)b * Ss + s0 + r) * Rr + q]);
    }
    CP_COMMIT();

    float acc[2][8][4];
#pragma unroll
    for (int mt = 0; mt < 2; mt++)
#pragma unroll
        for (int nt = 0; nt < 8; nt++)
#pragma unroll
            for (int c = 0; c < 4; c++) acc[mt][nt][c] = 0.f;

    CP_WAIT(0);
    __syncthreads();

#pragma unroll
    for (int ks = 0; ks < 8; ks++) {
        int kk = ks * 8;
        uint32_t ah[2][4], al[2][4];
#pragma unroll
        for (int mt = 0; mt < 2; mt++) {
            int r = wm * 32 + mt * 16;
            ah[mt][0] = __float_as_uint(sah[r + g][kk + tg]);
            ah[mt][1] = __float_as_uint(sah[r + g + 8][kk + tg]);
            ah[mt][2] = __float_as_uint(sah[r + g][kk + tg + 4]);
            ah[mt][3] = __float_as_uint(sah[r + g + 8][kk + tg + 4]);
            al[mt][0] = __float_as_uint(sal[r + g][kk + tg]);
            al[mt][1] = __float_as_uint(sal[r + g + 8][kk + tg]);
            al[mt][2] = __float_as_uint(sal[r + g][kk + tg + 4]);
            al[mt][3] = __float_as_uint(sal[r + g + 8][kk + tg + 4]);
        }
#pragma unroll
        for (int nt = 0; nt < 8; nt++) {
            int cc = wn * 64 + nt * 8 + g;
            uint32_t bh0 = __float_as_uint(sbh[cc][kk + tg]);
            uint32_t bh1 = __float_as_uint(sbh[cc][kk + tg + 4]);
            uint32_t bl0 = __float_as_uint(sbl[cc][kk + tg]);
            uint32_t bl1 = __float_as_uint(sbl[cc][kk + tg + 4]);
#pragma unroll
            for (int mt = 0; mt < 2; mt++) {
                MMA_TF32(acc[mt][nt], ah[mt], bh0, bh1);
                MMA_TF32(acc[mt][nt], ah[mt], bl0, bl1);
                MMA_TF32(acc[mt][nt], al[mt], bh0, bh1);
            }
        }
    }

#pragma unroll
    for (int mt = 0; mt < 2; mt++) {
        int m = m0 + wm * 32 + mt * 16 + g;
#pragma unroll
        for (int nt = 0; nt < 8; nt++) {
            int s = s0 + wn * 64 + nt * 8 + 2 * tg;
            *(float2*)&g_scores[((size_t)(b * Mm + m)) * Ss + s] =
                make_float2(acc[mt][nt][0], acc[mt][nt][1]);
            *(float2*)&g_scores[((size_t)(b * Mm + m + 8)) * Ss + s] =
                make_float2(acc[mt][nt][2], acc[mt][nt][3]);
        }
    }
}

// ---------------- write phase: warp-local bisection + 128-key register sort ----------------
__global__ __launch_bounds__(256) void write_kernel(
    const float* __restrict__ token_val, const float* __restrict__ token_state,
    const float* __restrict__ ln_g, const float* __restrict__ ln_b) {
    int bm = blockIdx.x;
    int b = bm >> 8, m = bm & 255;
    int tid = threadIdx.x, w = tid >> 5, lane = tid & 31;
    __shared__ ull skeys[128];
    __shared__ ull wk[8][32];
    __shared__ float swr[18];
    __shared__ float s_edge[16];
    __shared__ int s_eidx[16];

    const float* row = g_scores + (size_t)bm * Ss;

    int base = w * 256 + lane;
    float aa[8];
#pragma unroll
    for (int j = 0; j < 8; j++) aa[j] = fabsf(row[base + 32 * j]);

    unsigned um = 0;
#pragma unroll
    for (int j = 0; j < 8; j++) um = max(um, __float_as_uint(aa[j]));
    um = __reduce_max_sync(0xffffffffu, um);
    float hi = __uint_as_float(um), lo = 0.f;
    int cl = 256;
    for (int it = 0; it < 32 && cl > 32; it++) {
        float mid = 0.5f * (lo + hi);
        int c = 0;
#pragma unroll
        for (int j = 0; j < 8; j++) c += (aa[j] > mid);
        c = (int)__reduce_add_sync(0xffffffffu, (unsigned)c);
        if (c >= 16) { lo = mid; cl = c; } else { hi = mid; }
    }

    wk[w][lane] = 0ull;
    __syncwarp();
    int bc = 0;
#pragma unroll
    for (int j = 0; j < 8; j++) {
        bool p = aa[j] > lo;
        unsigned msk = __ballot_sync(0xffffffffu, p);
        if (p) {
            int pos = bc + __popc(msk & ((1u << lane) - 1));
            if (pos < 32)
                wk[w][pos] = ((ull)__float_as_uint(aa[j]) << 32) | (unsigned)(~(base + 32 * j));
        }
        bc += __popc(msk);
    }
    __syncwarp();

    ull key = wk[w][lane];
#pragma unroll
    for (int k = 2; k <= 32; k <<= 1) {
#pragma unroll
        for (int j = k >> 1; j; j >>= 1) {
            ull other = __shfl_xor_sync(0xffffffffu, key, j);
            bool takeMax = ((lane & k) == 0) != ((lane & j) != 0);
            ull mx = key > other ? key : other;
            ull mn = key > other ? other : key;
            key = takeMax ? mx : mn;
        }
    }
    if (lane < 16) skeys[w * 16 + lane] = key;
    __syncthreads();

    if (w == 0) {
        ull v[4];
#pragma unroll
        for (int s = 0; s < 4; s++) v[s] = skeys[lane + 32 * s];
#pragma unroll
        for (int k = 2; k <= 128; k <<= 1) {
#pragma unroll
            for (int j = k >> 1; j; j >>= 1) {
                if (j >= 32) {
                    int d = j >> 5;
#pragma unroll
                    for (int s = 0; s < 4; s++) {
                        int p = s ^ d;
                        if (p > s) {
                            int e = lane + 32 * s;
                            bool desc = ((e & k) == 0);
                            bool sw2 = desc ? (v[s] < v[p]) : (v[s] > v[p]);
                            if (sw2) { ull t = v[s]; v[s] = v[p]; v[p] = t; }
                        }
                    }
                } else {
#pragma unroll
                    for (int s = 0; s < 4; s++) {
                        ull other = __shfl_xor_sync(0xffffffffu, v[s], j);
                        int e = lane + 32 * s;
                        bool takeMax = ((e & k) == 0) != ((lane & j) != 0);
                        ull mx = v[s] > other ? v[s] : other;
                        ull mn = v[s] > other ? other : v[s];
                        v[s] = takeMax ? mx : mn;
                    }
                }
            }
        }
        bool valid = lane < 16;
        ull kk2 = v[0];
        float a = __uint_as_float((unsigned)(kk2 >> 32));
        int idx = (int)(~(unsigned)kk2);
        float maxa = __shfl_sync(0xffffffffu, a, 0);
        float sel = valid ? row[idx] : 0.f;
        float e = valid ? expf(a - maxa) : 0.f;
        float sum = e;
#pragma unroll
        for (int off = 8; off; off >>= 1) sum += __shfl_xor_sync(0xffffffffu, sum, off, 16);
        float sgn = (sel > 0.f) ? 1.f : ((sel < 0.f) ? -1.f : 0.f);
        float edge = sgn * e / sum;
        if (valid) { s_edge[lane] = edge; s_eidx[lane] = idx; }
        float c = valid ? edge * token_state[(size_t)b * Ss + idx] : 0.f;
#pragma unroll
        for (int off = 8; off; off >>= 1) c += __shfl_xor_sync(0xffffffffu, c, off, 16);
        if (lane == 0) g_state1_raw[bm] = g_mem_state0[m] + c;
    }
    __syncthreads();

    int d = tid;
    float a0 = g_mem_val0[(size_t)m * Dd + d];
    float a1 = g_mem_val0[(size_t)m * Dd + d + 256];
#pragma unroll
    for (int k = 0; k < 16; k++) {
        const float* tv = token_val + ((size_t)b * Ss + s_eidx[k]) * Dd;
        float ek = s_edge[k];
        a0 = fmaf(ek, tv[d], a0);
        a1 = fmaf(ek, tv[d + 256], a1);
    }
    float mu, ri;
    block_ln_512(a0, a1, mu, ri, swr);
    float* o = g_mem_val1 + (size_t)bm * Dd;
    o[d]       = (a0 - mu) * ri * ln_g[d] + ln_b[d];
    o[d + 256] = (a1 - mu) * ri * ln_g[d + 256] + ln_b[d + 256];
}

// ---------------- propagation: 16 rows/block, one-shot staging, warp-per-row ----------------
constexpr int PR_QS = 0;
constexpr int PR_QT = 256 * 68;
constexpr int PR_PR = 256 * 68 + 16 * 68;
constexpr int PR_SMEM_BYTES = (256 * 68 + 16 * 68 + 16 * 256) * 4;  // 90368

__global__ __launch_bounds__(256) void prop16_kernel(
    float* __restrict__ out_final, const float* __restrict__ ln_g,
    const float* __restrict__ ln_b) {
    extern __shared__ __align__(16) float smq[];
    float (*sqs)[68]  = (float(*)[68])(smq + PR_QS);
    float (*s_qt)[68] = (float(*)[68])(smq + PR_QT);
    float (*prow)[256] = (float(*)[256])(smq + PR_PR);
    __shared__ ull wkeys[8][32];
    __shared__ float s_edge[16][16];
    __shared__ int s_eidx[16][16];

    int b = blockIdx.x >> 4;
    int i0 = (blockIdx.x & 15) * 16;
    int tid = threadIdx.x, w = tid >> 5, lane = tid & 31;

    {
        int r = tid >> 4, q = (tid & 15) * 4;
        cpa16(&s_qt[r][q], &g_qt[((size_t)(b * Mm + i0 + r)) * Rr + q]);
    }
#pragma unroll
    for (int t = 0; t < 16; t++) {
        int f = tid + 256 * t;
        int r = f >> 4, q = (f & 15) * 4;
        cpa16(&sqs[r][q], &g_qs2[((size_t)(b * Mm + r)) * Rr + q]);
    }
    CP_COMMIT();
    CP_WAIT(0);
    __syncthreads();  // the only block-wide sync

#pragma unroll
    for (int rr = 0; rr < 2; rr++) {
        int row = 2 * w + rr;

        float pv[8];
#pragma unroll
        for (int jb = 0; jb < 8; jb++) {
            int j = jb * 32 + lane;
            float acc = 0.f;
#pragma unroll
            for (int k4 = 0; k4 < Rr; k4 += 4) {
                float4 qv = *(const float4*)&sqs[j][k4];
                float4 tv = *(const float4*)&s_qt[row][k4];
                acc = fmaf(qv.x, tv.x, fmaf(qv.y, tv.y, fmaf(qv.z, tv.z, fmaf(qv.w, tv.w, acc))));
            }
            pv[jb] = acc;
            prow[row][j] = acc;
        }
        __syncwarp();

        float av[8];
#pragma unroll
        for (int r2 = 0; r2 < 8; r2++) av[r2] = fabsf(pv[r2]);
        unsigned um = 0;
#pragma unroll
        for (int r2 = 0; r2 < 8; r2++) um = max(um, __float_as_uint(av[r2]));
        um = __reduce_max_sync(0xffffffffu, um);
        float hi = __uint_as_float(um), lo = 0.f;
        int cl = 256;
        for (int it = 0; it < 32 && cl > 32; it++) {
            float mid = 0.5f * (lo + hi);
            int c = 0;
#pragma unroll
            for (int r2 = 0; r2 < 8; r2++) c += (av[r2] > mid);
            c = (int)__reduce_add_sync(0xffffffffu, (unsigned)c);
            if (c >= 16) { lo = mid; cl = c; } else { hi = mid; }
        }

        wkeys[w][lane] = 0ull;
        __syncwarp();
        int base = 0;
#pragma unroll
        for (int r2 = 0; r2 < 8; r2++) {
            bool p = av[r2] > lo;
            unsigned msk = __ballot_sync(0xffffffffu, p);
            if (p) {
                int pos = base + __popc(msk & ((1u << lane) - 1));
                if (pos < 32)
                    wkeys[w][pos] =
                        ((ull)__float_as_uint(av[r2]) << 32) | (unsigned)(~(r2 * 32 + lane));
            }
            base += __popc(msk);
        }
        __syncwarp();

        ull key = wkeys[w][lane];
#pragma unroll
        for (int k = 2; k <= 32; k <<= 1) {
#pragma unroll
            for (int j = k >> 1; j; j >>= 1) {
                ull other = __shfl_xor_sync(0xffffffffu, key, j);
                bool takeMax = ((lane & k) == 0) != ((lane & j) != 0);
                ull mx2 = key > other ? key : other;
                ull mn2 = key > other ? other : key;
                key = takeMax ? mx2 : mn2;
            }
        }

        bool valid = lane < 16;
        float a = __uint_as_float((unsigned)(key >> 32));
        int idx = (int)(~(unsigned)key);
        float maxa = __shfl_sync(0xffffffffu, a, 0);
        float sel = valid ? prow[row][idx] : 0.f;
        float e = valid ? expf(a - maxa) : 0.f;
        float sum = e;
#pragma unroll
        for (int off = 8; off; off >>= 1) sum += __shfl_xor_sync(0xffffffffu, sum, off, 16);
        float sgn = (sel > 0.f) ? 1.f : ((sel < 0.f) ? -1.f : 0.f);
        float edge = sgn * e / sum;
        if (valid) { s_edge[row][lane] = edge; s_eidx[row][lane] = idx; }
        __syncwarp();

        int bi = b * Mm + i0 + row;
        float4 acc4[4];
#pragma unroll
        for (int q = 0; q < 4; q++)
            acc4[q] = *(const float4*)&g_mem_val1[(size_t)bi * Dd + (q * 32 + lane) * 4];
#pragma unroll
        for (int k = 0; k < 16; k++) {
            float ek = s_edge[row][k];
            const float* mv = g_mem_val1 + ((size_t)(b * Mm + s_eidx[row][k])) * Dd;
#pragma unroll
            for (int q = 0; q < 4; q++) {
                float4 v = *(const float4*)&mv[(q * 32 + lane) * 4];
                acc4[q].x = fmaf(ek, v.x, acc4[q].x);
                acc4[q].y = fmaf(ek, v.y, acc4[q].y);
                acc4[q].z = fmaf(ek, v.z, acc4[q].z);
                acc4[q].w = fmaf(ek, v.w, acc4[q].w);
            }
        }
        float s = 0.f, sq = 0.f;
#pragma unroll
        for (int q = 0; q < 4; q++) {
            s += acc4[q].x + acc4[q].y + acc4[q].z + acc4[q].w;
            sq = fmaf(acc4[q].x, acc4[q].x, sq);
            sq = fmaf(acc4[q].y, acc4[q].y, sq);
            sq = fmaf(acc4[q].z, acc4[q].z, sq);
            sq = fmaf(acc4[q].w, acc4[q].w, sq);
        }
#pragma unroll
        for (int off = 16; off; off >>= 1) {
            s += __shfl_down_sync(0xffffffffu, s, off);
            sq += __shfl_down_sync(0xffffffffu, sq, off);
        }
        s = __shfl_sync(0xffffffffu, s, 0);
        sq = __shfl_sync(0xffffffffu, sq, 0);
        float mu = s * (1.0f / 512.0f);
        float ri = rsqrtf(sq * (1.0f / 512.0f) - mu * mu + EPS);
#pragma unroll
        for (int q = 0; q < 4; q++) {
            int d4 = (q * 32 + lane) * 4;
            float4 gv = *(const float4*)&ln_g[d4];
            float4 bv = *(const float4*)&ln_b[d4];
            float4 o;
            o.x = (acc4[q].x - mu) * ri * gv.x + bv.x;
            o.y = (acc4[q].y - mu) * ri * gv.y + bv.y;
            o.z = (acc4[q].z - mu) * ri * gv.z + bv.z;
            o.w = (acc4[q].w - mu) * ri * gv.w + bv.w;
            *(float4*)&out_final[(size_t)bi * Dd + d4] = o;
        }
    }
}

// ---------------- host launch ----------------
extern "C" void kernel_launch(void* const* d_in, const int* in_sizes, int n_in,
                              void* d_out, int out_size) {
    (void)in_sizes; (void)n_in; (void)out_size;
    const float* token_val   = (const float*)d_in[0];
    const float* token_state = (const float*)d_in[1];
    const float* init_state  = (const float*)d_in[2];
    const float* init_val    = (const float*)d_in[3];
    const float* rUs_w = (const float*)d_in[4];
    const float* rUs_b = (const float*)d_in[5];
    const float* rUt_w = (const float*)d_in[6];
    const float* rUt_b = (const float*)d_in[7];
    const float* r_w   = (const float*)d_in[8];
    const float* pUs_w = (const float*)d_in[9];
    const float* pUs_b = (const float*)d_in[10];
    const float* pUt_w = (const float*)d_in[11];
    const float* pUt_b = (const float*)d_in[12];
    const float* p_w   = (const float*)d_in[13];
    const float* ln_g  = (const float*)d_in[14];
    const float* ln_b  = (const float*)d_in[15];
    float* out = (float*)d_out;

    float *p_mv0, *p_mv1, *p_qt, *p_qs2, *p_st1raw;
    float *p_Wh, *p_Wl, *p_Wth, *p_Wtl, *p_Wpsh, *p_Wpsl, *p_Wpth, *p_Wptl;
    float *p_bt2, *p_bqt, *p_pt2h, *p_pt2l, *p_psh, *p_psl;
    cudaGetSymbolAddress((void**)&p_mv0, g_mem_val0);
    cudaGetSymbolAddress((void**)&p_mv1, g_mem_val1);
    cudaGetSymbolAddress((void**)&p_qt, g_qt);
    cudaGetSymbolAddress((void**)&p_qs2, g_qs2);
    cudaGetSymbolAddress((void**)&p_st1raw, g_state1_raw);
    cudaGetSymbolAddress((void**)&p_Wh, g_Wh);
    cudaGetSymbolAddress((void**)&p_Wl, g_Wl);
    cudaGetSymbolAddress((void**)&p_Wth, g_Wth);
    cudaGetSymbolAddress((void**)&p_Wtl, g_Wtl);
    cudaGetSymbolAddress((void**)&p_Wpsh, g_Wpsh);
    cudaGetSymbolAddress((void**)&p_Wpsl, g_Wpsl);
    cudaGetSymbolAddress((void**)&p_Wpth, g_Wpth);
    cudaGetSymbolAddress((void**)&p_Wptl, g_Wptl);
    cudaGetSymbolAddress((void**)&p_bt2, g_bt2);
    cudaGetSymbolAddress((void**)&p_bqt, g_bqt);
    cudaGetSymbolAddress((void**)&p_pt2h, g_pt2_h);
    cudaGetSymbolAddress((void**)&p_pt2l, g_pt2_l);
    cudaGetSymbolAddress((void**)&p_psh, g_ps_h);
    cudaGetSymbolAddress((void**)&p_psl, g_ps_l);

    const int SC_SMEM = 4 * 128 * 72 * 4;  // 147456 bytes
    cudaFuncSetAttribute(scores_tc_kernel,
                         cudaFuncAttributeMaxDynamicSharedMemorySize, SC_SMEM);
    cudaFuncSetAttribute(gemm_tc_proj,
                         cudaFuncAttributeMaxDynamicSharedMemorySize, PS_SMEM_BYTES);
    cudaFuncSetAttribute(prop16_kernel,
                         cudaFuncAttributeMaxDynamicSharedMemorySize, PR_SMEM_BYTES);

    // fused prologue
    prep_kernel<<<322, 256>>>(init_val, init_state, rUs_w, rUt_w, rUt_b, r_w,
                              pUs_w, pUt_w, pUt_b, p_w, ln_g, ln_b);
    // fused TC projection: [0,256) -> ps (split out); [256,258) -> pt2 (split out)
    gemm_tc_proj<<<(Bb * Ss) / 128 + Mm / 128, 256, PS_SMEM_BYTES>>>(
        (Bb * Ss) / 128,
        token_val, rUs_b, p_Wh, p_Wl, p_psh, p_psl, nullptr,
        p_mv0, p_bt2, p_Wth, p_Wtl, p_pt2h, p_pt2l, nullptr);
    // scores = pt2 . ps  (pure MMA from pre-split tiles)
    scores_tc_kernel<<<dim3(Ss / 128, Mm / 128, Bb), 256, SC_SMEM>>>();
    // write phase: warp-local topk + edges + gather-add + LN; raw state update
    write_kernel<<<Bb * Mm, 256>>>(token_val, token_state, ln_g, ln_b);
    // fused TC projection: [0,32) -> qt (raw); [32,64) -> qs2 (raw, rowscale =
    // block-local signed-softmax of state1_raw — replaces the sss launch)
    gemm_tc_proj<<<(Bb * Mm) / 128 * 2, 256, PS_SMEM_BYTES>>>(
        (Bb * Mm) / 128,
        p_mv1, p_bqt, p_Wpth, p_Wptl, p_qt, nullptr, nullptr,
        p_mv1, pUs_b, p_Wpsh, p_Wpsl, p_qs2, nullptr, p_st1raw);
    // propagation (16 rows/block, warp-per-row) + final LN -> out
    prop16_kernel<<<(Bb * Mm) / 16, 256, PR_SMEM_BYTES>>>(out, ln_g, ln_b);
}

// round 16
// speedup vs baseline: 1.4191x; 1.0004x over previous
#include <cuda_runtime.h>
#include <math.h>
#include <stdint.h>

// Problem shapes (fixed by the dataset)
constexpr int Bb = 16;    // batch
constexpr int Ss = 2048;  // tokens
constexpr int Dd = 512;   // dim
constexpr int Mm = 256;   // memory slots
constexpr int Rr = 64;    // low rank
constexpr float EPS = 1e-5f;
constexpr float STATE_MASS = 4.0f;
constexpr float LRS = 0.1f;

typedef unsigned long long ull;

// ---------------- scratch (static device globals; no allocs) ----------------
__device__ float g_scores[(size_t)Bb * Mm * Ss];   // 33.5 MB (L2-resident) [b][m][s]
__device__ float g_ps_h[(size_t)Bb * Ss * Rr];     // ps split hi
__device__ float g_ps_l[(size_t)Bb * Ss * Rr];     // ps split lo
__device__ float g_mem_val0[(size_t)Mm * Dd];      // LN(init_val), batch-independent
__device__ float g_pt2_h[(size_t)Mm * Rr];         // pt2 split hi
__device__ float g_pt2_l[(size_t)Mm * Rr];         // pt2 split lo
__device__ float g_Wh[(size_t)Dd * Rr];            // rUs_w split hi
__device__ float g_Wl[(size_t)Dd * Rr];            // rUs_w split lo
__device__ float g_Wth[(size_t)Dd * Rr];           // (rUt_w * r_w * LRS) split hi
__device__ float g_Wtl[(size_t)Dd * Rr];           // (rUt_w * r_w * LRS) split lo
__device__ float g_Wpsh[(size_t)Dd * Rr];          // pUs_w split hi
__device__ float g_Wpsl[(size_t)Dd * Rr];          // pUs_w split lo
__device__ float g_Wpth[(size_t)Dd * Rr];          // (pUt_w * p_w * LRS) split hi
__device__ float g_Wptl[(size_t)Dd * Rr];          // (pUt_w * p_w * LRS) split lo
__device__ float g_bt2[Rr];                        // rUt_b * r_w * LRS
__device__ float g_bqt[Rr];                        // pUt_b * p_w * LRS
__device__ float g_mem_state0[Mm];                 // signed-softmax-state(init_state)
__device__ float g_mem_val1[(size_t)Bb * Mm * Dd]; // post-write, post-LN
__device__ float g_state1_raw[(size_t)Bb * Mm];
__device__ float g_qt[(size_t)Bb * Mm * Rr];       // (mem_val1@pUt + b) * p_w * 0.1
__device__ float g_qs2[(size_t)Bb * Mm * Rr];      // (mem_val1@pUs + b) * state1[b,j]

// ---------------- tf32 / cp.async helpers ----------------
__device__ __forceinline__ uint32_t f2tf32(float x) {
    uint32_t r;
    asm("cvt.rna.tf32.f32 %0, %1;" : "=r"(r) : "f"(x));
    return r;
}

__device__ __forceinline__ void cpa16(void* dst_smem, const void* src) {
    uint32_t d = (uint32_t)__cvta_generic_to_shared(dst_smem);
    asm volatile("cp.async.ca.shared.global [%0], [%1], 16;" :: "r"(d), "l"(src));
}
#define CP_COMMIT() asm volatile("cp.async.commit_group;")
#define CP_WAIT(n)  asm volatile("cp.async.wait_group %0;" :: "n"(n))

#define MMA_TF32(C, A, B0, B1)                                                  \
    asm volatile(                                                               \
        "mma.sync.aligned.m16n8k8.row.col.f32.tf32.tf32.f32 "                   \
        "{%0,%1,%2,%3}, {%4,%5,%6,%7}, {%8,%9}, {%0,%1,%2,%3};"                 \
        : "+f"((C)[0]), "+f"((C)[1]), "+f"((C)[2]), "+f"((C)[3])                \
        : "r"((A)[0]), "r"((A)[1]), "r"((A)[2]), "r"((A)[3]), "r"(B0), "r"(B1))

// ---------------- shared helpers ----------------
__device__ __forceinline__ void block_ln_512(float a0, float a1, float& mu, float& ri,
                                             float* swr) {
    float ps = a0 + a1;
    float pq = fmaf(a0, a0, a1 * a1);
#pragma unroll
    for (int off = 16; off; off >>= 1) {
        ps += __shfl_down_sync(0xffffffffu, ps, off);
        pq += __shfl_down_sync(0xffffffffu, pq, off);
    }
    int tid = threadIdx.x, wid = tid >> 5, lane = tid & 31;
    if (lane == 0) { swr[wid] = ps; swr[8 + wid] = pq; }
    __syncthreads();
    if (tid == 0) {
        float s = 0.f, q = 0.f;
#pragma unroll
        for (int i = 0; i < 8; i++) { s += swr[i]; q += swr[8 + i]; }
        float m = s * (1.0f / 512.0f);
        float v = q * (1.0f / 512.0f) - m * m;
        swr[16] = m;
        swr[17] = rsqrtf(v + EPS);
    }
    __syncthreads();
    mu = swr[16];
    ri = swr[17];
}

__device__ __forceinline__ void split2(float v, float& h, float& l) {
    h = __uint_as_float(f2tf32(v));
    l = __uint_as_float(f2tf32(v - h));
}

// ---------------- fused prologue kernel ----------------
__global__ __launch_bounds__(256) void prep_kernel(
    const float* __restrict__ init_val, const float* __restrict__ init_state,
    const float* __restrict__ rUs_w, const float* __restrict__ rUt_w,
    const float* __restrict__ rUt_b, const float* __restrict__ r_w,
    const float* __restrict__ pUs_w, const float* __restrict__ pUt_w,
    const float* __restrict__ pUt_b, const float* __restrict__ p_w,
    const float* __restrict__ ln_g, const float* __restrict__ ln_b) {
    __shared__ float swr[18];
    __shared__ float s_bc[2];
    int blk = blockIdx.x, tid = threadIdx.x;
    int wid = tid >> 5, lane = tid & 31;

    if (blk < 256) {
        const float* x = init_val + (size_t)blk * Dd;
        float a0 = x[tid], a1 = x[tid + 256];
        float mu, ri;
        block_ln_512(a0, a1, mu, ri, swr);
        float* o = g_mem_val0 + (size_t)blk * Dd;
        o[tid]       = (a0 - mu) * ri * ln_g[tid] + ln_b[tid];
        o[tid + 256] = (a1 - mu) * ri * ln_g[tid + 256] + ln_b[tid + 256];
    } else if (blk < 320) {
        int grp = (blk - 256) >> 4;        // 0: rUs, 1: rUt*r_w, 2: pUs, 3: pUt*p_w
        int base = ((blk - 256) & 15) * 2048 + tid * 8;
        const float* src = grp == 0 ? rUs_w : grp == 1 ? rUt_w : grp == 2 ? pUs_w : pUt_w;
        const float* sc  = grp == 1 ? r_w : grp == 3 ? p_w : nullptr;
        float* dh = grp == 0 ? g_Wh : grp == 1 ? g_Wth : grp == 2 ? g_Wpsh : g_Wpth;
        float* dl = grp == 0 ? g_Wl : grp == 1 ? g_Wtl : grp == 2 ? g_Wpsl : g_Wptl;
#pragma unroll
        for (int q = 0; q < 2; q++) {
            int i = base + 4 * q;
            float4 v = *(const float4*)&src[i];
            if (sc) {
                v.x *= sc[(i + 0) & 63] * LRS;
                v.y *= sc[(i + 1) & 63] * LRS;
                v.z *= sc[(i + 2) & 63] * LRS;
                v.w *= sc[(i + 3) & 63] * LRS;
            }
            float4 h, l;
            split2(v.x, h.x, l.x); split2(v.y, h.y, l.y);
            split2(v.z, h.z, l.z); split2(v.w, h.w, l.w);
            *(float4*)&dh[i] = h;
            *(float4*)&dl[i] = l;
        }
    } else if (blk == 320) {
        float v = init_state[tid];
        float a = fabsf(v);
        float m = a;
#pragma unroll
        for (int off = 16; off; off >>= 1) m = fmaxf(m, __shfl_down_sync(0xffffffffu, m, off));
        if (lane == 0) swr[wid] = m;
        __syncthreads();
        if (tid == 0) {
            float mm = swr[0];
#pragma unroll
            for (int i = 1; i < 8; i++) mm = fmaxf(mm, swr[i]);
            s_bc[0] = mm;
        }
        __syncthreads();
        float e = expf(a - s_bc[0]);
        float s = e;
#pragma unroll
        for (int off = 16; off; off >>= 1) s += __shfl_down_sync(0xffffffffu, s, off);
        __syncthreads();
        if (lane == 0) swr[wid] = s;
        __syncthreads();
        if (tid == 0) {
            float ss = 0.f;
#pragma unroll
            for (int i = 0; i < 8; i++) ss += swr[i];
            s_bc[1] = ss;
        }
        __syncthreads();
        float sgn = (v > 0.f) ? 1.f : ((v < 0.f) ? -1.f : 0.f);
        g_mem_state0[tid] = sgn * e / s_bc[1] * STATE_MASS;
    } else {
        if (tid < Rr) g_bt2[tid] = rUt_b[tid] * r_w[tid] * LRS;
        else if (tid < 2 * Rr) g_bqt[tid - Rr] = pUt_b[tid - Rr] * p_w[tid - Rr] * LRS;
    }
}

// ---------------- tensor-core projection GEMM (dual parameter set) ----------
constexpr int PS_XOFF = 0;
constexpr int PS_WHOFF = 128 * 20;
constexpr int PS_WLOFF = 128 * 20 + 16 * 72;
constexpr int PS_STAGE = 128 * 20 + 2 * 16 * 72;  // floats per stage = 4864
constexpr int PS_SMEM_BYTES = 4 * PS_STAGE * 4;   // 77824

__global__ __launch_bounds__(256) void gemm_tc_proj(
    int split,
    const float* __restrict__ X0, const float* __restrict__ b0,
    const float* __restrict__ Wh0, const float* __restrict__ Wl0,
    float* __restrict__ oh0, float* __restrict__ ol0, const float* __restrict__ sraw0,
    const float* __restrict__ X1, const float* __restrict__ b1,
    const float* __restrict__ Wh1, const float* __restrict__ Wl1,
    float* __restrict__ oh1, float* __restrict__ ol1, const float* __restrict__ sraw1) {
    extern __shared__ __align__(16) float smp[];
    __shared__ float sstate[256];
    __shared__ float swr2[10];
    int tid = threadIdx.x, w = tid >> 5, lane = tid & 31;
    int g = lane >> 2, tg = lane & 3;
    int set = ((int)blockIdx.x >= split);
    int rowblk = set ? (int)blockIdx.x - split : (int)blockIdx.x;
    const float* X    = set ? X1 : X0;
    const float* bias = set ? b1 : b0;
    const float* Wh   = set ? Wh1 : Wh0;
    const float* Wl   = set ? Wl1 : Wl0;
    float* oh         = set ? oh1 : oh0;
    float* ol         = set ? ol1 : ol0;
    const float* sraw = set ? sraw1 : sraw0;
    int row0 = rowblk * 128;
    int wm = w >> 1, wn = w & 1;

    int lr = tid >> 2, lq = (tid & 3) * 4;
    int wk = tid >> 4, wc = (tid & 15) * 4;

    float acc[2][4][4];
#pragma unroll
    for (int mt = 0; mt < 2; mt++)
#pragma unroll
        for (int nt = 0; nt < 4; nt++)
#pragma unroll
            for (int c = 0; c < 4; c++) acc[mt][nt][c] = 0.f;

#pragma unroll
    for (int pc = 0; pc < 3; pc++) {
        int k0 = pc * 16;
        float* st = smp + pc * PS_STAGE;
        cpa16(st + PS_XOFF + lr * 20 + lq,        &X[(size_t)(row0 + lr) * Dd + k0 + lq]);
        cpa16(st + PS_XOFF + (lr + 64) * 20 + lq, &X[(size_t)(row0 + lr + 64) * Dd + k0 + lq]);
        cpa16(st + PS_WHOFF + wk * 72 + wc,       &Wh[(size_t)(k0 + wk) * Rr + wc]);
        cpa16(st + PS_WLOFF + wk * 72 + wc,       &Wl[(size_t)(k0 + wk) * Rr + wc]);
        CP_COMMIT();
    }

    if (sraw) {
        int b = row0 >> 8;
        float v = sraw[b * Mm + tid];
        float a = fabsf(v);
        float m = a;
#pragma unroll
        for (int off = 16; off; off >>= 1) m = fmaxf(m, __shfl_down_sync(0xffffffffu, m, off));
        if (lane == 0) swr2[w] = m;
        __syncthreads();
        if (tid == 0) {
            float mm = swr2[0];
#pragma unroll
            for (int i = 1; i < 8; i++) mm = fmaxf(mm, swr2[i]);
            swr2[8] = mm;
        }
        __syncthreads();
        float e = expf(a - swr2[8]);
        float s = e;
#pragma unroll
        for (int off = 16; off; off >>= 1) s += __shfl_down_sync(0xffffffffu, s, off);
        __syncthreads();
        if (lane == 0) swr2[w] = s;
        __syncthreads();
        if (tid == 0) {
            float ss = 0.f;
#pragma unroll
            for (int i = 0; i < 8; i++) ss += swr2[i];
            swr2[9] = ss;
        }
        __syncthreads();
        float sgn = (v > 0.f) ? 1.f : ((v < 0.f) ? -1.f : 0.f);
        sstate[tid] = sgn * e / swr2[9] * STATE_MASS;
    }

    for (int c = 0; c < 32; c++) {
        CP_WAIT(2);
        __syncthreads();
        float* st = smp + (c & 3) * PS_STAGE;
        float* sx = st + PS_XOFF;
        float* swh = st + PS_WHOFF;
        float* swl = st + PS_WLOFF;
#pragma unroll
        for (int ks = 0; ks < 2; ks++) {
            int kk = ks * 8;
            uint32_t ah[2][4], al[2][4];
#pragma unroll
            for (int mt = 0; mt < 2; mt++) {
                int r = wm * 32 + mt * 16;
                float x0 = sx[(r + g) * 20 + kk + tg];
                float x1 = sx[(r + g + 8) * 20 + kk + tg];
                float x2 = sx[(r + g) * 20 + kk + tg + 4];
                float x3 = sx[(r + g + 8) * 20 + kk + tg + 4];
                ah[mt][0] = f2tf32(x0); al[mt][0] = f2tf32(x0 - __uint_as_float(ah[mt][0]));
                ah[mt][1] = f2tf32(x1); al[mt][1] = f2tf32(x1 - __uint_as_float(ah[mt][1]));
                ah[mt][2] = f2tf32(x2); al[mt][2] = f2tf32(x2 - __uint_as_float(ah[mt][2]));
                ah[mt][3] = f2tf32(x3); al[mt][3] = f2tf32(x3 - __uint_as_float(ah[mt][3]));
            }
#pragma unroll
            for (int nt = 0; nt < 4; nt++) {
                int cc = wn * 32 + nt * 8 + g;
                uint32_t bh0 = __float_as_uint(swh[(kk + tg) * 72 + cc]);
                uint32_t bh1 = __float_as_uint(swh[(kk + tg + 4) * 72 + cc]);
                uint32_t bl0 = __float_as_uint(swl[(kk + tg) * 72 + cc]);
                uint32_t bl1 = __float_as_uint(swl[(kk + tg + 4) * 72 + cc]);
#pragma unroll
                for (int mt = 0; mt < 2; mt++) {
                    MMA_TF32(acc[mt][nt], ah[mt], bh0, bh1);
                    MMA_TF32(acc[mt][nt], ah[mt], bl0, bl1);
                    MMA_TF32(acc[mt][nt], al[mt], bh0, bh1);
                }
            }
        }
        int nc = c + 3;
        if (nc < 32) {
            int k0 = nc * 16;
            float* s2 = smp + (nc & 3) * PS_STAGE;
            cpa16(s2 + PS_XOFF + lr * 20 + lq,        &X[(size_t)(row0 + lr) * Dd + k0 + lq]);
            cpa16(s2 + PS_XOFF + (lr + 64) * 20 + lq, &X[(size_t)(row0 + lr + 64) * Dd + k0 + lq]);
            cpa16(s2 + PS_WHOFF + wk * 72 + wc,       &Wh[(size_t)(k0 + wk) * Rr + wc]);
            cpa16(s2 + PS_WLOFF + wk * 72 + wc,       &Wl[(size_t)(k0 + wk) * Rr + wc]);
        }
        CP_COMMIT();
    }

#pragma unroll
    for (int mt = 0; mt < 2; mt++) {
        int r = row0 + wm * 32 + mt * 16 + g;
#pragma unroll
        for (int nt = 0; nt < 4; nt++) {
            int c = wn * 32 + nt * 8 + 2 * tg;
            float b0v = bias[c], b1v = bias[c + 1];
            float v00 = acc[mt][nt][0] + b0v, v01 = acc[mt][nt][1] + b1v;
            float v10 = acc[mt][nt][2] + b0v, v11 = acc[mt][nt][3] + b1v;
            if (ol) {
                float h00 = __uint_as_float(f2tf32(v00));
                float h01 = __uint_as_float(f2tf32(v01));
                float h10 = __uint_as_float(f2tf32(v10));
                float h11 = __uint_as_float(f2tf32(v11));
                *(float2*)&oh[(size_t)r * Rr + c]       = make_float2(h00, h01);
                *(float2*)&oh[(size_t)(r + 8) * Rr + c] = make_float2(h10, h11);
                *(float2*)&ol[(size_t)r * Rr + c] = make_float2(
                    __uint_as_float(f2tf32(v00 - h00)), __uint_as_float(f2tf32(v01 - h01)));
                *(float2*)&ol[(size_t)(r + 8) * Rr + c] = make_float2(
                    __uint_as_float(f2tf32(v10 - h10)), __uint_as_float(f2tf32(v11 - h11)));
            } else {
                float r0s = sraw ? sstate[r & 255] : 1.f;
                float r1s = sraw ? sstate[(r + 8) & 255] : 1.f;
                *(float2*)&oh[(size_t)r * Rr + c]       = make_float2(v00 * r0s, v01 * r0s);
                *(float2*)&oh[(size_t)(r + 8) * Rr + c] = make_float2(v10 * r1s, v11 * r1s);
            }
        }
    }
}

// ---------------- tensor-core scores GEMM: pure MMA from pre-split tiles ----------
__global__ __launch_bounds__(256) void scores_tc_kernel() {
    extern __shared__ __align__(16) float smc[];
    float (*sah)[72] = (float(*)[72])smc;
    float (*sal)[72] = (float(*)[72])(smc + 128 * 72);
    float (*sbh)[72] = (float(*)[72])(smc + 2 * 128 * 72);
    float (*sbl)[72] = (float(*)[72])(smc + 3 * 128 * 72);
    int tid = threadIdx.x, w = tid >> 5, lane = tid & 31;
    int g = lane >> 2, tg = lane & 3;
    int b = blockIdx.z;
    int m0 = blockIdx.y * 128;
    int s0 = blockIdx.x * 128;
    int wm = w >> 1, wn = w & 1;

#pragma unroll
    for (int t = 0; t < 8; t++) {
        int f = tid + 256 * t;
        int r = f >> 4, q = (f & 15) * 4;
        cpa16(&sah[r][q], &g_pt2_h[(size_t)(m0 + r) * Rr + q]);
        cpa16(&sal[r][q], &g_pt2_l[(size_t)(m0 + r) * Rr + q]);
        cpa16(&sbh[r][q], &g_ps_h[((size_t)b * Ss + s0 + r) * Rr + q]);
        cpa16(&sbl[r][q], &g_ps_l[((size_t)b * Ss + s0 + r) * Rr + q]);
    }
    CP_COMMIT();

    float acc[2][8][4];
#pragma unroll
    for (int mt = 0; mt < 2; mt++)
#pragma unroll
        for (int nt = 0; nt < 8; nt++)
#pragma unroll
            for (int c = 0; c < 4; c++) acc[mt][nt][c] = 0.f;

    CP_WAIT(0);
    __syncthreads();

#pragma unroll
    for (int ks = 0; ks < 8; ks++) {
        int kk = ks * 8;
        uint32_t ah[2][4], al[2][4];
#pragma unroll
        for (int mt = 0; mt < 2; mt++) {
            int r = wm * 32 + mt * 16;
            ah[mt][0] = __float_as_uint(sah[r + g][kk + tg]);
            ah[mt][1] = __float_as_uint(sah[r + g + 8][kk + tg]);
            ah[mt][2] = __float_as_uint(sah[r + g][kk + tg + 4]);
            ah[mt][3] = __float_as_uint(sah[r + g + 8][kk + tg + 4]);
            al[mt][0] = __float_as_uint(sal[r + g][kk + tg]);
            al[mt][1] = __float_as_uint(sal[r + g + 8][kk + tg]);
            al[mt][2] = __float_as_uint(sal[r + g][kk + tg + 4]);
            al[mt][3] = __float_as_uint(sal[r + g + 8][kk + tg + 4]);
        }
#pragma unroll
        for (int nt = 0; nt < 8; nt++) {
            int cc = wn * 64 + nt * 8 + g;
            uint32_t bh0 = __float_as_uint(sbh[cc][kk + tg]);
            uint32_t bh1 = __float_as_uint(sbh[cc][kk + tg + 4]);
            uint32_t bl0 = __float_as_uint(sbl[cc][kk + tg]);
            uint32_t bl1 = __float_as_uint(sbl[cc][kk + tg + 4]);
#pragma unroll
            for (int mt = 0; mt < 2; mt++) {
                MMA_TF32(acc[mt][nt], ah[mt], bh0, bh1);
                MMA_TF32(acc[mt][nt], ah[mt], bl0, bl1);
                MMA_TF32(acc[mt][nt], al[mt], bh0, bh1);
            }
        }
    }

#pragma unroll
    for (int mt = 0; mt < 2; mt++) {
        int m = m0 + wm * 32 + mt * 16 + g;
#pragma unroll
        for (int nt = 0; nt < 8; nt++) {
            int s = s0 + wn * 64 + nt * 8 + 2 * tg;
            *(float2*)&g_scores[((size_t)(b * Mm + m)) * Ss + s] =
                make_float2(acc[mt][nt][0], acc[mt][nt][1]);
            *(float2*)&g_scores[((size_t)(b * Mm + m + 8)) * Ss + s] =
                make_float2(acc[mt][nt][2], acc[mt][nt][3]);
        }
    }
}

// ---------------- write phase: vector scan + key-space merge + float2 gather ----------------
__global__ __launch_bounds__(256) void write_kernel(
    const float* __restrict__ token_val, const float* __restrict__ token_state,
    const float* __restrict__ ln_g, const float* __restrict__ ln_b) {
    int bm = blockIdx.x;
    int b = bm >> 8, m = bm & 255;
    int tid = threadIdx.x, w = tid >> 5, lane = tid & 31;
    __shared__ ull wk[8][32];
    __shared__ float swr[18];
    __shared__ float s_edge[16];
    __shared__ int s_eidx[16];

    const float* row = g_scores + (size_t)bm * Ss;

    // vectorized scan: thread owns 8 contiguous scores
    int base = w * 256 + lane * 8;
    float4 v0 = *(const float4*)&row[base];
    float4 v1 = *(const float4*)&row[base + 4];
    float aa[8] = {fabsf(v0.x), fabsf(v0.y), fabsf(v0.z), fabsf(v0.w),
                   fabsf(v1.x), fabsf(v1.y), fabsf(v1.z), fabsf(v1.w)};

    // warp-local bisection to <=32 survivors
    unsigned um = 0;
#pragma unroll
    for (int j = 0; j < 8; j++) um = max(um, __float_as_uint(aa[j]));
    um = __reduce_max_sync(0xffffffffu, um);
    float hi = __uint_as_float(um), lo = 0.f;
    int cl = 256;
    for (int it = 0; it < 32 && cl > 32; it++) {
        float mid = 0.5f * (lo + hi);
        int c = 0;
#pragma unroll
        for (int j = 0; j < 8; j++) c += (aa[j] > mid);
        c = (int)__reduce_add_sync(0xffffffffu, (unsigned)c);
        if (c >= 16) { lo = mid; cl = c; } else { hi = mid; }
    }

    // ballot-compact survivors (unsorted) into wk[w], pad zeros
    wk[w][lane] = 0ull;
    __syncwarp();
    int bc = 0;
#pragma unroll
    for (int j = 0; j < 8; j++) {
        bool p = aa[j] > lo;
        unsigned msk = __ballot_sync(0xffffffffu, p);
        if (p) {
            int pos = bc + __popc(msk & ((1u << lane) - 1));
            if (pos < 32)
                wk[w][pos] = ((ull)__float_as_uint(aa[j]) << 32) | (unsigned)(~(base + j));
        }
        bc += __popc(msk);
    }
    __syncthreads();

    // warp 0: 64-bit key-space bisection over 256 keys (8/lane) -> <=32 -> sort-32
    if (w == 0) {
        ull kv[8];
#pragma unroll
        for (int j = 0; j < 8; j++) kv[j] = wk[j][lane];
        ull kmax = kv[0];
#pragma unroll
        for (int j = 1; j < 8; j++) kmax = kv[j] > kmax ? kv[j] : kmax;
#pragma unroll
        for (int off = 16; off; off >>= 1) {
            ull o = __shfl_xor_sync(0xffffffffu, kmax, off);
            kmax = o > kmax ? o : kmax;
        }
        ull klo = 0ull, khi = kmax;
        int cl2 = 256;
        for (int it = 0; it < 64 && cl2 > 32; it++) {
            ull mid = klo + ((khi - klo) >> 1);
            int c = 0;
#pragma unroll
            for (int j = 0; j < 8; j++) c += (kv[j] > mid);
            c = (int)__reduce_add_sync(0xffffffffu, (unsigned)c);
            if (c >= 16) { klo = mid; cl2 = c; } else { khi = mid; }
        }
        // compact <=32 survivors into registers via ballots
        ull key = 0ull;
        int bc2 = 0;
#pragma unroll
        for (int j = 0; j < 8; j++) {
            bool p = kv[j] > klo;
            unsigned msk = __ballot_sync(0xffffffffu, p);
            if (p) {
                int pos = bc2 + __popc(msk & ((1u << lane) - 1));
                if (pos < 32) wk[0][pos] = kv[j];
            }
            bc2 += __popc(msk);
        }
        __syncwarp();
        // clear tail beyond count
        if (lane >= bc2 && lane < 32) wk[0][lane] = 0ull;
        __syncwarp();
        key = wk[0][lane];
        // warp bitonic sort-32 descending
#pragma unroll
        for (int k = 2; k <= 32; k <<= 1) {
#pragma unroll
            for (int j = k >> 1; j; j >>= 1) {
                ull other = __shfl_xor_sync(0xffffffffu, key, j);
                bool takeMax = ((lane & k) == 0) != ((lane & j) != 0);
                ull mx = key > other ? key : other;
                ull mn = key > other ? other : key;
                key = takeMax ? mx : mn;
            }
        }
        bool valid = lane < 16;
        float a = __uint_as_float((unsigned)(key >> 32));
        int idx = (int)(~(unsigned)key);
        float maxa = __shfl_sync(0xffffffffu, a, 0);
        float sel = valid ? row[idx] : 0.f;
        float e = valid ? expf(a - maxa) : 0.f;
        float sum = e;
#pragma unroll
        for (int off = 8; off; off >>= 1) sum += __shfl_xor_sync(0xffffffffu, sum, off, 16);
        float sgn = (sel > 0.f) ? 1.f : ((sel < 0.f) ? -1.f : 0.f);
        float edge = sgn * e / sum;
        if (valid) { s_edge[lane] = edge; s_eidx[lane] = idx; }
        float c = valid ? edge * token_state[(size_t)b * Ss + idx] : 0.f;
#pragma unroll
        for (int off = 8; off; off >>= 1) c += __shfl_xor_sync(0xffffffffu, c, off, 16);
        if (lane == 0) g_state1_raw[bm] = g_mem_state0[m] + c;
    }
    __syncthreads();

    // value update + LN (float2: thread owns elements 2t, 2t+1)
    float2 a2 = *(const float2*)&g_mem_val0[(size_t)m * Dd + 2 * tid];
#pragma unroll
    for (int k = 0; k < 16; k++) {
        const float2 tv = *(const float2*)&token_val[((size_t)b * Ss + s_eidx[k]) * Dd + 2 * tid];
        float ek = s_edge[k];
        a2.x = fmaf(ek, tv.x, a2.x);
        a2.y = fmaf(ek, tv.y, a2.y);
    }
    float mu, ri;
    block_ln_512(a2.x, a2.y, mu, ri, swr);
    float2 gv = *(const float2*)&ln_g[2 * tid];
    float2 bv = *(const float2*)&ln_b[2 * tid];
    float2 o2;
    o2.x = (a2.x - mu) * ri * gv.x + bv.x;
    o2.y = (a2.y - mu) * ri * gv.y + bv.y;
    *(float2*)&g_mem_val1[(size_t)bm * Dd + 2 * tid] = o2;
}

// ---------------- propagation: 16 rows/block, one-shot staging, warp-per-row ----------------
constexpr int PR_QS = 0;
constexpr int PR_QT = 256 * 68;
constexpr int PR_PR = 256 * 68 + 16 * 68;
constexpr int PR_SMEM_BYTES = (256 * 68 + 16 * 68 + 16 * 256) * 4;  // 90368

__global__ __launch_bounds__(256) void prop16_kernel(
    float* __restrict__ out_final, const float* __restrict__ ln_g,
    const float* __restrict__ ln_b) {
    extern __shared__ __align__(16) float smq[];
    float (*sqs)[68]  = (float(*)[68])(smq + PR_QS);
    float (*s_qt)[68] = (float(*)[68])(smq + PR_QT);
    float (*prow)[256] = (float(*)[256])(smq + PR_PR);
    __shared__ ull wkeys[8][32];
    __shared__ float s_edge[16][16];
    __shared__ int s_eidx[16][16];

    int b = blockIdx.x >> 4;
    int i0 = (blockIdx.x & 15) * 16;
    int tid = threadIdx.x, w = tid >> 5, lane = tid & 31;

    {
        int r = tid >> 4, q = (tid & 15) * 4;
        cpa16(&s_qt[r][q], &g_qt[((size_t)(b * Mm + i0 + r)) * Rr + q]);
    }
#pragma unroll
    for (int t = 0; t < 16; t++) {
        int f = tid + 256 * t;
        int r = f >> 4, q = (f & 15) * 4;
        cpa16(&sqs[r][q], &g_qs2[((size_t)(b * Mm + r)) * Rr + q]);
    }
    CP_COMMIT();
    CP_WAIT(0);
    __syncthreads();

#pragma unroll
    for (int rr = 0; rr < 2; rr++) {
        int row = 2 * w + rr;

        float pv[8];
#pragma unroll
        for (int jb = 0; jb < 8; jb++) {
            int j = jb * 32 + lane;
            float acc = 0.f;
#pragma unroll
            for (int k4 = 0; k4 < Rr; k4 += 4) {
                float4 qv = *(const float4*)&sqs[j][k4];
                float4 tv = *(const float4*)&s_qt[row][k4];
                acc = fmaf(qv.x, tv.x, fmaf(qv.y, tv.y, fmaf(qv.z, tv.z, fmaf(qv.w, tv.w, acc))));
            }
            pv[jb] = acc;
            prow[row][j] = acc;
        }
        __syncwarp();

        float av[8];
#pragma unroll
        for (int r2 = 0; r2 < 8; r2++) av[r2] = fabsf(pv[r2]);
        unsigned um = 0;
#pragma unroll
        for (int r2 = 0; r2 < 8; r2++) um = max(um, __float_as_uint(av[r2]));
        um = __reduce_max_sync(0xffffffffu, um);
        float hi = __uint_as_float(um), lo = 0.f;
        int cl = 256;
        for (int it = 0; it < 32 && cl > 32; it++) {
            float mid = 0.5f * (lo + hi);
            int c = 0;
#pragma unroll
            for (int r2 = 0; r2 < 8; r2++) c += (av[r2] > mid);
            c = (int)__reduce_add_sync(0xffffffffu, (unsigned)c);
            if (c >= 16) { lo = mid; cl = c; } else { hi = mid; }
        }

        wkeys[w][lane] = 0ull;
        __syncwarp();
        int base = 0;
#pragma unroll
        for (int r2 = 0; r2 < 8; r2++) {
            bool p = av[r2] > lo;
            unsigned msk = __ballot_sync(0xffffffffu, p);
            if (p) {
                int pos = base + __popc(msk & ((1u << lane) - 1));
                if (pos < 32)
                    wkeys[w][pos] =
                        ((ull)__float_as_uint(av[r2]) << 32) | (unsigned)(~(r2 * 32 + lane));
            }
            base += __popc(msk);
        }
        __syncwarp();

        ull key = wkeys[w][lane];
#pragma unroll
        for (int k = 2; k <= 32; k <<= 1) {
#pragma unroll
            for (int j = k >> 1; j; j >>= 1) {
                ull other = __shfl_xor_sync(0xffffffffu, key, j);
                bool takeMax = ((lane & k) == 0) != ((lane & j) != 0);
                ull mx2 = key > other ? key : other;
                ull mn2 = key > other ? other : key;
                key = takeMax ? mx2 : mn2;
            }
        }

        bool valid = lane < 16;
        float a = __uint_as_float((unsigned)(key >> 32));
        int idx = (int)(~(unsigned)key);
        float maxa = __shfl_sync(0xffffffffu, a, 0);
        float sel = valid ? prow[row][idx] : 0.f;
        float e = valid ? expf(a - maxa) : 0.f;
        float sum = e;
#pragma unroll
        for (int off = 8; off; off >>= 1) sum += __shfl_xor_sync(0xffffffffu, sum, off, 16);
        float sgn = (sel > 0.f) ? 1.f : ((sel < 0.f) ? -1.f : 0.f);
        float edge = sgn * e / sum;
        if (valid) { s_edge[row][lane] = edge; s_eidx[row][lane] = idx; }
        __syncwarp();

        int bi = b * Mm + i0 + row;
        float4 acc4[4];
#pragma unroll
        for (int q = 0; q < 4; q++)
            acc4[q] = *(const float4*)&g_mem_val1[(size_t)bi * Dd + (q * 32 + lane) * 4];
#pragma unroll
        for (int k = 0; k < 16; k++) {
            float ek = s_edge[row][k];
            const float* mv = g_mem_val1 + ((size_t)(b * Mm + s_eidx[row][k])) * Dd;
#pragma unroll
            for (int q = 0; q < 4; q++) {
                float4 v = *(const float4*)&mv[(q * 32 + lane) * 4];
                acc4[q].x = fmaf(ek, v.x, acc4[q].x);
                acc4[q].y = fmaf(ek, v.y, acc4[q].y);
                acc4[q].z = fmaf(ek, v.z, acc4[q].z);
                acc4[q].w = fmaf(ek, v.w, acc4[q].w);
            }
        }
        float s = 0.f, sq = 0.f;
#pragma unroll
        for (int q = 0; q < 4; q++) {
            s += acc4[q].x + acc4[q].y + acc4[q].z + acc4[q].w;
            sq = fmaf(acc4[q].x, acc4[q].x, sq);
            sq = fmaf(acc4[q].y, acc4[q].y, sq);
            sq = fmaf(acc4[q].z, acc4[q].z, sq);
            sq = fmaf(acc4[q].w, acc4[q].w, sq);
        }
#pragma unroll
        for (int off = 16; off; off >>= 1) {
            s += __shfl_down_sync(0xffffffffu, s, off);
            sq += __shfl_down_sync(0xffffffffu, sq, off);
        }
        s = __shfl_sync(0xffffffffu, s, 0);
        sq = __shfl_sync(0xffffffffu, sq, 0);
        float mu = s * (1.0f / 512.0f);
        float ri = rsqrtf(sq * (1.0f / 512.0f) - mu * mu + EPS);
#pragma unroll
        for (int q = 0; q < 4; q++) {
            int d4 = (q * 32 + lane) * 4;
            float4 gv = *(const float4*)&ln_g[d4];
            float4 bv = *(const float4*)&ln_b[d4];
            float4 o;
            o.x = (acc4[q].x - mu) * ri * gv.x + bv.x;
            o.y = (acc4[q].y - mu) * ri * gv.y + bv.y;
            o.z = (acc4[q].z - mu) * ri * gv.z + bv.z;
            o.w = (acc4[q].w - mu) * ri * gv.w + bv.w;
            *(float4*)&out_final[(size_t)bi * Dd + d4] = o;
        }
    }
}

// ---------------- host launch ----------------
extern "C" void kernel_launch(void* const* d_in, const int* in_sizes, int n_in,
                              void* d_out, int out_size) {
    (void)in_sizes; (void)n_in; (void)out_size;
    const float* token_val   = (const float*)d_in[0];
    const float* token_state = (const float*)d_in[1];
    const float* init_state  = (const float*)d_in[2];
    const float* init_val    = (const float*)d_in[3];
    const float* rUs_w = (const float*)d_in[4];
    const float* rUs_b = (const float*)d_in[5];
    const float* rUt_w = (const float*)d_in[6];
    const float* rUt_b = (const float*)d_in[7];
    const float* r_w   = (const float*)d_in[8];
    const float* pUs_w = (const float*)d_in[9];
    const float* pUs_b = (const float*)d_in[10];
    const float* pUt_w = (const float*)d_in[11];
    const float* pUt_b = (const float*)d_in[12];
    const float* p_w   = (const float*)d_in[13];
    const float* ln_g  = (const float*)d_in[14];
    const float* ln_b  = (const float*)d_in[15];
    float* out = (float*)d_out;

    float *p_mv0, *p_mv1, *p_qt, *p_qs2, *p_st1raw;
    float *p_Wh, *p_Wl, *p_Wth, *p_Wtl, *p_Wpsh, *p_Wpsl, *p_Wpth, *p_Wptl;
    float *p_bt2, *p_bqt, *p_pt2h, *p_pt2l, *p_psh, *p_psl;
    cudaGetSymbolAddress((void**)&p_mv0, g_mem_val0);
    cudaGetSymbolAddress((void**)&p_mv1, g_mem_val1);
    cudaGetSymbolAddress((void**)&p_qt, g_qt);
    cudaGetSymbolAddress((void**)&p_qs2, g_qs2);
    cudaGetSymbolAddress((void**)&p_st1raw, g_state1_raw);
    cudaGetSymbolAddress((void**)&p_Wh, g_Wh);
    cudaGetSymbolAddress((void**)&p_Wl, g_Wl);
    cudaGetSymbolAddress((void**)&p_Wth, g_Wth);
    cudaGetSymbolAddress((void**)&p_Wtl, g_Wtl);
    cudaGetSymbolAddress((void**)&p_Wpsh, g_Wpsh);
    cudaGetSymbolAddress((void**)&p_Wpsl, g_Wpsl);
    cudaGetSymbolAddress((void**)&p_Wpth, g_Wpth);
    cudaGetSymbolAddress((void**)&p_Wptl, g_Wptl);
    cudaGetSymbolAddress((void**)&p_bt2, g_bt2);
    cudaGetSymbolAddress((void**)&p_bqt, g_bqt);
    cudaGetSymbolAddress((void**)&p_pt2h, g_pt2_h);
    cudaGetSymbolAddress((void**)&p_pt2l, g_pt2_l);
    cudaGetSymbolAddress((void**)&p_psh, g_ps_h);
    cudaGetSymbolAddress((void**)&p_psl, g_ps_l);

    const int SC_SMEM = 4 * 128 * 72 * 4;  // 147456 bytes
    cudaFuncSetAttribute(scores_tc_kernel,
                         cudaFuncAttributeMaxDynamicSharedMemorySize, SC_SMEM);
    cudaFuncSetAttribute(gemm_tc_proj,
                         cudaFuncAttributeMaxDynamicSharedMemorySize, PS_SMEM_BYTES);
    cudaFuncSetAttribute(prop16_kernel,
                         cudaFuncAttributeMaxDynamicSharedMemorySize, PR_SMEM_BYTES);

    // fused prologue
    prep_kernel<<<322, 256>>>(init_val, init_state, rUs_w, rUt_w, rUt_b, r_w,
                              pUs_w, pUt_w, pUt_b, p_w, ln_g, ln_b);
    // fused TC projection: [0,256) -> ps (split out); [256,258) -> pt2 (split out)
    gemm_tc_proj<<<(Bb * Ss) / 128 + Mm / 128, 256, PS_SMEM_BYTES>>>(
        (Bb * Ss) / 128,
        token_val, rUs_b, p_Wh, p_Wl, p_psh, p_psl, nullptr,
        p_mv0, p_bt2, p_Wth, p_Wtl, p_pt2h, p_pt2l, nullptr);
    // scores = pt2 . ps  (pure MMA from pre-split tiles)
    scores_tc_kernel<<<dim3(Ss / 128, Mm / 128, Bb), 256, SC_SMEM>>>();
    // write phase: warp-local topk + key-space merge + edges + float2 gather + LN
    write_kernel<<<Bb * Mm, 256>>>(token_val, token_state, ln_g, ln_b);
    // fused TC projection: [0,32) -> qt (raw); [32,64) -> qs2 (raw, rowscale =
    // block-local signed-softmax of state1_raw)
    gemm_tc_proj<<<(Bb * Mm) / 128 * 2, 256, PS_SMEM_BYTES>>>(
        (Bb * Mm) / 128,
        p_mv1, p_bqt, p_Wpth, p_Wptl, p_qt, nullptr, nullptr,
        p_mv1, pUs_b, p_Wpsh, p_Wpsl, p_qs2, nullptr, p_st1raw);
    // propagation (16 rows/block, warp-per-row) + final LN -> out
    prop16_kernel<<<(Bb * Mm) / 16, 256, PR_SMEM_BYTES>>>(out, ln_g, ln_b);
}